// round 1
// baseline (speedup 1.0000x reference)
#include <cuda_runtime.h>
#include <math.h>

// ---------------------------------------------------------------------------
// Problem constants
// ---------------------------------------------------------------------------
constexpr int DM   = 192;      // d_model
constexpr int FPD  = 128;      // fingerprint dim
constexpr int MAXB = 65536;    // batch
constexpr long NT  = 2L * MAXB; // token rows (2 per batch row)

// ---------------------------------------------------------------------------
// Device scratch (static __device__ arrays: the sanctioned no-alloc workaround)
// ---------------------------------------------------------------------------
__device__ float g_seq [NT * DM];        //  96 MB  [2B,192]
__device__ float g_qkv [NT * 3 * DM];    // 288 MB  [2B,576]
__device__ float g_ctx [NT * DM];        //  96 MB
__device__ float g_attn[NT * DM];        //  96 MB
__device__ float g_x   [NT * DM];        //  96 MB
__device__ float g_h   [NT * 2 * DM];    // 192 MB  [2B,384]
__device__ float g_ffn [NT * DM];        //  96 MB
__device__ float g_z   [(long)MAXB * DM];
__device__ float g_c   [(long)MAXB * DM];
__device__ float g_fp  [(long)MAXB * FPD];

// ---------------------------------------------------------------------------
// Tiled fp32 GEMM:  C[m, coff + n] = act( A[m,:] . W[n,:] + bias[n] )
//   A: [M, K] row-major with row stride lda
//   W: [N, K] row-major (torch Linear weight layout)
//   C: row stride ldc, column offset coff
// Tile: BM=128, BN=64, BK=16, 128 threads, 8x8 micro-tile per thread.
// Requires: M % 128 == 0, N % 64 == 0, K % 16 == 0 (true for all our shapes).
// ---------------------------------------------------------------------------
template<bool RELU>
__global__ void __launch_bounds__(128)
gemm_tn(const float* __restrict__ A, int lda,
        const float* __restrict__ W,
        const float* __restrict__ bias,
        float* __restrict__ C, int ldc, int coff,
        int K)
{
    constexpr int BM = 128, BN = 64, BK = 16, TM = 8, TN = 8;
    __shared__ float As[BK][BM];
    __shared__ float Bs[BK][BN];

    const int tid = threadIdx.x;
    const int bx  = blockIdx.x;   // N tile
    const int by  = blockIdx.y;   // M tile
    const int tx  = tid & 7;      // 0..7  -> BN/TN
    const int ty  = tid >> 3;     // 0..15 -> BM/TM

    float acc[TM][TN];
#pragma unroll
    for (int i = 0; i < TM; i++)
#pragma unroll
        for (int j = 0; j < TN; j++) acc[i][j] = 0.f;

    const float* aptr = A + (size_t)(by * BM + tid) * lda;      // one A row per thread
    const int bn = tid >> 1;                                    // 0..63
    const int bk = (tid & 1) * 8;                               // 0 or 8
    const float* bptr = W + (size_t)(bx * BN + bn) * K + bk;

    for (int k0 = 0; k0 < K; k0 += BK) {
        float4 a0 = *(const float4*)(aptr + k0);
        float4 a1 = *(const float4*)(aptr + k0 + 4);
        float4 a2 = *(const float4*)(aptr + k0 + 8);
        float4 a3 = *(const float4*)(aptr + k0 + 12);
        float4 b0 = *(const float4*)(bptr + k0);
        float4 b1 = *(const float4*)(bptr + k0 + 4);

        __syncthreads();   // previous tile fully consumed
        As[ 0][tid] = a0.x; As[ 1][tid] = a0.y; As[ 2][tid] = a0.z; As[ 3][tid] = a0.w;
        As[ 4][tid] = a1.x; As[ 5][tid] = a1.y; As[ 6][tid] = a1.z; As[ 7][tid] = a1.w;
        As[ 8][tid] = a2.x; As[ 9][tid] = a2.y; As[10][tid] = a2.z; As[11][tid] = a2.w;
        As[12][tid] = a3.x; As[13][tid] = a3.y; As[14][tid] = a3.z; As[15][tid] = a3.w;
        Bs[bk + 0][bn] = b0.x; Bs[bk + 1][bn] = b0.y; Bs[bk + 2][bn] = b0.z; Bs[bk + 3][bn] = b0.w;
        Bs[bk + 4][bn] = b1.x; Bs[bk + 5][bn] = b1.y; Bs[bk + 6][bn] = b1.z; Bs[bk + 7][bn] = b1.w;
        __syncthreads();

#pragma unroll
        for (int kk = 0; kk < BK; kk++) {
            float ar[TM], br[TN];
            *(float4*)&ar[0] = *(const float4*)&As[kk][ty * TM];
            *(float4*)&ar[4] = *(const float4*)&As[kk][ty * TM + 4];
            *(float4*)&br[0] = *(const float4*)&Bs[kk][tx * TN];
            *(float4*)&br[4] = *(const float4*)&Bs[kk][tx * TN + 4];
#pragma unroll
            for (int i = 0; i < TM; i++)
#pragma unroll
                for (int j = 0; j < TN; j++)
                    acc[i][j] = fmaf(ar[i], br[j], acc[i][j]);
        }
    }

    float bv[TN];
#pragma unroll
    for (int j = 0; j < TN; j++) bv[j] = bias[bx * BN + tx * TN + j];

#pragma unroll
    for (int i = 0; i < TM; i++) {
        const int row = by * BM + ty * TM + i;
        float* cp = C + (size_t)row * ldc + coff + bx * BN + tx * TN;
        float4 v0, v1;
        v0.x = acc[i][0] + bv[0]; v0.y = acc[i][1] + bv[1];
        v0.z = acc[i][2] + bv[2]; v0.w = acc[i][3] + bv[3];
        v1.x = acc[i][4] + bv[4]; v1.y = acc[i][5] + bv[5];
        v1.z = acc[i][6] + bv[6]; v1.w = acc[i][7] + bv[7];
        if (RELU) {
            v0.x = fmaxf(v0.x, 0.f); v0.y = fmaxf(v0.y, 0.f);
            v0.z = fmaxf(v0.z, 0.f); v0.w = fmaxf(v0.w, 0.f);
            v1.x = fmaxf(v1.x, 0.f); v1.y = fmaxf(v1.y, 0.f);
            v1.z = fmaxf(v1.z, 0.f); v1.w = fmaxf(v1.w, 0.f);
        }
        *(float4*)cp       = v0;
        *(float4*)(cp + 4) = v1;
    }
}

// ---------------------------------------------------------------------------
// Attention over 2-token sequence, 3 heads of 64. One warp per batch row.
// qkv: [2B, 576] (q|k|v), ctx out: [2B, 192]
// ---------------------------------------------------------------------------
__global__ void attn_kernel(const float* __restrict__ qkv, float* __restrict__ ctx, int B)
{
    const int w    = (blockIdx.x * blockDim.x + threadIdx.x) >> 5;
    const int lane = threadIdx.x & 31;
    if (w >= B) return;
    const float* r0 = qkv + (size_t)(2 * w) * 576;
    const float* r1 = r0 + 576;
    float* c0 = ctx + (size_t)(2 * w) * 192;
    float* c1 = c0 + 192;

#pragma unroll
    for (int h = 0; h < 3; h++) {
        const int o = h * 64 + 2 * lane;
        float2 q0 = *(const float2*)(r0 + o);
        float2 q1 = *(const float2*)(r1 + o);
        float2 k0 = *(const float2*)(r0 + 192 + o);
        float2 k1 = *(const float2*)(r1 + 192 + o);
        float2 v0 = *(const float2*)(r0 + 384 + o);
        float2 v1 = *(const float2*)(r1 + 384 + o);

        float s00 = q0.x * k0.x + q0.y * k0.y;
        float s01 = q0.x * k1.x + q0.y * k1.y;
        float s10 = q1.x * k0.x + q1.y * k0.y;
        float s11 = q1.x * k1.x + q1.y * k1.y;
#pragma unroll
        for (int d = 16; d; d >>= 1) {
            s00 += __shfl_xor_sync(0xffffffffu, s00, d);
            s01 += __shfl_xor_sync(0xffffffffu, s01, d);
            s10 += __shfl_xor_sync(0xffffffffu, s10, d);
            s11 += __shfl_xor_sync(0xffffffffu, s11, d);
        }
        s00 *= 0.125f; s01 *= 0.125f; s10 *= 0.125f; s11 *= 0.125f;

        float m0 = fmaxf(s00, s01);
        float e00 = expf(s00 - m0), e01 = expf(s01 - m0);
        float inv0 = 1.f / (e00 + e01);
        float a00 = e00 * inv0, a01 = e01 * inv0;

        float m1 = fmaxf(s10, s11);
        float e10 = expf(s10 - m1), e11 = expf(s11 - m1);
        float inv1 = 1.f / (e10 + e11);
        float a10 = e10 * inv1, a11 = e11 * inv1;

        float2 o0, o1;
        o0.x = a00 * v0.x + a01 * v1.x;  o0.y = a00 * v0.y + a01 * v1.y;
        o1.x = a10 * v0.x + a11 * v1.x;  o1.y = a10 * v0.y + a11 * v1.y;
        *(float2*)(c0 + o) = o0;
        *(float2*)(c1 + o) = o1;
    }
}

// ---------------------------------------------------------------------------
// x = LayerNorm(a + b) * g + beta   (192-wide row, one warp per row)
// ---------------------------------------------------------------------------
__global__ void add_ln_kernel(const float* __restrict__ A, const float* __restrict__ Bq,
                              const float* __restrict__ g, const float* __restrict__ be,
                              float* __restrict__ O, int nrows)
{
    const int w    = (blockIdx.x * blockDim.x + threadIdx.x) >> 5;
    const int lane = threadIdx.x & 31;
    if (w >= nrows) return;
    const float* a = A  + (size_t)w * 192;
    const float* b = Bq + (size_t)w * 192;
    float y[6], s = 0.f, ss = 0.f;
#pragma unroll
    for (int j = 0; j < 6; j++) {
        const int idx = lane + 32 * j;
        y[j] = a[idx] + b[idx];
        s += y[j]; ss += y[j] * y[j];
    }
#pragma unroll
    for (int d = 16; d; d >>= 1) {
        s  += __shfl_xor_sync(0xffffffffu, s,  d);
        ss += __shfl_xor_sync(0xffffffffu, ss, d);
    }
    const float mu  = s * (1.f / 192.f);
    const float var = ss * (1.f / 192.f) - mu * mu;
    const float rs  = rsqrtf(var + 1e-5f);
    float* o = O + (size_t)w * 192;
#pragma unroll
    for (int j = 0; j < 6; j++) {
        const int idx = lane + 32 * j;
        o[idx] = (y[j] - mu) * rs * g[idx] + be[idx];
    }
}

// ---------------------------------------------------------------------------
// x2 = LN(x + ffn); z = mean over the 2 tokens. One warp per batch row.
// ---------------------------------------------------------------------------
__global__ void ln2_mean_kernel(const float* __restrict__ X, const float* __restrict__ F,
                                const float* __restrict__ g, const float* __restrict__ be,
                                float* __restrict__ Z, int B)
{
    const int w    = (blockIdx.x * blockDim.x + threadIdx.x) >> 5;
    const int lane = threadIdx.x & 31;
    if (w >= B) return;
    float zacc[6];
#pragma unroll
    for (int j = 0; j < 6; j++) zacc[j] = 0.f;

#pragma unroll
    for (int t = 0; t < 2; t++) {
        const size_t row = (size_t)(2 * w + t) * 192;
        float y[6], s = 0.f, ss = 0.f;
#pragma unroll
        for (int j = 0; j < 6; j++) {
            const int idx = lane + 32 * j;
            y[j] = X[row + idx] + F[row + idx];
            s += y[j]; ss += y[j] * y[j];
        }
#pragma unroll
        for (int d = 16; d; d >>= 1) {
            s  += __shfl_xor_sync(0xffffffffu, s,  d);
            ss += __shfl_xor_sync(0xffffffffu, ss, d);
        }
        const float mu  = s * (1.f / 192.f);
        const float var = ss * (1.f / 192.f) - mu * mu;
        const float rs  = rsqrtf(var + 1e-5f);
#pragma unroll
        for (int j = 0; j < 6; j++) {
            const int idx = lane + 32 * j;
            zacc[j] += 0.5f * ((y[j] - mu) * rs * g[idx] + be[idx]);
        }
    }
    float* z = Z + (size_t)w * 192;
#pragma unroll
    for (int j = 0; j < 6; j++) z[lane + 32 * j] = zacc[j];
}

// ---------------------------------------------------------------------------
// Final heads: logits = c . cls_w2^T + b2 -> sigmoid -> 3 prob columns;
// fp = normalize(fp_raw). One warp per batch row.
// out layout: [B] p0 | [B] p1 | [B] p2 | [B*128] fp
// ---------------------------------------------------------------------------
__global__ void head_kernel(const float* __restrict__ C, const float* __restrict__ FPr,
                            const float* __restrict__ w2, const float* __restrict__ b2,
                            float* __restrict__ out, int B)
{
    const int w    = (blockIdx.x * blockDim.x + threadIdx.x) >> 5;
    const int lane = threadIdx.x & 31;
    if (w >= B) return;

    const float* c = C + (size_t)w * 192;
    float l0 = 0.f, l1 = 0.f, l2 = 0.f;
#pragma unroll
    for (int j = 0; j < 6; j++) {
        const int idx = lane + 32 * j;
        const float cv = c[idx];
        l0 += cv * w2[idx];
        l1 += cv * w2[192 + idx];
        l2 += cv * w2[384 + idx];
    }
#pragma unroll
    for (int d = 16; d; d >>= 1) {
        l0 += __shfl_xor_sync(0xffffffffu, l0, d);
        l1 += __shfl_xor_sync(0xffffffffu, l1, d);
        l2 += __shfl_xor_sync(0xffffffffu, l2, d);
    }
    if (lane == 0) {
        out[w]         = 1.f / (1.f + expf(-(l0 + b2[0])));
        out[B + w]     = 1.f / (1.f + expf(-(l1 + b2[1])));
        out[2 * B + w] = 1.f / (1.f + expf(-(l2 + b2[2])));
    }

    const float* f = FPr + (size_t)w * 128;
    float fv[4], ss = 0.f;
#pragma unroll
    for (int j = 0; j < 4; j++) {
        fv[j] = f[lane + 32 * j];
        ss += fv[j] * fv[j];
    }
#pragma unroll
    for (int d = 16; d; d >>= 1) ss += __shfl_xor_sync(0xffffffffu, ss, d);
    const float nrm = sqrtf(ss);
    const float sc  = 1.f / fmaxf(nrm, 1e-12f);
    float* fo = out + 3L * B + (size_t)w * 128;
#pragma unroll
    for (int j = 0; j < 4; j++) fo[lane + 32 * j] = fv[j] * sc;
}

// ---------------------------------------------------------------------------
// Host orchestration
// ---------------------------------------------------------------------------
extern "C" void kernel_launch(void* const* d_in, const int* in_sizes, int n_in,
                              void* d_out, int out_size)
{
    const float* perc   = (const float*)d_in[0];
    const float* tech   = (const float*)d_in[1];
    const float* Wp     = (const float*)d_in[2];
    const float* bp     = (const float*)d_in[3];
    const float* Wt     = (const float*)d_in[4];
    const float* bt     = (const float*)d_in[5];
    const float* in_w   = (const float*)d_in[6];
    const float* in_b   = (const float*)d_in[7];
    const float* out_w  = (const float*)d_in[8];
    const float* out_b  = (const float*)d_in[9];
    const float* ffn_w1 = (const float*)d_in[10];
    const float* ffn_b1 = (const float*)d_in[11];
    const float* ffn_w2 = (const float*)d_in[12];
    const float* ffn_b2 = (const float*)d_in[13];
    const float* ln1_g  = (const float*)d_in[14];
    const float* ln1_b  = (const float*)d_in[15];
    const float* ln2_g  = (const float*)d_in[16];
    const float* ln2_b  = (const float*)d_in[17];
    const float* cls_w1 = (const float*)d_in[18];
    const float* cls_b1 = (const float*)d_in[19];
    const float* cls_w2 = (const float*)d_in[20];
    const float* cls_b2 = (const float*)d_in[21];
    const float* fp_w   = (const float*)d_in[22];
    const float* fp_b   = (const float*)d_in[23];

    int B = in_sizes[0] / DM;
    if (B > MAXB) B = MAXB;
    const int T = 2 * B;

    float *seq, *qkv, *ctx, *attn, *x, *h, *ffn, *z, *c, *fp;
    cudaGetSymbolAddress((void**)&seq,  g_seq);
    cudaGetSymbolAddress((void**)&qkv,  g_qkv);
    cudaGetSymbolAddress((void**)&ctx,  g_ctx);
    cudaGetSymbolAddress((void**)&attn, g_attn);
    cudaGetSymbolAddress((void**)&x,    g_x);
    cudaGetSymbolAddress((void**)&h,    g_h);
    cudaGetSymbolAddress((void**)&ffn,  g_ffn);
    cudaGetSymbolAddress((void**)&z,    g_z);
    cudaGetSymbolAddress((void**)&c,    g_c);
    cudaGetSymbolAddress((void**)&fp,   g_fp);

    float* out = (float*)d_out;

    // 1) projections -> seq [B,2,192] (row stride 384)
    gemm_tn<false><<<dim3(3, B / 128), 128>>>(perc, 192, Wp, bp, seq, 384, 0,   192);
    gemm_tn<false><<<dim3(3, B / 128), 128>>>(tech, 192, Wt, bt, seq, 384, 192, 192);
    // 2) qkv = seq @ in_w^T + in_b   [2B,576]
    gemm_tn<false><<<dim3(9, T / 128), 128>>>(seq, 192, in_w, in_b, qkv, 576, 0, 192);
    // 3) attention -> ctx [2B,192]
    attn_kernel<<<(B + 7) / 8, 256>>>(qkv, ctx, B);
    // 4) out proj
    gemm_tn<false><<<dim3(3, T / 128), 128>>>(ctx, 192, out_w, out_b, attn, 192, 0, 192);
    // 5) x = LN1(seq + attn)
    add_ln_kernel<<<(T + 7) / 8, 256>>>(seq, attn, ln1_g, ln1_b, x, T);
    // 6) FFN
    gemm_tn<true ><<<dim3(6, T / 128), 128>>>(x, 192, ffn_w1, ffn_b1, h,   384, 0, 192);
    gemm_tn<false><<<dim3(3, T / 128), 128>>>(h, 384, ffn_w2, ffn_b2, ffn, 192, 0, 384);
    // 7) x2 = LN2(x + ffn); z = token mean
    ln2_mean_kernel<<<(B + 7) / 8, 256>>>(x, ffn, ln2_g, ln2_b, z, B);
    // 8) heads
    gemm_tn<true ><<<dim3(3, B / 128), 128>>>(z, 192, cls_w1, cls_b1, c,  192, 0, 192);
    gemm_tn<false><<<dim3(2, B / 128), 128>>>(z, 192, fp_w,   fp_b,   fp, 128, 0, 192);
    head_kernel<<<(B + 7) / 8, 256>>>(c, fp, cls_w2, cls_b2, out, B);
}

// round 2
// speedup vs baseline: 1.0016x; 1.0016x over previous
#include <cuda_runtime.h>
#include <math.h>

// ---------------------------------------------------------------------------
// Problem constants
// ---------------------------------------------------------------------------
constexpr int DM   = 192;      // d_model
constexpr int FPD  = 128;      // fingerprint dim
constexpr int MAXB = 65536;    // batch
constexpr long NT  = 2L * MAXB; // token rows (2 per batch row)

// ---------------------------------------------------------------------------
// Device scratch (static __device__ arrays: the sanctioned no-alloc workaround)
// ---------------------------------------------------------------------------
__device__ float g_seq [NT * DM];        //  96 MB  [2B,192]
__device__ float g_qkv [NT * 3 * DM];    // 288 MB  [2B,576]
__device__ float g_ctx [NT * DM];        //  96 MB
__device__ float g_attn[NT * DM];        //  96 MB
__device__ float g_x   [NT * DM];        //  96 MB
__device__ float g_h   [NT * 2 * DM];    // 192 MB  [2B,384]
__device__ float g_ffn [NT * DM];        //  96 MB
__device__ float g_z   [(long)MAXB * DM];
__device__ float g_c   [(long)MAXB * DM];
__device__ float g_fp  [(long)MAXB * FPD];

// ---------------------------------------------------------------------------
// Tiled fp32 GEMM:  C[m, coff + n] = act( A[m,:] . W[n,:] + bias[n] )
//   A: [M, K] row-major with row stride lda
//   W: [N, K] row-major (torch Linear weight layout)
//   C: row stride ldc, column offset coff
// Tile: BM=128, BN=64, BK=16, 128 threads, 8x8 micro-tile per thread.
// Requires: M % 128 == 0, N % 64 == 0, K % 16 == 0 (true for all our shapes).
// ---------------------------------------------------------------------------
template<bool RELU>
__global__ void __launch_bounds__(128)
gemm_tn(const float* __restrict__ A, int lda,
        const float* __restrict__ W,
        const float* __restrict__ bias,
        float* __restrict__ C, int ldc, int coff,
        int K)
{
    constexpr int BM = 128, BN = 64, BK = 16, TM = 8, TN = 8;
    __shared__ float As[BK][BM];
    __shared__ float Bs[BK][BN];

    const int tid = threadIdx.x;
    const int bx  = blockIdx.x;   // N tile
    const int by  = blockIdx.y;   // M tile
    const int tx  = tid & 7;      // 0..7  -> BN/TN
    const int ty  = tid >> 3;     // 0..15 -> BM/TM

    float acc[TM][TN];
#pragma unroll
    for (int i = 0; i < TM; i++)
#pragma unroll
        for (int j = 0; j < TN; j++) acc[i][j] = 0.f;

    const float* aptr = A + (size_t)(by * BM + tid) * lda;      // one A row per thread
    const int bn = tid >> 1;                                    // 0..63
    const int bk = (tid & 1) * 8;                               // 0 or 8
    const float* bptr = W + (size_t)(bx * BN + bn) * K + bk;

    for (int k0 = 0; k0 < K; k0 += BK) {
        float4 a0 = *(const float4*)(aptr + k0);
        float4 a1 = *(const float4*)(aptr + k0 + 4);
        float4 a2 = *(const float4*)(aptr + k0 + 8);
        float4 a3 = *(const float4*)(aptr + k0 + 12);
        float4 b0 = *(const float4*)(bptr + k0);
        float4 b1 = *(const float4*)(bptr + k0 + 4);

        __syncthreads();   // previous tile fully consumed
        As[ 0][tid] = a0.x; As[ 1][tid] = a0.y; As[ 2][tid] = a0.z; As[ 3][tid] = a0.w;
        As[ 4][tid] = a1.x; As[ 5][tid] = a1.y; As[ 6][tid] = a1.z; As[ 7][tid] = a1.w;
        As[ 8][tid] = a2.x; As[ 9][tid] = a2.y; As[10][tid] = a2.z; As[11][tid] = a2.w;
        As[12][tid] = a3.x; As[13][tid] = a3.y; As[14][tid] = a3.z; As[15][tid] = a3.w;
        Bs[bk + 0][bn] = b0.x; Bs[bk + 1][bn] = b0.y; Bs[bk + 2][bn] = b0.z; Bs[bk + 3][bn] = b0.w;
        Bs[bk + 4][bn] = b1.x; Bs[bk + 5][bn] = b1.y; Bs[bk + 6][bn] = b1.z; Bs[bk + 7][bn] = b1.w;
        __syncthreads();

#pragma unroll
        for (int kk = 0; kk < BK; kk++) {
            float ar[TM], br[TN];
            *(float4*)&ar[0] = *(const float4*)&As[kk][ty * TM];
            *(float4*)&ar[4] = *(const float4*)&As[kk][ty * TM + 4];
            *(float4*)&br[0] = *(const float4*)&Bs[kk][tx * TN];
            *(float4*)&br[4] = *(const float4*)&Bs[kk][tx * TN + 4];
#pragma unroll
            for (int i = 0; i < TM; i++)
#pragma unroll
                for (int j = 0; j < TN; j++)
                    acc[i][j] = fmaf(ar[i], br[j], acc[i][j]);
        }
    }

    float bv[TN];
#pragma unroll
    for (int j = 0; j < TN; j++) bv[j] = bias[bx * BN + tx * TN + j];

#pragma unroll
    for (int i = 0; i < TM; i++) {
        const int row = by * BM + ty * TM + i;
        float* cp = C + (size_t)row * ldc + coff + bx * BN + tx * TN;
        float4 v0, v1;
        v0.x = acc[i][0] + bv[0]; v0.y = acc[i][1] + bv[1];
        v0.z = acc[i][2] + bv[2]; v0.w = acc[i][3] + bv[3];
        v1.x = acc[i][4] + bv[4]; v1.y = acc[i][5] + bv[5];
        v1.z = acc[i][6] + bv[6]; v1.w = acc[i][7] + bv[7];
        if (RELU) {
            v0.x = fmaxf(v0.x, 0.f); v0.y = fmaxf(v0.y, 0.f);
            v0.z = fmaxf(v0.z, 0.f); v0.w = fmaxf(v0.w, 0.f);
            v1.x = fmaxf(v1.x, 0.f); v1.y = fmaxf(v1.y, 0.f);
            v1.z = fmaxf(v1.z, 0.f); v1.w = fmaxf(v1.w, 0.f);
        }
        *(float4*)cp       = v0;
        *(float4*)(cp + 4) = v1;
    }
}

// ---------------------------------------------------------------------------
// Attention over 2-token sequence, 3 heads of 64. One warp per batch row.
// qkv: [2B, 576] (q|k|v), ctx out: [2B, 192]
// ---------------------------------------------------------------------------
__global__ void attn_kernel(const float* __restrict__ qkv, float* __restrict__ ctx, int B)
{
    const int w    = (blockIdx.x * blockDim.x + threadIdx.x) >> 5;
    const int lane = threadIdx.x & 31;
    if (w >= B) return;
    const float* r0 = qkv + (size_t)(2 * w) * 576;
    const float* r1 = r0 + 576;
    float* c0 = ctx + (size_t)(2 * w) * 192;
    float* c1 = c0 + 192;

#pragma unroll
    for (int h = 0; h < 3; h++) {
        const int o = h * 64 + 2 * lane;
        float2 q0 = *(const float2*)(r0 + o);
        float2 q1 = *(const float2*)(r1 + o);
        float2 k0 = *(const float2*)(r0 + 192 + o);
        float2 k1 = *(const float2*)(r1 + 192 + o);
        float2 v0 = *(const float2*)(r0 + 384 + o);
        float2 v1 = *(const float2*)(r1 + 384 + o);

        float s00 = q0.x * k0.x + q0.y * k0.y;
        float s01 = q0.x * k1.x + q0.y * k1.y;
        float s10 = q1.x * k0.x + q1.y * k0.y;
        float s11 = q1.x * k1.x + q1.y * k1.y;
#pragma unroll
        for (int d = 16; d; d >>= 1) {
            s00 += __shfl_xor_sync(0xffffffffu, s00, d);
            s01 += __shfl_xor_sync(0xffffffffu, s01, d);
            s10 += __shfl_xor_sync(0xffffffffu, s10, d);
            s11 += __shfl_xor_sync(0xffffffffu, s11, d);
        }
        s00 *= 0.125f; s01 *= 0.125f; s10 *= 0.125f; s11 *= 0.125f;

        float m0 = fmaxf(s00, s01);
        float e00 = expf(s00 - m0), e01 = expf(s01 - m0);
        float inv0 = 1.f / (e00 + e01);
        float a00 = e00 * inv0, a01 = e01 * inv0;

        float m1 = fmaxf(s10, s11);
        float e10 = expf(s10 - m1), e11 = expf(s11 - m1);
        float inv1 = 1.f / (e10 + e11);
        float a10 = e10 * inv1, a11 = e11 * inv1;

        float2 o0, o1;
        o0.x = a00 * v0.x + a01 * v1.x;  o0.y = a00 * v0.y + a01 * v1.y;
        o1.x = a10 * v0.x + a11 * v1.x;  o1.y = a10 * v0.y + a11 * v1.y;
        *(float2*)(c0 + o) = o0;
        *(float2*)(c1 + o) = o1;
    }
}

// ---------------------------------------------------------------------------
// x = LayerNorm(a + b) * g + beta   (192-wide row, one warp per row)
// ---------------------------------------------------------------------------
__global__ void add_ln_kernel(const float* __restrict__ A, const float* __restrict__ Bq,
                              const float* __restrict__ g, const float* __restrict__ be,
                              float* __restrict__ O, int nrows)
{
    const int w    = (blockIdx.x * blockDim.x + threadIdx.x) >> 5;
    const int lane = threadIdx.x & 31;
    if (w >= nrows) return;
    const float* a = A  + (size_t)w * 192;
    const float* b = Bq + (size_t)w * 192;
    float y[6], s = 0.f, ss = 0.f;
#pragma unroll
    for (int j = 0; j < 6; j++) {
        const int idx = lane + 32 * j;
        y[j] = a[idx] + b[idx];
        s += y[j]; ss += y[j] * y[j];
    }
#pragma unroll
    for (int d = 16; d; d >>= 1) {
        s  += __shfl_xor_sync(0xffffffffu, s,  d);
        ss += __shfl_xor_sync(0xffffffffu, ss, d);
    }
    const float mu  = s * (1.f / 192.f);
    const float var = ss * (1.f / 192.f) - mu * mu;
    const float rs  = rsqrtf(var + 1e-5f);
    float* o = O + (size_t)w * 192;
#pragma unroll
    for (int j = 0; j < 6; j++) {
        const int idx = lane + 32 * j;
        o[idx] = (y[j] - mu) * rs * g[idx] + be[idx];
    }
}

// ---------------------------------------------------------------------------
// x2 = LN(x + ffn); z = mean over the 2 tokens. One warp per batch row.
// ---------------------------------------------------------------------------
__global__ void ln2_mean_kernel(const float* __restrict__ X, const float* __restrict__ F,
                                const float* __restrict__ g, const float* __restrict__ be,
                                float* __restrict__ Z, int B)
{
    const int w    = (blockIdx.x * blockDim.x + threadIdx.x) >> 5;
    const int lane = threadIdx.x & 31;
    if (w >= B) return;
    float zacc[6];
#pragma unroll
    for (int j = 0; j < 6; j++) zacc[j] = 0.f;

#pragma unroll
    for (int t = 0; t < 2; t++) {
        const size_t row = (size_t)(2 * w + t) * 192;
        float y[6], s = 0.f, ss = 0.f;
#pragma unroll
        for (int j = 0; j < 6; j++) {
            const int idx = lane + 32 * j;
            y[j] = X[row + idx] + F[row + idx];
            s += y[j]; ss += y[j] * y[j];
        }
#pragma unroll
        for (int d = 16; d; d >>= 1) {
            s  += __shfl_xor_sync(0xffffffffu, s,  d);
            ss += __shfl_xor_sync(0xffffffffu, ss, d);
        }
        const float mu  = s * (1.f / 192.f);
        const float var = ss * (1.f / 192.f) - mu * mu;
        const float rs  = rsqrtf(var + 1e-5f);
#pragma unroll
        for (int j = 0; j < 6; j++) {
            const int idx = lane + 32 * j;
            zacc[j] += 0.5f * ((y[j] - mu) * rs * g[idx] + be[idx]);
        }
    }
    float* z = Z + (size_t)w * 192;
#pragma unroll
    for (int j = 0; j < 6; j++) z[lane + 32 * j] = zacc[j];
}

// ---------------------------------------------------------------------------
// Final heads: logits = c . cls_w2^T + b2 -> sigmoid -> 3 prob columns;
// fp = normalize(fp_raw). One warp per batch row.
// out layout: [B] p0 | [B] p1 | [B] p2 | [B*128] fp
// ---------------------------------------------------------------------------
__global__ void head_kernel(const float* __restrict__ C, const float* __restrict__ FPr,
                            const float* __restrict__ w2, const float* __restrict__ b2,
                            float* __restrict__ out, int B)
{
    const int w    = (blockIdx.x * blockDim.x + threadIdx.x) >> 5;
    const int lane = threadIdx.x & 31;
    if (w >= B) return;

    const float* c = C + (size_t)w * 192;
    float l0 = 0.f, l1 = 0.f, l2 = 0.f;
#pragma unroll
    for (int j = 0; j < 6; j++) {
        const int idx = lane + 32 * j;
        const float cv = c[idx];
        l0 += cv * w2[idx];
        l1 += cv * w2[192 + idx];
        l2 += cv * w2[384 + idx];
    }
#pragma unroll
    for (int d = 16; d; d >>= 1) {
        l0 += __shfl_xor_sync(0xffffffffu, l0, d);
        l1 += __shfl_xor_sync(0xffffffffu, l1, d);
        l2 += __shfl_xor_sync(0xffffffffu, l2, d);
    }
    if (lane == 0) {
        out[w]         = 1.f / (1.f + expf(-(l0 + b2[0])));
        out[B + w]     = 1.f / (1.f + expf(-(l1 + b2[1])));
        out[2 * B + w] = 1.f / (1.f + expf(-(l2 + b2[2])));
    }

    const float* f = FPr + (size_t)w * 128;
    float fv[4], ss = 0.f;
#pragma unroll
    for (int j = 0; j < 4; j++) {
        fv[j] = f[lane + 32 * j];
        ss += fv[j] * fv[j];
    }
#pragma unroll
    for (int d = 16; d; d >>= 1) ss += __shfl_xor_sync(0xffffffffu, ss, d);
    const float nrm = sqrtf(ss);
    const float sc  = 1.f / fmaxf(nrm, 1e-12f);
    float* fo = out + 3L * B + (size_t)w * 128;
#pragma unroll
    for (int j = 0; j < 4; j++) fo[lane + 32 * j] = fv[j] * sc;
}

// ---------------------------------------------------------------------------
// Host orchestration
// ---------------------------------------------------------------------------
extern "C" void kernel_launch(void* const* d_in, const int* in_sizes, int n_in,
                              void* d_out, int out_size)
{
    const float* perc   = (const float*)d_in[0];
    const float* tech   = (const float*)d_in[1];
    const float* Wp     = (const float*)d_in[2];
    const float* bp     = (const float*)d_in[3];
    const float* Wt     = (const float*)d_in[4];
    const float* bt     = (const float*)d_in[5];
    const float* in_w   = (const float*)d_in[6];
    const float* in_b   = (const float*)d_in[7];
    const float* out_w  = (const float*)d_in[8];
    const float* out_b  = (const float*)d_in[9];
    const float* ffn_w1 = (const float*)d_in[10];
    const float* ffn_b1 = (const float*)d_in[11];
    const float* ffn_w2 = (const float*)d_in[12];
    const float* ffn_b2 = (const float*)d_in[13];
    const float* ln1_g  = (const float*)d_in[14];
    const float* ln1_b  = (const float*)d_in[15];
    const float* ln2_g  = (const float*)d_in[16];
    const float* ln2_b  = (const float*)d_in[17];
    const float* cls_w1 = (const float*)d_in[18];
    const float* cls_b1 = (const float*)d_in[19];
    const float* cls_w2 = (const float*)d_in[20];
    const float* cls_b2 = (const float*)d_in[21];
    const float* fp_w   = (const float*)d_in[22];
    const float* fp_b   = (const float*)d_in[23];

    int B = in_sizes[0] / DM;
    if (B > MAXB) B = MAXB;
    const int T = 2 * B;

    float *seq, *qkv, *ctx, *attn, *x, *h, *ffn, *z, *c, *fp;
    cudaGetSymbolAddress((void**)&seq,  g_seq);
    cudaGetSymbolAddress((void**)&qkv,  g_qkv);
    cudaGetSymbolAddress((void**)&ctx,  g_ctx);
    cudaGetSymbolAddress((void**)&attn, g_attn);
    cudaGetSymbolAddress((void**)&x,    g_x);
    cudaGetSymbolAddress((void**)&h,    g_h);
    cudaGetSymbolAddress((void**)&ffn,  g_ffn);
    cudaGetSymbolAddress((void**)&z,    g_z);
    cudaGetSymbolAddress((void**)&c,    g_c);
    cudaGetSymbolAddress((void**)&fp,   g_fp);

    float* out = (float*)d_out;

    // 1) projections -> seq [B,2,192] (row stride 384)
    gemm_tn<false><<<dim3(3, B / 128), 128>>>(perc, 192, Wp, bp, seq, 384, 0,   192);
    gemm_tn<false><<<dim3(3, B / 128), 128>>>(tech, 192, Wt, bt, seq, 384, 192, 192);
    // 2) qkv = seq @ in_w^T + in_b   [2B,576]
    gemm_tn<false><<<dim3(9, T / 128), 128>>>(seq, 192, in_w, in_b, qkv, 576, 0, 192);
    // 3) attention -> ctx [2B,192]
    attn_kernel<<<(B + 7) / 8, 256>>>(qkv, ctx, B);
    // 4) out proj
    gemm_tn<false><<<dim3(3, T / 128), 128>>>(ctx, 192, out_w, out_b, attn, 192, 0, 192);
    // 5) x = LN1(seq + attn)
    add_ln_kernel<<<(T + 7) / 8, 256>>>(seq, attn, ln1_g, ln1_b, x, T);
    // 6) FFN
    gemm_tn<true ><<<dim3(6, T / 128), 128>>>(x, 192, ffn_w1, ffn_b1, h,   384, 0, 192);
    gemm_tn<false><<<dim3(3, T / 128), 128>>>(h, 384, ffn_w2, ffn_b2, ffn, 192, 0, 384);
    // 7) x2 = LN2(x + ffn); z = token mean
    ln2_mean_kernel<<<(B + 7) / 8, 256>>>(x, ffn, ln2_g, ln2_b, z, B);
    // 8) heads
    gemm_tn<true ><<<dim3(3, B / 128), 128>>>(z, 192, cls_w1, cls_b1, c,  192, 0, 192);
    gemm_tn<false><<<dim3(2, B / 128), 128>>>(z, 192, fp_w,   fp_b,   fp, 128, 0, 192);
    head_kernel<<<(B + 7) / 8, 256>>>(c, fp, cls_w2, cls_b2, out, B);
}

// round 5
// speedup vs baseline: 1.7065x; 1.7038x over previous
#include <cuda_runtime.h>
#include <cuda_bf16.h>
#include <stdint.h>
#include <string.h>
#include <math.h>

constexpr int DM = 192;
constexpr int MAXB = 65536;
constexpr long NT = 2L * MAXB;

__device__ float g_seq[NT * DM];
__device__ float g_qkv[NT * 3 * DM];
__device__ float g_ctx[NT * DM];
__device__ float g_attn[NT * DM];
__device__ float g_x[NT * DM];
__device__ float g_h[NT * 2 * DM];
__device__ float g_ffn[NT * DM];
__device__ float g_z[(long)MAXB * DM];
__device__ float g_c[(long)MAXB * DM];
__device__ float g_fp[(long)MAXB * 128];

__device__ __forceinline__ void mma16816(float* c, const uint32_t* a, const uint32_t* b) {
    asm volatile(
        "mma.sync.aligned.m16n8k16.row.col.f32.bf16.bf16.f32 "
        "{%0,%1,%2,%3}, {%4,%5,%6,%7}, {%8,%9}, {%0,%1,%2,%3};"
        : "+f"(c[0]), "+f"(c[1]), "+f"(c[2]), "+f"(c[3])
        : "r"(a[0]), "r"(a[1]), "r"(a[2]), "r"(a[3]), "r"(b[0]), "r"(b[1]));
}

// ---------------------------------------------------------------------------
// Split-precision bf16 HMMA GEMM: C[m, coff+n] = act(A[m,:] . W[n,:] + bias[n])
// A:[M,K] fp32 stride lda; W:[N,K] fp32 (torch Linear). Tile 128x64xBK32.
// 8 warps in 4(m) x 2(n); warp tile 32x32; mma m16n8k16.
// Requires M%128==0, N%64==0, K%32==0.
// ---------------------------------------------------------------------------
template<bool RELU>
__global__ void __launch_bounds__(256)
tc_gemm(const float* __restrict__ A, int lda, const float* __restrict__ W,
        const float* __restrict__ bias, float* __restrict__ C, int ldc, int coff, int K)
{
    // padded rows: 32 k -> 16 b32 data, padded to 20 b32 (80B) for conflict-free LDS
    __shared__ __align__(16) uint32_t sm32[7680];
    uint32_t* Ah32 = sm32;              // 128*20
    uint32_t* Al32 = sm32 + 2560;
    uint32_t* Bh32 = sm32 + 5120;       // 64*20
    uint32_t* Bl32 = sm32 + 6400;

    const int tid = threadIdx.x;
    const int wid = tid >> 5, lane = tid & 31;
    const int wr = wid >> 1, wc = wid & 1;           // 4 x 2 warp grid
    const int m0 = blockIdx.y * 128, n0 = blockIdx.x * 64;
    const int lg = lane >> 2, lq = lane & 3;

    float acc[2][4][4];
#pragma unroll
    for (int i = 0; i < 2; i++)
#pragma unroll
        for (int j = 0; j < 4; j++)
#pragma unroll
            for (int q = 0; q < 4; q++) acc[i][j][q] = 0.f;

    const int r2 = tid >> 1;        // 0..127
    const int half = tid & 1;       // k-half (16 floats)

    for (int k0 = 0; k0 < K; k0 += 32) {
        // ---- load + split A: 128 rows x 32 k; 2 threads/row, 16 floats each
        {
            const float* ap = A + (size_t)(m0 + r2) * lda + k0 + half * 16;
            float v[16];
            *(float4*)(v)      = *(const float4*)(ap);
            *(float4*)(v + 4)  = *(const float4*)(ap + 4);
            *(float4*)(v + 8)  = *(const float4*)(ap + 8);
            *(float4*)(v + 12) = *(const float4*)(ap + 12);
            const int base = r2 * 20 + half * 8;
#pragma unroll
            for (int q = 0; q < 8; q++) {
                float x = v[2 * q], y = v[2 * q + 1];
                __nv_bfloat162 h = __floats2bfloat162_rn(x, y);
                float2 hf = __bfloat1622float2(h);
                __nv_bfloat162 lo = __floats2bfloat162_rn(x - hf.x, y - hf.y);
                uint32_t uh, ul;
                memcpy(&uh, &h, 4); memcpy(&ul, &lo, 4);
                Ah32[base + q] = uh;
                Al32[base + q] = ul;
            }
        }
        // ---- load + split B: 64 rows x 32 k (threads 0..127)
        if (tid < 128) {
            const int rb = tid >> 1, hb = tid & 1;
            const float* wp = W + (size_t)(n0 + rb) * K + k0 + hb * 16;
            float v[16];
            *(float4*)(v)      = *(const float4*)(wp);
            *(float4*)(v + 4)  = *(const float4*)(wp + 4);
            *(float4*)(v + 8)  = *(const float4*)(wp + 8);
            *(float4*)(v + 12) = *(const float4*)(wp + 12);
            const int base = rb * 20 + hb * 8;
#pragma unroll
            for (int q = 0; q < 8; q++) {
                float x = v[2 * q], y = v[2 * q + 1];
                __nv_bfloat162 h = __floats2bfloat162_rn(x, y);
                float2 hf = __bfloat1622float2(h);
                __nv_bfloat162 lo = __floats2bfloat162_rn(x - hf.x, y - hf.y);
                uint32_t uh, ul;
                memcpy(&uh, &h, 4); memcpy(&ul, &lo, 4);
                Bh32[base + q] = uh;
                Bl32[base + q] = ul;
            }
        }
        __syncthreads();

#pragma unroll
        for (int s = 0; s < 2; s++) {
            uint32_t ah[2][4], al[2][4], bh[4][2], bl[4][2];
#pragma unroll
            for (int i = 0; i < 2; i++) {
                const int row = wr * 32 + i * 16 + lg;
                const int i0 = row * 20 + s * 8 + lq;
                const int i1 = (row + 8) * 20 + s * 8 + lq;
                ah[i][0] = Ah32[i0]; ah[i][1] = Ah32[i1];
                ah[i][2] = Ah32[i0 + 4]; ah[i][3] = Ah32[i1 + 4];
                al[i][0] = Al32[i0]; al[i][1] = Al32[i1];
                al[i][2] = Al32[i0 + 4]; al[i][3] = Al32[i1 + 4];
            }
#pragma unroll
            for (int j = 0; j < 4; j++) {
                const int n = wc * 32 + j * 8 + lg;
                const int b0 = n * 20 + s * 8 + lq;
                bh[j][0] = Bh32[b0]; bh[j][1] = Bh32[b0 + 4];
                bl[j][0] = Bl32[b0]; bl[j][1] = Bl32[b0 + 4];
            }
#pragma unroll
            for (int i = 0; i < 2; i++)
#pragma unroll
                for (int j = 0; j < 4; j++) {
                    mma16816(acc[i][j], ah[i], bh[j]);
                    mma16816(acc[i][j], ah[i], bl[j]);
                    mma16816(acc[i][j], al[i], bh[j]);
                }
        }
        __syncthreads();
    }

    // ---- epilogue: bias (+relu), direct global stores
#pragma unroll
    for (int i = 0; i < 2; i++) {
        const int row = m0 + wr * 32 + i * 16 + lg;
#pragma unroll
        for (int j = 0; j < 4; j++) {
            const int col = n0 + wc * 32 + j * 8 + 2 * lq;
            const float bx = bias[col], by = bias[col + 1];
            float2 v0, v1;
            v0.x = acc[i][j][0] + bx; v0.y = acc[i][j][1] + by;
            v1.x = acc[i][j][2] + bx; v1.y = acc[i][j][3] + by;
            if (RELU) {
                v0.x = fmaxf(v0.x, 0.f); v0.y = fmaxf(v0.y, 0.f);
                v1.x = fmaxf(v1.x, 0.f); v1.y = fmaxf(v1.y, 0.f);
            }
            *(float2*)(C + (size_t)row * ldc + coff + col) = v0;
            *(float2*)(C + (size_t)(row + 8) * ldc + coff + col) = v1;
        }
    }
}

// ---------------- elementwise kernels ----------------
__global__ void attn_kernel(const float* __restrict__ qkv, float* __restrict__ ctx, int B)
{
    const int w = (blockIdx.x * blockDim.x + threadIdx.x) >> 5;
    const int lane = threadIdx.x & 31;
    if (w >= B) return;
    const float* r0 = qkv + (size_t)(2 * w) * 576;
    const float* r1 = r0 + 576;
    float* c0 = ctx + (size_t)(2 * w) * 192;
    float* c1 = c0 + 192;
#pragma unroll
    for (int h = 0; h < 3; h++) {
        const int o = h * 64 + 2 * lane;
        float2 q0 = *(const float2*)(r0 + o);
        float2 q1 = *(const float2*)(r1 + o);
        float2 k0 = *(const float2*)(r0 + 192 + o);
        float2 k1 = *(const float2*)(r1 + 192 + o);
        float2 v0 = *(const float2*)(r0 + 384 + o);
        float2 v1 = *(const float2*)(r1 + 384 + o);
        float s00 = q0.x * k0.x + q0.y * k0.y;
        float s01 = q0.x * k1.x + q0.y * k1.y;
        float s10 = q1.x * k0.x + q1.y * k0.y;
        float s11 = q1.x * k1.x + q1.y * k1.y;
#pragma unroll
        for (int d = 16; d; d >>= 1) {
            s00 += __shfl_xor_sync(0xffffffffu, s00, d);
            s01 += __shfl_xor_sync(0xffffffffu, s01, d);
            s10 += __shfl_xor_sync(0xffffffffu, s10, d);
            s11 += __shfl_xor_sync(0xffffffffu, s11, d);
        }
        s00 *= 0.125f; s01 *= 0.125f; s10 *= 0.125f; s11 *= 0.125f;
        float m0 = fmaxf(s00, s01);
        float e00 = expf(s00 - m0), e01 = expf(s01 - m0);
        float i0 = 1.f / (e00 + e01);
        float m1 = fmaxf(s10, s11);
        float e10 = expf(s10 - m1), e11 = expf(s11 - m1);
        float i1 = 1.f / (e10 + e11);
        float a00 = e00 * i0, a01 = e01 * i0, a10 = e10 * i1, a11 = e11 * i1;
        float2 o0, o1;
        o0.x = a00 * v0.x + a01 * v1.x; o0.y = a00 * v0.y + a01 * v1.y;
        o1.x = a10 * v0.x + a11 * v1.x; o1.y = a10 * v0.y + a11 * v1.y;
        *(float2*)(c0 + o) = o0;
        *(float2*)(c1 + o) = o1;
    }
}

__global__ void add_ln_kernel(const float* __restrict__ A, const float* __restrict__ Bq,
                              const float* __restrict__ g, const float* __restrict__ be,
                              float* __restrict__ O, int nrows)
{
    const int w = (blockIdx.x * blockDim.x + threadIdx.x) >> 5;
    const int lane = threadIdx.x & 31;
    if (w >= nrows) return;
    const float* a = A + (size_t)w * 192;
    const float* b = Bq + (size_t)w * 192;
    float y[6], s = 0.f, ss = 0.f;
#pragma unroll
    for (int j = 0; j < 6; j++) {
        const int idx = lane + 32 * j;
        y[j] = a[idx] + b[idx];
        s += y[j]; ss += y[j] * y[j];
    }
#pragma unroll
    for (int d = 16; d; d >>= 1) {
        s += __shfl_xor_sync(0xffffffffu, s, d);
        ss += __shfl_xor_sync(0xffffffffu, ss, d);
    }
    const float mu = s * (1.f / 192.f);
    const float rs = rsqrtf(ss * (1.f / 192.f) - mu * mu + 1e-5f);
    float* o = O + (size_t)w * 192;
#pragma unroll
    for (int j = 0; j < 6; j++) {
        const int idx = lane + 32 * j;
        o[idx] = (y[j] - mu) * rs * g[idx] + be[idx];
    }
}

__global__ void ln2_mean_kernel(const float* __restrict__ X, const float* __restrict__ F,
                                const float* __restrict__ g, const float* __restrict__ be,
                                float* __restrict__ Z, int B)
{
    const int w = (blockIdx.x * blockDim.x + threadIdx.x) >> 5;
    const int lane = threadIdx.x & 31;
    if (w >= B) return;
    float zacc[6];
#pragma unroll
    for (int j = 0; j < 6; j++) zacc[j] = 0.f;
#pragma unroll
    for (int t = 0; t < 2; t++) {
        const size_t row = (size_t)(2 * w + t) * 192;
        float y[6], s = 0.f, ss = 0.f;
#pragma unroll
        for (int j = 0; j < 6; j++) {
            const int idx = lane + 32 * j;
            y[j] = X[row + idx] + F[row + idx];
            s += y[j]; ss += y[j] * y[j];
        }
#pragma unroll
        for (int d = 16; d; d >>= 1) {
            s += __shfl_xor_sync(0xffffffffu, s, d);
            ss += __shfl_xor_sync(0xffffffffu, ss, d);
        }
        const float mu = s * (1.f / 192.f);
        const float rs = rsqrtf(ss * (1.f / 192.f) - mu * mu + 1e-5f);
#pragma unroll
        for (int j = 0; j < 6; j++) {
            const int idx = lane + 32 * j;
            zacc[j] += 0.5f * ((y[j] - mu) * rs * g[idx] + be[idx]);
        }
    }
    float* z = Z + (size_t)w * 192;
#pragma unroll
    for (int j = 0; j < 6; j++) z[lane + 32 * j] = zacc[j];
}

__global__ void head_kernel(const float* __restrict__ C, const float* __restrict__ FPr,
                            const float* __restrict__ w2, const float* __restrict__ b2,
                            float* __restrict__ out, int B)
{
    const int w = (blockIdx.x * blockDim.x + threadIdx.x) >> 5;
    const int lane = threadIdx.x & 31;
    if (w >= B) return;
    const float* c = C + (size_t)w * 192;
    float l0 = 0.f, l1 = 0.f, l2 = 0.f;
#pragma unroll
    for (int j = 0; j < 6; j++) {
        const int idx = lane + 32 * j;
        const float cv = c[idx];
        l0 += cv * w2[idx];
        l1 += cv * w2[192 + idx];
        l2 += cv * w2[384 + idx];
    }
#pragma unroll
    for (int d = 16; d; d >>= 1) {
        l0 += __shfl_xor_sync(0xffffffffu, l0, d);
        l1 += __shfl_xor_sync(0xffffffffu, l1, d);
        l2 += __shfl_xor_sync(0xffffffffu, l2, d);
    }
    if (lane == 0) {
        out[w]         = 1.f / (1.f + expf(-(l0 + b2[0])));
        out[B + w]     = 1.f / (1.f + expf(-(l1 + b2[1])));
        out[2 * B + w] = 1.f / (1.f + expf(-(l2 + b2[2])));
    }
    const float* f = FPr + (size_t)w * 128;
    float fv[4], ss = 0.f;
#pragma unroll
    for (int j = 0; j < 4; j++) {
        fv[j] = f[lane + 32 * j];
        ss += fv[j] * fv[j];
    }
#pragma unroll
    for (int d = 16; d; d >>= 1) ss += __shfl_xor_sync(0xffffffffu, ss, d);
    const float sc = 1.f / fmaxf(sqrtf(ss), 1e-12f);
    float* fo = out + 3L * B + (size_t)w * 128;
#pragma unroll
    for (int j = 0; j < 4; j++) fo[lane + 32 * j] = fv[j] * sc;
}

// ---------------- host ----------------
extern "C" void kernel_launch(void* const* d_in, const int* in_sizes, int n_in,
                              void* d_out, int out_size)
{
    const float* perc   = (const float*)d_in[0];
    const float* tech   = (const float*)d_in[1];
    const float* Wp     = (const float*)d_in[2];
    const float* bp     = (const float*)d_in[3];
    const float* Wt     = (const float*)d_in[4];
    const float* bt     = (const float*)d_in[5];
    const float* in_w   = (const float*)d_in[6];
    const float* in_b   = (const float*)d_in[7];
    const float* out_w  = (const float*)d_in[8];
    const float* out_b  = (const float*)d_in[9];
    const float* ffn_w1 = (const float*)d_in[10];
    const float* ffn_b1 = (const float*)d_in[11];
    const float* ffn_w2 = (const float*)d_in[12];
    const float* ffn_b2 = (const float*)d_in[13];
    const float* ln1_g  = (const float*)d_in[14];
    const float* ln1_b  = (const float*)d_in[15];
    const float* ln2_g  = (const float*)d_in[16];
    const float* ln2_b  = (const float*)d_in[17];
    const float* cls_w1 = (const float*)d_in[18];
    const float* cls_b1 = (const float*)d_in[19];
    const float* cls_w2 = (const float*)d_in[20];
    const float* cls_b2 = (const float*)d_in[21];
    const float* fp_w   = (const float*)d_in[22];
    const float* fp_b   = (const float*)d_in[23];

    int B = in_sizes[0] / DM;
    if (B > MAXB) B = MAXB;
    const int T = 2 * B;

    float *seq, *qkv, *ctx, *attn, *x, *h, *ffn, *z, *c, *fp;
    cudaGetSymbolAddress((void**)&seq,  g_seq);
    cudaGetSymbolAddress((void**)&qkv,  g_qkv);
    cudaGetSymbolAddress((void**)&ctx,  g_ctx);
    cudaGetSymbolAddress((void**)&attn, g_attn);
    cudaGetSymbolAddress((void**)&x,    g_x);
    cudaGetSymbolAddress((void**)&h,    g_h);
    cudaGetSymbolAddress((void**)&ffn,  g_ffn);
    cudaGetSymbolAddress((void**)&z,    g_z);
    cudaGetSymbolAddress((void**)&c,    g_c);
    cudaGetSymbolAddress((void**)&fp,   g_fp);

    float* out = (float*)d_out;

    tc_gemm<false><<<dim3(3, B / 128), 256>>>(perc, 192, Wp, bp, seq, 384, 0,   192);
    tc_gemm<false><<<dim3(3, B / 128), 256>>>(tech, 192, Wt, bt, seq, 384, 192, 192);
    tc_gemm<false><<<dim3(9, T / 128), 256>>>(seq, 192, in_w, in_b, qkv, 576, 0, 192);
    attn_kernel<<<(B + 7) / 8, 256>>>(qkv, ctx, B);
    tc_gemm<false><<<dim3(3, T / 128), 256>>>(ctx, 192, out_w, out_b, attn, 192, 0, 192);
    add_ln_kernel<<<(T + 7) / 8, 256>>>(seq, attn, ln1_g, ln1_b, x, T);
    tc_gemm<true ><<<dim3(6, T / 128), 256>>>(x, 192, ffn_w1, ffn_b1, h, 384, 0, 192);
    tc_gemm<false><<<dim3(3, T / 128), 256>>>(h, 384, ffn_w2, ffn_b2, ffn, 192, 0, 384);
    ln2_mean_kernel<<<(B + 7) / 8, 256>>>(x, ffn, ln2_g, ln2_b, z, B);
    tc_gemm<true ><<<dim3(3, B / 128), 256>>>(z, 192, cls_w1, cls_b1, c, 192, 0, 192);
    tc_gemm<false><<<dim3(2, B / 128), 256>>>(z, 192, fp_w, fp_b, fp, 128, 0, 192);
    head_kernel<<<(B + 7) / 8, 256>>>(c, fp, cls_w2, cls_b2, out, B);
}

// round 7
// speedup vs baseline: 1.9008x; 1.1138x over previous
#include <cuda_runtime.h>
#include <cuda_bf16.h>
#include <stdint.h>
#include <string.h>
#include <math.h>

typedef __nv_bfloat16 bf16;
typedef __nv_bfloat162 bf162;

constexpr int DM = 192;
constexpr int MAXB = 65536;
constexpr long NT = 2L * MAXB;

// fp32 scratch
__device__ float g_seq[NT * DM];
__device__ float g_qkv[NT * 3 * DM];
__device__ float g_attn[NT * DM];
__device__ float g_x[NT * DM];
__device__ float g_ffn[NT * DM];
__device__ float g_c[(long)MAXB * DM];
__device__ float g_fp[(long)MAXB * 128];

// bf16 split scratch (hi/lo)
__device__ bf16 g_pa_hi[(long)MAXB * DM], g_pa_lo[(long)MAXB * DM];
__device__ bf16 g_ta_hi[(long)MAXB * DM], g_ta_lo[(long)MAXB * DM];
__device__ bf16 g_seq_hi[NT * DM], g_seq_lo[NT * DM];
__device__ bf16 g_ctx_hi[NT * DM], g_ctx_lo[NT * DM];
__device__ bf16 g_x_hi[NT * DM], g_x_lo[NT * DM];
__device__ bf16 g_h_hi[NT * 2 * DM], g_h_lo[NT * 2 * DM];
__device__ bf16 g_z_hi[(long)MAXB * DM], g_z_lo[(long)MAXB * DM];

// weight split scratch
constexpr int OW_P = 0, OW_T = 36864, OW_IN = 73728, OW_OUT = 184320;
constexpr int OW_F1 = 221184, OW_F2 = 294912, OW_CLS = 368640, OW_FP = 405504;
constexpr int OW_TOT = 430080;
__device__ bf16 g_whi[OW_TOT], g_wlo[OW_TOT];

// ---------------- split kernel: fp32 -> bf16 hi + lo ----------------
__global__ void split_k(const float* __restrict__ s, bf16* __restrict__ hi,
                        bf16* __restrict__ lo, long n)
{
    long i = 4L * (blockIdx.x * (long)blockDim.x + threadIdx.x);
    if (i >= n) return;
    float4 v = *(const float4*)(s + i);
    bf162 h01 = __floats2bfloat162_rn(v.x, v.y);
    bf162 h23 = __floats2bfloat162_rn(v.z, v.w);
    float2 f01 = __bfloat1622float2(h01);
    float2 f23 = __bfloat1622float2(h23);
    bf162 l01 = __floats2bfloat162_rn(v.x - f01.x, v.y - f01.y);
    bf162 l23 = __floats2bfloat162_rn(v.z - f23.x, v.w - f23.y);
    *(bf162*)(hi + i) = h01; *(bf162*)(hi + i + 2) = h23;
    *(bf162*)(lo + i) = l01; *(bf162*)(lo + i + 2) = l23;
}

__device__ __forceinline__ void mma16816(float* c, const uint32_t* a, const uint32_t* b) {
    asm volatile(
        "mma.sync.aligned.m16n8k16.row.col.f32.bf16.bf16.f32 "
        "{%0,%1,%2,%3}, {%4,%5,%6,%7}, {%8,%9}, {%0,%1,%2,%3};"
        : "+f"(c[0]), "+f"(c[1]), "+f"(c[2]), "+f"(c[3])
        : "r"(a[0]), "r"(a[1]), "r"(a[2]), "r"(a[3]), "r"(b[0]), "r"(b[1]));
}

__device__ __forceinline__ void split2(float x, float y, uint32_t& h, uint32_t& l) {
    bf162 hb = __floats2bfloat162_rn(x, y);
    float2 hf = __bfloat1622float2(hb);
    bf162 lb = __floats2bfloat162_rn(x - hf.x, y - hf.y);
    memcpy(&h, &hb, 4); memcpy(&l, &lb, 4);
}

// ---------------------------------------------------------------------------
// Split bf16 HMMA GEMM on pre-split operands.
// C = act(A . W^T + bias); A hi/lo [M,K] bf16 stride lda; W hi/lo [N,K] bf16.
// Tile 128x64xBK32; 8 warps 4x2; warp tile 32x32.
// ---------------------------------------------------------------------------
template<bool RELU, bool WF32, bool WSPLIT>
__global__ void __launch_bounds__(256)
tc_gemm(const bf16* __restrict__ Ahg, const bf16* __restrict__ Alg, int lda,
        const bf16* __restrict__ Whg, const bf16* __restrict__ Wlg,
        const float* __restrict__ bias,
        float* __restrict__ C, int ldc, int coff,
        bf16* __restrict__ Sh, bf16* __restrict__ Sl, int lds_, int scoff,
        int K)
{
    __shared__ __align__(16) uint32_t sm32[7680];
    uint32_t* Ah32 = sm32;
    uint32_t* Al32 = sm32 + 2560;
    uint32_t* Bh32 = sm32 + 5120;
    uint32_t* Bl32 = sm32 + 6400;

    const int tid = threadIdx.x;
    const int wid = tid >> 5, lane = tid & 31;
    const int wr = wid >> 1, wc = wid & 1;
    const int m0 = blockIdx.y * 128, n0 = blockIdx.x * 64;
    const int lg = lane >> 2, lq = lane & 3;

    float acc[2][4][4];
#pragma unroll
    for (int i = 0; i < 2; i++)
#pragma unroll
        for (int j = 0; j < 4; j++)
#pragma unroll
            for (int q = 0; q < 4; q++) acc[i][j][q] = 0.f;

    const int lr = tid >> 2;       // 0..63
    const int seg = tid & 3;       // 16B segment

    for (int k0 = 0; k0 < K; k0 += 32) {
#pragma unroll
        for (int it = 0; it < 2; it++) {
            const int r = lr + it * 64;
            const size_t go = (size_t)(m0 + r) * lda + k0 + seg * 8;
            *(uint4*)(Ah32 + r * 20 + seg * 4) = *(const uint4*)(Ahg + go);
            *(uint4*)(Al32 + r * 20 + seg * 4) = *(const uint4*)(Alg + go);
        }
        {
            const size_t go = (size_t)(n0 + lr) * K + k0 + seg * 8;
            *(uint4*)(Bh32 + lr * 20 + seg * 4) = *(const uint4*)(Whg + go);
            *(uint4*)(Bl32 + lr * 20 + seg * 4) = *(const uint4*)(Wlg + go);
        }
        __syncthreads();

#pragma unroll
        for (int s = 0; s < 2; s++) {
            uint32_t ah[2][4], al[2][4], bh[4][2], bl[4][2];
#pragma unroll
            for (int i = 0; i < 2; i++) {
                const int row = wr * 32 + i * 16 + lg;
                const int i0 = row * 20 + s * 8 + lq;
                const int i1 = (row + 8) * 20 + s * 8 + lq;
                ah[i][0] = Ah32[i0]; ah[i][1] = Ah32[i1];
                ah[i][2] = Ah32[i0 + 4]; ah[i][3] = Ah32[i1 + 4];
                al[i][0] = Al32[i0]; al[i][1] = Al32[i1];
                al[i][2] = Al32[i0 + 4]; al[i][3] = Al32[i1 + 4];
            }
#pragma unroll
            for (int j = 0; j < 4; j++) {
                const int n = wc * 32 + j * 8 + lg;
                const int b0 = n * 20 + s * 8 + lq;
                bh[j][0] = Bh32[b0]; bh[j][1] = Bh32[b0 + 4];
                bl[j][0] = Bl32[b0]; bl[j][1] = Bl32[b0 + 4];
            }
#pragma unroll
            for (int i = 0; i < 2; i++)
#pragma unroll
                for (int j = 0; j < 4; j++) {
                    mma16816(acc[i][j], ah[i], bh[j]);
                    mma16816(acc[i][j], ah[i], bl[j]);
                    mma16816(acc[i][j], al[i], bh[j]);
                }
        }
        __syncthreads();
    }

#pragma unroll
    for (int i = 0; i < 2; i++) {
        const int row = m0 + wr * 32 + i * 16 + lg;
#pragma unroll
        for (int j = 0; j < 4; j++) {
            const int col = n0 + wc * 32 + j * 8 + 2 * lq;
            const float bx = bias[col], by = bias[col + 1];
            float2 v0, v1;
            v0.x = acc[i][j][0] + bx; v0.y = acc[i][j][1] + by;
            v1.x = acc[i][j][2] + bx; v1.y = acc[i][j][3] + by;
            if (RELU) {
                v0.x = fmaxf(v0.x, 0.f); v0.y = fmaxf(v0.y, 0.f);
                v1.x = fmaxf(v1.x, 0.f); v1.y = fmaxf(v1.y, 0.f);
            }
            if (WF32) {
                *(float2*)(C + (size_t)row * ldc + coff + col) = v0;
                *(float2*)(C + (size_t)(row + 8) * ldc + coff + col) = v1;
            }
            if (WSPLIT) {
                uint32_t h0, l0, h1, l1;
                split2(v0.x, v0.y, h0, l0);
                split2(v1.x, v1.y, h1, l1);
                *(uint32_t*)(Sh + (size_t)row * lds_ + scoff + col) = h0;
                *(uint32_t*)(Sl + (size_t)row * lds_ + scoff + col) = l0;
                *(uint32_t*)(Sh + (size_t)(row + 8) * lds_ + scoff + col) = h1;
                *(uint32_t*)(Sl + (size_t)(row + 8) * lds_ + scoff + col) = l1;
            }
        }
    }
}

// ---------------- elementwise ----------------
__global__ void attn_kernel(const float* __restrict__ qkv, bf16* __restrict__ ch,
                            bf16* __restrict__ cl, int B)
{
    const int w = (blockIdx.x * blockDim.x + threadIdx.x) >> 5;
    const int lane = threadIdx.x & 31;
    if (w >= B) return;
    const float* r0 = qkv + (size_t)(2 * w) * 576;
    const float* r1 = r0 + 576;
    const size_t o0r = (size_t)(2 * w) * 192, o1r = o0r + 192;
#pragma unroll
    for (int h = 0; h < 3; h++) {
        const int o = h * 64 + 2 * lane;
        float2 q0 = *(const float2*)(r0 + o);
        float2 q1 = *(const float2*)(r1 + o);
        float2 k0 = *(const float2*)(r0 + 192 + o);
        float2 k1 = *(const float2*)(r1 + 192 + o);
        float2 v0 = *(const float2*)(r0 + 384 + o);
        float2 v1 = *(const float2*)(r1 + 384 + o);
        float s00 = q0.x * k0.x + q0.y * k0.y;
        float s01 = q0.x * k1.x + q0.y * k1.y;
        float s10 = q1.x * k0.x + q1.y * k0.y;
        float s11 = q1.x * k1.x + q1.y * k1.y;
#pragma unroll
        for (int d = 16; d; d >>= 1) {
            s00 += __shfl_xor_sync(0xffffffffu, s00, d);
            s01 += __shfl_xor_sync(0xffffffffu, s01, d);
            s10 += __shfl_xor_sync(0xffffffffu, s10, d);
            s11 += __shfl_xor_sync(0xffffffffu, s11, d);
        }
        s00 *= 0.125f; s01 *= 0.125f; s10 *= 0.125f; s11 *= 0.125f;
        float m0 = fmaxf(s00, s01);
        float e00 = expf(s00 - m0), e01 = expf(s01 - m0);
        float i0 = 1.f / (e00 + e01);
        float m1 = fmaxf(s10, s11);
        float e10 = expf(s10 - m1), e11 = expf(s11 - m1);
        float i1 = 1.f / (e10 + e11);
        float a00 = e00 * i0, a01 = e01 * i0, a10 = e10 * i1, a11 = e11 * i1;
        float ox0 = a00 * v0.x + a01 * v1.x, oy0 = a00 * v0.y + a01 * v1.y;
        float ox1 = a10 * v0.x + a11 * v1.x, oy1 = a10 * v0.y + a11 * v1.y;
        uint32_t h0, l0, h1, l1;
        split2(ox0, oy0, h0, l0);
        split2(ox1, oy1, h1, l1);
        *(uint32_t*)(ch + o0r + o) = h0; *(uint32_t*)(cl + o0r + o) = l0;
        *(uint32_t*)(ch + o1r + o) = h1; *(uint32_t*)(cl + o1r + o) = l1;
    }
}

__global__ void add_ln_kernel(const float* __restrict__ A, const float* __restrict__ Bq,
                              const float* __restrict__ g, const float* __restrict__ be,
                              float* __restrict__ O, bf16* __restrict__ Oh,
                              bf16* __restrict__ Ol, int nrows)
{
    const int w = (blockIdx.x * blockDim.x + threadIdx.x) >> 5;
    const int lane = threadIdx.x & 31;
    if (w >= nrows) return;
    const float* a = A + (size_t)w * 192;
    const float* b = Bq + (size_t)w * 192;
    float y[6], s = 0.f, ss = 0.f;
#pragma unroll
    for (int j = 0; j < 6; j++) {
        const int idx = lane + 32 * j;
        y[j] = a[idx] + b[idx];
        s += y[j]; ss += y[j] * y[j];
    }
#pragma unroll
    for (int d = 16; d; d >>= 1) {
        s += __shfl_xor_sync(0xffffffffu, s, d);
        ss += __shfl_xor_sync(0xffffffffu, ss, d);
    }
    const float mu = s * (1.f / 192.f);
    const float rs = rsqrtf(ss * (1.f / 192.f) - mu * mu + 1e-5f);
    float* o = O + (size_t)w * 192;
#pragma unroll
    for (int j = 0; j < 6; j++) {
        const int idx = lane + 32 * j;
        float v = (y[j] - mu) * rs * g[idx] + be[idx];
        o[idx] = v;
        bf16 h = __float2bfloat16_rn(v);
        Oh[(size_t)w * 192 + idx] = h;
        Ol[(size_t)w * 192 + idx] = __float2bfloat16_rn(v - __bfloat162float(h));
    }
}

__global__ void ln2_mean_kernel(const float* __restrict__ X, const float* __restrict__ F,
                                const float* __restrict__ g, const float* __restrict__ be,
                                bf16* __restrict__ Zh, bf16* __restrict__ Zl, int B)
{
    const int w = (blockIdx.x * blockDim.x + threadIdx.x) >> 5;
    const int lane = threadIdx.x & 31;
    if (w >= B) return;
    float zacc[6];
#pragma unroll
    for (int j = 0; j < 6; j++) zacc[j] = 0.f;
#pragma unroll
    for (int t = 0; t < 2; t++) {
        const size_t row = (size_t)(2 * w + t) * 192;
        float y[6], s = 0.f, ss = 0.f;
#pragma unroll
        for (int j = 0; j < 6; j++) {
            const int idx = lane + 32 * j;
            y[j] = X[row + idx] + F[row + idx];
            s += y[j]; ss += y[j] * y[j];
        }
#pragma unroll
        for (int d = 16; d; d >>= 1) {
            s += __shfl_xor_sync(0xffffffffu, s, d);
            ss += __shfl_xor_sync(0xffffffffu, ss, d);
        }
        const float mu = s * (1.f / 192.f);
        const float rs = rsqrtf(ss * (1.f / 192.f) - mu * mu + 1e-5f);
#pragma unroll
        for (int j = 0; j < 6; j++) {
            const int idx = lane + 32 * j;
            zacc[j] += 0.5f * ((y[j] - mu) * rs * g[idx] + be[idx]);
        }
    }
#pragma unroll
    for (int j = 0; j < 6; j++) {
        const int idx = lane + 32 * j;
        bf16 h = __float2bfloat16_rn(zacc[j]);
        Zh[(size_t)w * 192 + idx] = h;
        Zl[(size_t)w * 192 + idx] = __float2bfloat16_rn(zacc[j] - __bfloat162float(h));
    }
}

__global__ void head_kernel(const float* __restrict__ C, const float* __restrict__ FPr,
                            const float* __restrict__ w2, const float* __restrict__ b2,
                            float* __restrict__ out, int B)
{
    const int w = (blockIdx.x * blockDim.x + threadIdx.x) >> 5;
    const int lane = threadIdx.x & 31;
    if (w >= B) return;
    const float* c = C + (size_t)w * 192;
    float l0 = 0.f, l1 = 0.f, l2 = 0.f;
#pragma unroll
    for (int j = 0; j < 6; j++) {
        const int idx = lane + 32 * j;
        const float cv = c[idx];
        l0 += cv * w2[idx];
        l1 += cv * w2[192 + idx];
        l2 += cv * w2[384 + idx];
    }
#pragma unroll
    for (int d = 16; d; d >>= 1) {
        l0 += __shfl_xor_sync(0xffffffffu, l0, d);
        l1 += __shfl_xor_sync(0xffffffffu, l1, d);
        l2 += __shfl_xor_sync(0xffffffffu, l2, d);
    }
    if (lane == 0) {
        out[w]         = 1.f / (1.f + expf(-(l0 + b2[0])));
        out[B + w]     = 1.f / (1.f + expf(-(l1 + b2[1])));
        out[2 * B + w] = 1.f / (1.f + expf(-(l2 + b2[2])));
    }
    const float* f = FPr + (size_t)w * 128;
    float fv[4], ss = 0.f;
#pragma unroll
    for (int j = 0; j < 4; j++) {
        fv[j] = f[lane + 32 * j];
        ss += fv[j] * fv[j];
    }
#pragma unroll
    for (int d = 16; d; d >>= 1) ss += __shfl_xor_sync(0xffffffffu, ss, d);
    const float sc = 1.f / fmaxf(sqrtf(ss), 1e-12f);
    float* fo = out + 3L * B + (size_t)w * 128;
#pragma unroll
    for (int j = 0; j < 4; j++) fo[lane + 32 * j] = fv[j] * sc;
}

// ---------------- host ----------------
static inline void dsym(void** p, const void* sym) { cudaGetSymbolAddress(p, sym); }

extern "C" void kernel_launch(void* const* d_in, const int* in_sizes, int n_in,
                              void* d_out, int out_size)
{
    const float* perc   = (const float*)d_in[0];
    const float* tech   = (const float*)d_in[1];
    const float* Wp     = (const float*)d_in[2];
    const float* bp     = (const float*)d_in[3];
    const float* Wt     = (const float*)d_in[4];
    const float* bt     = (const float*)d_in[5];
    const float* in_w   = (const float*)d_in[6];
    const float* in_b   = (const float*)d_in[7];
    const float* out_w  = (const float*)d_in[8];
    const float* out_b  = (const float*)d_in[9];
    const float* ffn_w1 = (const float*)d_in[10];
    const float* ffn_b1 = (const float*)d_in[11];
    const float* ffn_w2 = (const float*)d_in[12];
    const float* ffn_b2 = (const float*)d_in[13];
    const float* ln1_g  = (const float*)d_in[14];
    const float* ln1_b  = (const float*)d_in[15];
    const float* ln2_g  = (const float*)d_in[16];
    const float* ln2_b  = (const float*)d_in[17];
    const float* cls_w1 = (const float*)d_in[18];
    const float* cls_b1 = (const float*)d_in[19];
    const float* cls_w2 = (const float*)d_in[20];
    const float* cls_b2 = (const float*)d_in[21];
    const float* fp_w   = (const float*)d_in[22];
    const float* fp_b   = (const float*)d_in[23];

    int B = in_sizes[0] / DM;
    if (B > MAXB) B = MAXB;
    const int T = 2 * B;

    float *seq, *qkv, *attnf, *x, *ffn, *c, *fp;
    dsym((void**)&seq, g_seq); dsym((void**)&qkv, g_qkv); dsym((void**)&attnf, g_attn);
    dsym((void**)&x, g_x); dsym((void**)&ffn, g_ffn); dsym((void**)&c, g_c);
    dsym((void**)&fp, g_fp);

    bf16 *pah, *pal, *tah, *tal, *seqh, *seql, *ctxh, *ctxl, *xh, *xl, *hh, *hl, *zh, *zl, *whi, *wlo;
    dsym((void**)&pah, g_pa_hi); dsym((void**)&pal, g_pa_lo);
    dsym((void**)&tah, g_ta_hi); dsym((void**)&tal, g_ta_lo);
    dsym((void**)&seqh, g_seq_hi); dsym((void**)&seql, g_seq_lo);
    dsym((void**)&ctxh, g_ctx_hi); dsym((void**)&ctxl, g_ctx_lo);
    dsym((void**)&xh, g_x_hi); dsym((void**)&xl, g_x_lo);
    dsym((void**)&hh, g_h_hi); dsym((void**)&hl, g_h_lo);
    dsym((void**)&zh, g_z_hi); dsym((void**)&zl, g_z_lo);
    dsym((void**)&whi, g_whi); dsym((void**)&wlo, g_wlo);

    float* out = (float*)d_out;

    auto spl = [&](const float* s, bf16* h, bf16* l, long n) {
        split_k<<<(int)((n / 4 + 255) / 256), 256>>>(s, h, l, n);
    };
    // weights + inputs
    spl(Wp, whi + OW_P, wlo + OW_P, 36864);
    spl(Wt, whi + OW_T, wlo + OW_T, 36864);
    spl(in_w, whi + OW_IN, wlo + OW_IN, 110592);
    spl(out_w, whi + OW_OUT, wlo + OW_OUT, 36864);
    spl(ffn_w1, whi + OW_F1, wlo + OW_F1, 73728);
    spl(ffn_w2, whi + OW_F2, wlo + OW_F2, 73728);
    spl(cls_w1, whi + OW_CLS, wlo + OW_CLS, 36864);
    spl(fp_w, whi + OW_FP, wlo + OW_FP, 24576);
    spl(perc, pah, pal, (long)B * 192);
    spl(tech, tah, tal, (long)B * 192);

    // projections -> seq fp32 + split  (seq stored [B,384]; token view is [2B,192])
    tc_gemm<false, true, true><<<dim3(3, B / 128), 256>>>(
        pah, pal, 192, whi + OW_P, wlo + OW_P, bp, seq, 384, 0, seqh, seql, 384, 0, 192);
    tc_gemm<false, true, true><<<dim3(3, B / 128), 256>>>(
        tah, tal, 192, whi + OW_T, wlo + OW_T, bt, seq, 384, 192, seqh, seql, 384, 192, 192);
    // qkv: seq token view [2B,192] -> lda = 192 (FIX: was 384)
    tc_gemm<false, true, false><<<dim3(9, T / 128), 256>>>(
        seqh, seql, 192, whi + OW_IN, wlo + OW_IN, in_b, qkv, 576, 0, nullptr, nullptr, 0, 0, 192);
    attn_kernel<<<(B + 7) / 8, 256>>>(qkv, ctxh, ctxl, B);
    // out proj
    tc_gemm<false, true, false><<<dim3(3, T / 128), 256>>>(
        ctxh, ctxl, 192, whi + OW_OUT, wlo + OW_OUT, out_b, attnf, 192, 0, nullptr, nullptr, 0, 0, 192);
    add_ln_kernel<<<(T + 7) / 8, 256>>>(seq, attnf, ln1_g, ln1_b, x, xh, xl, T);
    // ffn
    tc_gemm<true, false, true><<<dim3(6, T / 128), 256>>>(
        xh, xl, 192, whi + OW_F1, wlo + OW_F1, ffn_b1, nullptr, 0, 0, hh, hl, 384, 0, 192);
    tc_gemm<false, true, false><<<dim3(3, T / 128), 256>>>(
        hh, hl, 384, whi + OW_F2, wlo + OW_F2, ffn_b2, ffn, 192, 0, nullptr, nullptr, 0, 0, 384);
    ln2_mean_kernel<<<(B + 7) / 8, 256>>>(x, ffn, ln2_g, ln2_b, zh, zl, B);
    // heads
    tc_gemm<true, true, false><<<dim3(3, B / 128), 256>>>(
        zh, zl, 192, whi + OW_CLS, wlo + OW_CLS, cls_b1, c, 192, 0, nullptr, nullptr, 0, 0, 192);
    tc_gemm<false, true, false><<<dim3(2, B / 128), 256>>>(
        zh, zl, 192, whi + OW_FP, wlo + OW_FP, fp_b, fp, 128, 0, nullptr, nullptr, 0, 0, 192);
    head_kernel<<<(B + 7) / 8, 256>>>(c, fp, cls_w2, cls_b2, out, B);
}

// round 8
// speedup vs baseline: 2.1551x; 1.1338x over previous
#include <cuda_runtime.h>
#include <cuda_bf16.h>
#include <stdint.h>
#include <string.h>
#include <math.h>

typedef __nv_bfloat16 bf16;
typedef __nv_bfloat162 bf162;

constexpr int DM = 192;
constexpr int MAXB = 65536;
constexpr long NT = 2L * MAXB;

// fp32 scratch
__device__ float g_seq[NT * DM];
__device__ float g_qkv[NT * 3 * DM];
__device__ float g_attn[NT * DM];
__device__ float g_x[NT * DM];
__device__ float g_ffn[NT * DM];
__device__ float g_c[(long)MAXB * DM];
__device__ float g_fp[(long)MAXB * 128];

// bf16 split scratch (hi/lo)
__device__ bf16 g_pa_hi[(long)MAXB * DM], g_pa_lo[(long)MAXB * DM];
__device__ bf16 g_ta_hi[(long)MAXB * DM], g_ta_lo[(long)MAXB * DM];
__device__ bf16 g_seq_hi[NT * DM], g_seq_lo[NT * DM];
__device__ bf16 g_ctx_hi[NT * DM], g_ctx_lo[NT * DM];
__device__ bf16 g_x_hi[NT * DM], g_x_lo[NT * DM];
__device__ bf16 g_h_hi[NT * 2 * DM], g_h_lo[NT * 2 * DM];
__device__ bf16 g_z_hi[(long)MAXB * DM], g_z_lo[(long)MAXB * DM];

// weight split scratch
constexpr int OW_P = 0, OW_T = 36864, OW_IN = 73728, OW_OUT = 184320;
constexpr int OW_F1 = 221184, OW_F2 = 294912, OW_CLS = 368640, OW_FP = 405504;
constexpr int OW_TOT = 430080;
__device__ bf16 g_whi[OW_TOT], g_wlo[OW_TOT];

// ---------------- helpers ----------------
__device__ __forceinline__ uint32_t smem_u32(const void* p) {
    uint32_t a;
    asm("{ .reg .u64 t; cvta.to.shared.u64 t, %1; cvt.u32.u64 %0, t; }" : "=r"(a) : "l"(p));
    return a;
}
__device__ __forceinline__ void cp16(uint32_t dst, const void* src) {
    asm volatile("cp.async.cg.shared.global [%0], [%1], 16;" :: "r"(dst), "l"(src));
}
__device__ __forceinline__ void cp_commit() { asm volatile("cp.async.commit_group;"); }
__device__ __forceinline__ void cp_wait1() { asm volatile("cp.async.wait_group 1;"); }
__device__ __forceinline__ void ldsm_x4(uint32_t* r, uint32_t addr) {
    asm volatile("ldmatrix.sync.aligned.m8n8.x4.shared.b16 {%0,%1,%2,%3}, [%4];"
        : "=r"(r[0]), "=r"(r[1]), "=r"(r[2]), "=r"(r[3]) : "r"(addr));
}
__device__ __forceinline__ void mma16816(float* c, const uint32_t* a, const uint32_t* b) {
    asm volatile(
        "mma.sync.aligned.m16n8k16.row.col.f32.bf16.bf16.f32 "
        "{%0,%1,%2,%3}, {%4,%5,%6,%7}, {%8,%9}, {%0,%1,%2,%3};"
        : "+f"(c[0]), "+f"(c[1]), "+f"(c[2]), "+f"(c[3])
        : "r"(a[0]), "r"(a[1]), "r"(a[2]), "r"(a[3]), "r"(b[0]), "r"(b[1]));
}
__device__ __forceinline__ void split2(float x, float y, uint32_t& h, uint32_t& l) {
    bf162 hb = __floats2bfloat162_rn(x, y);
    float2 hf = __bfloat1622float2(hb);
    bf162 lb = __floats2bfloat162_rn(x - hf.x, y - hf.y);
    memcpy(&h, &hb, 4); memcpy(&l, &lb, 4);
}

__global__ void split_k(const float* __restrict__ s, bf16* __restrict__ hi,
                        bf16* __restrict__ lo, long n)
{
    long i = 4L * (blockIdx.x * (long)blockDim.x + threadIdx.x);
    if (i >= n) return;
    float4 v = *(const float4*)(s + i);
    uint32_t h0, l0, h1, l1;
    split2(v.x, v.y, h0, l0);
    split2(v.z, v.w, h1, l1);
    *(uint32_t*)(hi + i) = h0; *(uint32_t*)(hi + i + 2) = h1;
    *(uint32_t*)(lo + i) = l0; *(uint32_t*)(lo + i + 2) = l1;
}

// ---------------------------------------------------------------------------
// Split bf16 HMMA GEMM, cp.async double-buffered, ldmatrix fragment loads.
// C = act(A . W^T + bias). Tile 128x64xBK32; 8 warps 4x2; warp tile 32x32.
// Stage layout (u32 idx): Ah[0,2560) Al[2560,5120) Bh[5120,6400) Bl[6400,7680)
// rows padded to 20 u32. Two stages.
// ---------------------------------------------------------------------------
constexpr int STG = 7680;
constexpr int GEMM_SMEM = 2 * STG * 4;   // 61440 B

template<bool RELU, bool WF32, bool WSPLIT>
__global__ void __launch_bounds__(256)
tc_gemm(const bf16* __restrict__ Ahg, const bf16* __restrict__ Alg, int lda,
        const bf16* __restrict__ Whg, const bf16* __restrict__ Wlg,
        const float* __restrict__ bias,
        float* __restrict__ C, int ldc, int coff,
        bf16* __restrict__ Sh, bf16* __restrict__ Sl, int lds_, int scoff,
        int K)
{
    extern __shared__ __align__(16) uint32_t sm32[];
    const uint32_t sbase = smem_u32(sm32);

    const int tid = threadIdx.x;
    const int wid = tid >> 5, lane = tid & 31;
    const int wr = wid >> 1, wc = wid & 1;
    const int m0 = blockIdx.y * 128, n0 = blockIdx.x * 64;

    float acc[2][4][4];
#pragma unroll
    for (int i = 0; i < 2; i++)
#pragma unroll
        for (int j = 0; j < 4; j++)
#pragma unroll
            for (int q = 0; q < 4; q++) acc[i][j][q] = 0.f;

    const int lr = tid >> 2, seg = tid & 3;

    // ldmatrix per-lane base indices (u32 units, without k-step/stage)
    const int t7 = lane & 7, mi = lane >> 3;
    const int aRow0 = wr * 32 + t7 + (mi & 1) * 8;       // + i*16
    const int aCol  = (mi >> 1) * 4;
    const int bRow0 = wc * 32 + t7 + (mi >> 1) * 8;      // + jp*16
    const int bCol  = (mi & 1) * 4;

    const int nc = K >> 5;

    auto issue = [&](int c, int buf) {
        const int k0 = c << 5;
        const uint32_t sb = sbase + buf * (STG * 4);
#pragma unroll
        for (int it = 0; it < 2; it++) {
            const int r = lr + it * 64;
            const size_t go = (size_t)(m0 + r) * lda + k0 + seg * 8;
            cp16(sb + (r * 20 + seg * 4) * 4, Ahg + go);
            cp16(sb + (2560 + r * 20 + seg * 4) * 4, Alg + go);
        }
        const size_t gb = (size_t)(n0 + lr) * K + k0 + seg * 8;
        cp16(sb + (5120 + lr * 20 + seg * 4) * 4, Whg + gb);
        cp16(sb + (6400 + lr * 20 + seg * 4) * 4, Wlg + gb);
    };

    issue(0, 0);
    cp_commit();

    for (int c = 0; c < nc; c++) {
        if (c + 1 < nc) issue(c + 1, (c + 1) & 1);
        cp_commit();
        cp_wait1();
        __syncthreads();

        const uint32_t sb = sbase + (c & 1) * (STG * 4);
#pragma unroll
        for (int s = 0; s < 2; s++) {
            uint32_t ah[2][4], al[2][4], bh[4][2], bl[4][2];
#pragma unroll
            for (int i = 0; i < 2; i++) {
                const uint32_t ai = (uint32_t)((aRow0 + i * 16) * 20 + s * 8 + aCol) * 4;
                ldsm_x4(ah[i], sb + ai);
                ldsm_x4(al[i], sb + 2560 * 4 + ai);
            }
#pragma unroll
            for (int jp = 0; jp < 2; jp++) {
                const uint32_t bi = (uint32_t)((bRow0 + jp * 16) * 20 + s * 8 + bCol) * 4;
                uint32_t tb[4];
                ldsm_x4(tb, sb + 5120 * 4 + bi);
                bh[2 * jp][0] = tb[0]; bh[2 * jp][1] = tb[1];
                bh[2 * jp + 1][0] = tb[2]; bh[2 * jp + 1][1] = tb[3];
                ldsm_x4(tb, sb + 6400 * 4 + bi);
                bl[2 * jp][0] = tb[0]; bl[2 * jp][1] = tb[1];
                bl[2 * jp + 1][0] = tb[2]; bl[2 * jp + 1][1] = tb[3];
            }
#pragma unroll
            for (int i = 0; i < 2; i++)
#pragma unroll
                for (int j = 0; j < 4; j++) {
                    mma16816(acc[i][j], ah[i], bh[j]);
                    mma16816(acc[i][j], ah[i], bl[j]);
                    mma16816(acc[i][j], al[i], bh[j]);
                }
        }
        __syncthreads();
    }

    const int lg = lane >> 2, lq = lane & 3;
#pragma unroll
    for (int i = 0; i < 2; i++) {
        const int row = m0 + wr * 32 + i * 16 + lg;
#pragma unroll
        for (int j = 0; j < 4; j++) {
            const int col = n0 + wc * 32 + j * 8 + 2 * lq;
            const float bx = bias[col], by = bias[col + 1];
            float2 v0, v1;
            v0.x = acc[i][j][0] + bx; v0.y = acc[i][j][1] + by;
            v1.x = acc[i][j][2] + bx; v1.y = acc[i][j][3] + by;
            if (RELU) {
                v0.x = fmaxf(v0.x, 0.f); v0.y = fmaxf(v0.y, 0.f);
                v1.x = fmaxf(v1.x, 0.f); v1.y = fmaxf(v1.y, 0.f);
            }
            if (WF32) {
                *(float2*)(C + (size_t)row * ldc + coff + col) = v0;
                *(float2*)(C + (size_t)(row + 8) * ldc + coff + col) = v1;
            }
            if (WSPLIT) {
                uint32_t h0, l0, h1, l1;
                split2(v0.x, v0.y, h0, l0);
                split2(v1.x, v1.y, h1, l1);
                *(uint32_t*)(Sh + (size_t)row * lds_ + scoff + col) = h0;
                *(uint32_t*)(Sl + (size_t)row * lds_ + scoff + col) = l0;
                *(uint32_t*)(Sh + (size_t)(row + 8) * lds_ + scoff + col) = h1;
                *(uint32_t*)(Sl + (size_t)(row + 8) * lds_ + scoff + col) = l1;
            }
        }
    }
}

// ---------------- elementwise ----------------
__global__ void attn_kernel(const float* __restrict__ qkv, bf16* __restrict__ ch,
                            bf16* __restrict__ cl, int B)
{
    const int w = (blockIdx.x * blockDim.x + threadIdx.x) >> 5;
    const int lane = threadIdx.x & 31;
    if (w >= B) return;
    const float* r0 = qkv + (size_t)(2 * w) * 576;
    const float* r1 = r0 + 576;
    const size_t o0r = (size_t)(2 * w) * 192, o1r = o0r + 192;
#pragma unroll
    for (int h = 0; h < 3; h++) {
        const int o = h * 64 + 2 * lane;
        float2 q0 = *(const float2*)(r0 + o);
        float2 q1 = *(const float2*)(r1 + o);
        float2 k0 = *(const float2*)(r0 + 192 + o);
        float2 k1 = *(const float2*)(r1 + 192 + o);
        float2 v0 = *(const float2*)(r0 + 384 + o);
        float2 v1 = *(const float2*)(r1 + 384 + o);
        float s00 = q0.x * k0.x + q0.y * k0.y;
        float s01 = q0.x * k1.x + q0.y * k1.y;
        float s10 = q1.x * k0.x + q1.y * k0.y;
        float s11 = q1.x * k1.x + q1.y * k1.y;
#pragma unroll
        for (int d = 16; d; d >>= 1) {
            s00 += __shfl_xor_sync(0xffffffffu, s00, d);
            s01 += __shfl_xor_sync(0xffffffffu, s01, d);
            s10 += __shfl_xor_sync(0xffffffffu, s10, d);
            s11 += __shfl_xor_sync(0xffffffffu, s11, d);
        }
        s00 *= 0.125f; s01 *= 0.125f; s10 *= 0.125f; s11 *= 0.125f;
        float m0 = fmaxf(s00, s01);
        float e00 = expf(s00 - m0), e01 = expf(s01 - m0);
        float i0 = 1.f / (e00 + e01);
        float m1 = fmaxf(s10, s11);
        float e10 = expf(s10 - m1), e11 = expf(s11 - m1);
        float i1 = 1.f / (e10 + e11);
        float a00 = e00 * i0, a01 = e01 * i0, a10 = e10 * i1, a11 = e11 * i1;
        float ox0 = a00 * v0.x + a01 * v1.x, oy0 = a00 * v0.y + a01 * v1.y;
        float ox1 = a10 * v0.x + a11 * v1.x, oy1 = a10 * v0.y + a11 * v1.y;
        uint32_t h0, l0, h1, l1;
        split2(ox0, oy0, h0, l0);
        split2(ox1, oy1, h1, l1);
        *(uint32_t*)(ch + o0r + o) = h0; *(uint32_t*)(cl + o0r + o) = l0;
        *(uint32_t*)(ch + o1r + o) = h1; *(uint32_t*)(cl + o1r + o) = l1;
    }
}

__global__ void add_ln_kernel(const float* __restrict__ A, const float* __restrict__ Bq,
                              const float* __restrict__ g, const float* __restrict__ be,
                              float* __restrict__ O, bf16* __restrict__ Oh,
                              bf16* __restrict__ Ol, int nrows)
{
    const int w = (blockIdx.x * blockDim.x + threadIdx.x) >> 5;
    const int lane = threadIdx.x & 31;
    if (w >= nrows) return;
    const float* a = A + (size_t)w * 192;
    const float* b = Bq + (size_t)w * 192;
    float y[6], s = 0.f, ss = 0.f;
#pragma unroll
    for (int j = 0; j < 6; j++) {
        const int idx = lane + 32 * j;
        y[j] = a[idx] + b[idx];
        s += y[j]; ss += y[j] * y[j];
    }
#pragma unroll
    for (int d = 16; d; d >>= 1) {
        s += __shfl_xor_sync(0xffffffffu, s, d);
        ss += __shfl_xor_sync(0xffffffffu, ss, d);
    }
    const float mu = s * (1.f / 192.f);
    const float rs = rsqrtf(ss * (1.f / 192.f) - mu * mu + 1e-5f);
    float* o = O + (size_t)w * 192;
#pragma unroll
    for (int j = 0; j < 6; j++) {
        const int idx = lane + 32 * j;
        float v = (y[j] - mu) * rs * g[idx] + be[idx];
        o[idx] = v;
        bf16 h = __float2bfloat16_rn(v);
        Oh[(size_t)w * 192 + idx] = h;
        Ol[(size_t)w * 192 + idx] = __float2bfloat16_rn(v - __bfloat162float(h));
    }
}

__global__ void ln2_mean_kernel(const float* __restrict__ X, const float* __restrict__ F,
                                const float* __restrict__ g, const float* __restrict__ be,
                                bf16* __restrict__ Zh, bf16* __restrict__ Zl, int B)
{
    const int w = (blockIdx.x * blockDim.x + threadIdx.x) >> 5;
    const int lane = threadIdx.x & 31;
    if (w >= B) return;
    float zacc[6];
#pragma unroll
    for (int j = 0; j < 6; j++) zacc[j] = 0.f;
#pragma unroll
    for (int t = 0; t < 2; t++) {
        const size_t row = (size_t)(2 * w + t) * 192;
        float y[6], s = 0.f, ss = 0.f;
#pragma unroll
        for (int j = 0; j < 6; j++) {
            const int idx = lane + 32 * j;
            y[j] = X[row + idx] + F[row + idx];
            s += y[j]; ss += y[j] * y[j];
        }
#pragma unroll
        for (int d = 16; d; d >>= 1) {
            s += __shfl_xor_sync(0xffffffffu, s, d);
            ss += __shfl_xor_sync(0xffffffffu, ss, d);
        }
        const float mu = s * (1.f / 192.f);
        const float rs = rsqrtf(ss * (1.f / 192.f) - mu * mu + 1e-5f);
#pragma unroll
        for (int j = 0; j < 6; j++) {
            const int idx = lane + 32 * j;
            zacc[j] += 0.5f * ((y[j] - mu) * rs * g[idx] + be[idx]);
        }
    }
#pragma unroll
    for (int j = 0; j < 6; j++) {
        const int idx = lane + 32 * j;
        bf16 h = __float2bfloat16_rn(zacc[j]);
        Zh[(size_t)w * 192 + idx] = h;
        Zl[(size_t)w * 192 + idx] = __float2bfloat16_rn(zacc[j] - __bfloat162float(h));
    }
}

__global__ void head_kernel(const float* __restrict__ C, const float* __restrict__ FPr,
                            const float* __restrict__ w2, const float* __restrict__ b2,
                            float* __restrict__ out, int B)
{
    const int w = (blockIdx.x * blockDim.x + threadIdx.x) >> 5;
    const int lane = threadIdx.x & 31;
    if (w >= B) return;
    const float* c = C + (size_t)w * 192;
    float l0 = 0.f, l1 = 0.f, l2 = 0.f;
#pragma unroll
    for (int j = 0; j < 6; j++) {
        const int idx = lane + 32 * j;
        const float cv = c[idx];
        l0 += cv * w2[idx];
        l1 += cv * w2[192 + idx];
        l2 += cv * w2[384 + idx];
    }
#pragma unroll
    for (int d = 16; d; d >>= 1) {
        l0 += __shfl_xor_sync(0xffffffffu, l0, d);
        l1 += __shfl_xor_sync(0xffffffffu, l1, d);
        l2 += __shfl_xor_sync(0xffffffffu, l2, d);
    }
    if (lane == 0) {
        out[w]         = 1.f / (1.f + expf(-(l0 + b2[0])));
        out[B + w]     = 1.f / (1.f + expf(-(l1 + b2[1])));
        out[2 * B + w] = 1.f / (1.f + expf(-(l2 + b2[2])));
    }
    const float* f = FPr + (size_t)w * 128;
    float fv[4], ss = 0.f;
#pragma unroll
    for (int j = 0; j < 4; j++) {
        fv[j] = f[lane + 32 * j];
        ss += fv[j] * fv[j];
    }
#pragma unroll
    for (int d = 16; d; d >>= 1) ss += __shfl_xor_sync(0xffffffffu, ss, d);
    const float sc = 1.f / fmaxf(sqrtf(ss), 1e-12f);
    float* fo = out + 3L * B + (size_t)w * 128;
#pragma unroll
    for (int j = 0; j < 4; j++) fo[lane + 32 * j] = fv[j] * sc;
}

// ---------------- host ----------------
static inline void dsym(void** p, const void* sym) { cudaGetSymbolAddress(p, sym); }

extern "C" void kernel_launch(void* const* d_in, const int* in_sizes, int n_in,
                              void* d_out, int out_size)
{
    const float* perc   = (const float*)d_in[0];
    const float* tech   = (const float*)d_in[1];
    const float* Wp     = (const float*)d_in[2];
    const float* bp     = (const float*)d_in[3];
    const float* Wt     = (const float*)d_in[4];
    const float* bt     = (const float*)d_in[5];
    const float* in_w   = (const float*)d_in[6];
    const float* in_b   = (const float*)d_in[7];
    const float* out_w  = (const float*)d_in[8];
    const float* out_b  = (const float*)d_in[9];
    const float* ffn_w1 = (const float*)d_in[10];
    const float* ffn_b1 = (const float*)d_in[11];
    const float* ffn_w2 = (const float*)d_in[12];
    const float* ffn_b2 = (const float*)d_in[13];
    const float* ln1_g  = (const float*)d_in[14];
    const float* ln1_b  = (const float*)d_in[15];
    const float* ln2_g  = (const float*)d_in[16];
    const float* ln2_b  = (const float*)d_in[17];
    const float* cls_w1 = (const float*)d_in[18];
    const float* cls_b1 = (const float*)d_in[19];
    const float* cls_w2 = (const float*)d_in[20];
    const float* cls_b2 = (const float*)d_in[21];
    const float* fp_w   = (const float*)d_in[22];
    const float* fp_b   = (const float*)d_in[23];

    int B = in_sizes[0] / DM;
    if (B > MAXB) B = MAXB;
    const int T = 2 * B;

    float *seq, *qkv, *attnf, *x, *ffn, *c, *fp;
    dsym((void**)&seq, g_seq); dsym((void**)&qkv, g_qkv); dsym((void**)&attnf, g_attn);
    dsym((void**)&x, g_x); dsym((void**)&ffn, g_ffn); dsym((void**)&c, g_c);
    dsym((void**)&fp, g_fp);

    bf16 *pah, *pal, *tah, *tal, *seqh, *seql, *ctxh, *ctxl, *xh, *xl, *hh, *hl, *zh, *zl, *whi, *wlo;
    dsym((void**)&pah, g_pa_hi); dsym((void**)&pal, g_pa_lo);
    dsym((void**)&tah, g_ta_hi); dsym((void**)&tal, g_ta_lo);
    dsym((void**)&seqh, g_seq_hi); dsym((void**)&seql, g_seq_lo);
    dsym((void**)&ctxh, g_ctx_hi); dsym((void**)&ctxl, g_ctx_lo);
    dsym((void**)&xh, g_x_hi); dsym((void**)&xl, g_x_lo);
    dsym((void**)&hh, g_h_hi); dsym((void**)&hl, g_h_lo);
    dsym((void**)&zh, g_z_hi); dsym((void**)&zl, g_z_lo);
    dsym((void**)&whi, g_whi); dsym((void**)&wlo, g_wlo);

    cudaFuncSetAttribute(tc_gemm<false, true,  true >, cudaFuncAttributeMaxDynamicSharedMemorySize, GEMM_SMEM);
    cudaFuncSetAttribute(tc_gemm<false, true,  false>, cudaFuncAttributeMaxDynamicSharedMemorySize, GEMM_SMEM);
    cudaFuncSetAttribute(tc_gemm<true,  false, true >, cudaFuncAttributeMaxDynamicSharedMemorySize, GEMM_SMEM);
    cudaFuncSetAttribute(tc_gemm<true,  true,  false>, cudaFuncAttributeMaxDynamicSharedMemorySize, GEMM_SMEM);

    float* out = (float*)d_out;

    auto spl = [&](const float* s, bf16* h, bf16* l, long n) {
        split_k<<<(int)((n / 4 + 255) / 256), 256>>>(s, h, l, n);
    };
    spl(Wp, whi + OW_P, wlo + OW_P, 36864);
    spl(Wt, whi + OW_T, wlo + OW_T, 36864);
    spl(in_w, whi + OW_IN, wlo + OW_IN, 110592);
    spl(out_w, whi + OW_OUT, wlo + OW_OUT, 36864);
    spl(ffn_w1, whi + OW_F1, wlo + OW_F1, 73728);
    spl(ffn_w2, whi + OW_F2, wlo + OW_F2, 73728);
    spl(cls_w1, whi + OW_CLS, wlo + OW_CLS, 36864);
    spl(fp_w, whi + OW_FP, wlo + OW_FP, 24576);
    spl(perc, pah, pal, (long)B * 192);
    spl(tech, tah, tal, (long)B * 192);

    // projections -> seq fp32 + split (seq stored [B,384]; token view [2B,192])
    tc_gemm<false, true, true><<<dim3(3, B / 128), 256, GEMM_SMEM>>>(
        pah, pal, 192, whi + OW_P, wlo + OW_P, bp, seq, 384, 0, seqh, seql, 384, 0, 192);
    tc_gemm<false, true, true><<<dim3(3, B / 128), 256, GEMM_SMEM>>>(
        tah, tal, 192, whi + OW_T, wlo + OW_T, bt, seq, 384, 192, seqh, seql, 384, 192, 192);
    // qkv: token view -> lda 192
    tc_gemm<false, true, false><<<dim3(9, T / 128), 256, GEMM_SMEM>>>(
        seqh, seql, 192, whi + OW_IN, wlo + OW_IN, in_b, qkv, 576, 0, nullptr, nullptr, 0, 0, 192);
    attn_kernel<<<(B + 7) / 8, 256>>>(qkv, ctxh, ctxl, B);
    tc_gemm<false, true, false><<<dim3(3, T / 128), 256, GEMM_SMEM>>>(
        ctxh, ctxl, 192, whi + OW_OUT, wlo + OW_OUT, out_b, attnf, 192, 0, nullptr, nullptr, 0, 0, 192);
    add_ln_kernel<<<(T + 7) / 8, 256>>>(seq, attnf, ln1_g, ln1_b, x, xh, xl, T);
    tc_gemm<true, false, true><<<dim3(6, T / 128), 256, GEMM_SMEM>>>(
        xh, xl, 192, whi + OW_F1, wlo + OW_F1, ffn_b1, nullptr, 0, 0, hh, hl, 384, 0, 192);
    tc_gemm<false, true, false><<<dim3(3, T / 128), 256, GEMM_SMEM>>>(
        hh, hl, 384, whi + OW_F2, wlo + OW_F2, ffn_b2, ffn, 192, 0, nullptr, nullptr, 0, 0, 384);
    ln2_mean_kernel<<<(B + 7) / 8, 256>>>(x, ffn, ln2_g, ln2_b, zh, zl, B);
    tc_gemm<true, true, false><<<dim3(3, B / 128), 256, GEMM_SMEM>>>(
        zh, zl, 192, whi + OW_CLS, wlo + OW_CLS, cls_b1, c, 192, 0, nullptr, nullptr, 0, 0, 192);
    tc_gemm<false, true, false><<<dim3(2, B / 128), 256, GEMM_SMEM>>>(
        zh, zl, 192, whi + OW_FP, wlo + OW_FP, fp_b, fp, 128, 0, nullptr, nullptr, 0, 0, 192);
    head_kernel<<<(B + 7) / 8, 256>>>(c, fp, cls_w2, cls_b2, out, B);
}

// round 9
// speedup vs baseline: 2.2804x; 1.0581x over previous
#include <cuda_runtime.h>
#include <cuda_bf16.h>
#include <stdint.h>
#include <string.h>
#include <math.h>

typedef __nv_bfloat16 bf16;
typedef __nv_bfloat162 bf162;

constexpr int DM = 192;
constexpr int MAXB = 65536;
constexpr long NT = 2L * MAXB;

// fp32 scratch
__device__ float g_seq[NT * DM];
__device__ float g_qkv[NT * 3 * DM];
__device__ float g_attn[NT * DM];
__device__ float g_x[NT * DM];
__device__ float g_ffn[NT * DM];
__device__ float g_c[(long)MAXB * DM];
__device__ float g_fp[(long)MAXB * 128];

// bf16 split scratch (hi/lo)
__device__ bf16 g_pa_hi[(long)MAXB * DM], g_pa_lo[(long)MAXB * DM];
__device__ bf16 g_ta_hi[(long)MAXB * DM], g_ta_lo[(long)MAXB * DM];
__device__ bf16 g_seq_hi[NT * DM], g_seq_lo[NT * DM];
__device__ bf16 g_ctx_hi[NT * DM], g_ctx_lo[NT * DM];
__device__ bf16 g_x_hi[NT * DM], g_x_lo[NT * DM];
__device__ bf16 g_h_hi[NT * 2 * DM], g_h_lo[NT * 2 * DM];
__device__ bf16 g_z_hi[(long)MAXB * DM], g_z_lo[(long)MAXB * DM];

// weight split scratch
constexpr int OW_P = 0, OW_T = 36864, OW_IN = 73728, OW_OUT = 184320;
constexpr int OW_F1 = 221184, OW_F2 = 294912, OW_CLS = 368640, OW_FP = 405504;
constexpr int OW_TOT = 430080;
__device__ bf16 g_whi[OW_TOT], g_wlo[OW_TOT];

// ---------------- helpers ----------------
__device__ __forceinline__ uint32_t smem_u32(const void* p) {
    uint32_t a;
    asm("{ .reg .u64 t; cvta.to.shared.u64 t, %1; cvt.u32.u64 %0, t; }" : "=r"(a) : "l"(p));
    return a;
}
__device__ __forceinline__ void cp16(uint32_t dst, const void* src) {
    asm volatile("cp.async.cg.shared.global [%0], [%1], 16;" :: "r"(dst), "l"(src));
}
__device__ __forceinline__ void cp_commit() { asm volatile("cp.async.commit_group;"); }
__device__ __forceinline__ void cp_wait1() { asm volatile("cp.async.wait_group 1;"); }
__device__ __forceinline__ void ldsm_x4(uint32_t* r, uint32_t addr) {
    asm volatile("ldmatrix.sync.aligned.m8n8.x4.shared.b16 {%0,%1,%2,%3}, [%4];"
        : "=r"(r[0]), "=r"(r[1]), "=r"(r[2]), "=r"(r[3]) : "r"(addr));
}
__device__ __forceinline__ void mma16816(float* c, const uint32_t* a, const uint32_t* b) {
    asm volatile(
        "mma.sync.aligned.m16n8k16.row.col.f32.bf16.bf16.f32 "
        "{%0,%1,%2,%3}, {%4,%5,%6,%7}, {%8,%9}, {%0,%1,%2,%3};"
        : "+f"(c[0]), "+f"(c[1]), "+f"(c[2]), "+f"(c[3])
        : "r"(a[0]), "r"(a[1]), "r"(a[2]), "r"(a[3]), "r"(b[0]), "r"(b[1]));
}
__device__ __forceinline__ void split2(float x, float y, uint32_t& h, uint32_t& l) {
    bf162 hb = __floats2bfloat162_rn(x, y);
    float2 hf = __bfloat1622float2(hb);
    bf162 lb = __floats2bfloat162_rn(x - hf.x, y - hf.y);
    memcpy(&h, &hb, 4); memcpy(&l, &lb, 4);
}

__global__ void split_k(const float* __restrict__ s, bf16* __restrict__ hi,
                        bf16* __restrict__ lo, long n)
{
    long i = 4L * (blockIdx.x * (long)blockDim.x + threadIdx.x);
    if (i >= n) return;
    float4 v = *(const float4*)(s + i);
    uint32_t h0, l0, h1, l1;
    split2(v.x, v.y, h0, l0);
    split2(v.z, v.w, h1, l1);
    *(uint32_t*)(hi + i) = h0; *(uint32_t*)(hi + i + 2) = h1;
    *(uint32_t*)(lo + i) = l0; *(uint32_t*)(lo + i + 2) = l1;
}

// ---------------------------------------------------------------------------
// Split bf16 HMMA GEMM, cp.async double-buffered, ldmatrix, templated BN.
// Tile 128 x BN x 32k; 8 warps 4(m) x 2(n); warp tile 32 x BN/2.
// Stage (u32): Ah[0,2560) Al[2560,5120) Bh[5120,5120+BN*20) Bl[+BN*20)
// ---------------------------------------------------------------------------
template<int BN> struct StgSz { static constexpr int v = 5120 + BN * 40; };
constexpr int GEMM_SMEM96 = 2 * StgSz<96>::v * 4;
constexpr int GEMM_SMEM64 = 2 * StgSz<64>::v * 4;

template<int BN, bool RELU, bool WF32, bool WSPLIT>
__global__ void __launch_bounds__(256)
tc_gemm(const bf16* __restrict__ Ahg, const bf16* __restrict__ Alg, int lda,
        const bf16* __restrict__ Whg, const bf16* __restrict__ Wlg,
        const float* __restrict__ bias,
        float* __restrict__ C, int ldc, int coff,
        bf16* __restrict__ Sh, bf16* __restrict__ Sl, int lds_, int scoff,
        int K)
{
    constexpr int NJ = BN / 16;     // n-fragments per warp
    constexpr int NJP = BN / 32;    // ldmatrix x4 groups for B
    constexpr int STG = StgSz<BN>::v;
    constexpr int BLOFF = 5120 + BN * 20;

    extern __shared__ __align__(16) uint32_t sm32[];
    const uint32_t sbase = smem_u32(sm32);

    const int tid = threadIdx.x;
    const int wid = tid >> 5, lane = tid & 31;
    const int wr = wid >> 1, wc = wid & 1;
    const int m0 = blockIdx.y * 128, n0 = blockIdx.x * BN;

    float acc[2][NJ][4];
#pragma unroll
    for (int i = 0; i < 2; i++)
#pragma unroll
        for (int j = 0; j < NJ; j++)
#pragma unroll
            for (int q = 0; q < 4; q++) acc[i][j][q] = 0.f;

    const int lr = tid >> 2, seg = tid & 3;

    const int t7 = lane & 7, mi = lane >> 3;
    const int aRow0 = wr * 32 + t7 + (mi & 1) * 8;
    const int aCol  = (mi >> 1) * 4;
    const int bRow0 = wc * (BN / 2) + t7 + (mi >> 1) * 8;
    const int bCol  = (mi & 1) * 4;

    const int nc = K >> 5;

    auto issue = [&](int c, int buf) {
        const int k0 = c << 5;
        const uint32_t sb = sbase + buf * (STG * 4);
#pragma unroll
        for (int it = 0; it < 2; it++) {
            const int r = lr + it * 64;
            const size_t go = (size_t)(m0 + r) * lda + k0 + seg * 8;
            cp16(sb + (r * 20 + seg * 4) * 4, Ahg + go);
            cp16(sb + (2560 + r * 20 + seg * 4) * 4, Alg + go);
        }
#pragma unroll
        for (int i = tid; i < BN * 4; i += 256) {
            const int r = i >> 2, sg = i & 3;
            const size_t gb = (size_t)(n0 + r) * K + k0 + sg * 8;
            cp16(sb + (5120 + r * 20 + sg * 4) * 4, Whg + gb);
            cp16(sb + (BLOFF + r * 20 + sg * 4) * 4, Wlg + gb);
        }
    };

    issue(0, 0);
    cp_commit();

    for (int c = 0; c < nc; c++) {
        if (c + 1 < nc) issue(c + 1, (c + 1) & 1);
        cp_commit();
        cp_wait1();
        __syncthreads();

        const uint32_t sb = sbase + (c & 1) * (STG * 4);
#pragma unroll
        for (int s = 0; s < 2; s++) {
            uint32_t ah[2][4], al[2][4], bh[NJ][2], bl[NJ][2];
#pragma unroll
            for (int i = 0; i < 2; i++) {
                const uint32_t ai = (uint32_t)((aRow0 + i * 16) * 20 + s * 8 + aCol) * 4;
                ldsm_x4(ah[i], sb + ai);
                ldsm_x4(al[i], sb + 2560 * 4 + ai);
            }
#pragma unroll
            for (int jp = 0; jp < NJP; jp++) {
                const uint32_t bi = (uint32_t)((bRow0 + jp * 16) * 20 + s * 8 + bCol) * 4;
                uint32_t tb[4];
                ldsm_x4(tb, sb + 5120 * 4 + bi);
                bh[2 * jp][0] = tb[0]; bh[2 * jp][1] = tb[1];
                bh[2 * jp + 1][0] = tb[2]; bh[2 * jp + 1][1] = tb[3];
                ldsm_x4(tb, sb + BLOFF * 4 + bi);
                bl[2 * jp][0] = tb[0]; bl[2 * jp][1] = tb[1];
                bl[2 * jp + 1][0] = tb[2]; bl[2 * jp + 1][1] = tb[3];
            }
#pragma unroll
            for (int i = 0; i < 2; i++)
#pragma unroll
                for (int j = 0; j < NJ; j++) {
                    mma16816(acc[i][j], ah[i], bh[j]);
                    mma16816(acc[i][j], ah[i], bl[j]);
                    mma16816(acc[i][j], al[i], bh[j]);
                }
        }
        __syncthreads();
    }

    const int lg = lane >> 2, lq = lane & 3;
#pragma unroll
    for (int i = 0; i < 2; i++) {
        const int row = m0 + wr * 32 + i * 16 + lg;
#pragma unroll
        for (int j = 0; j < NJ; j++) {
            const int col = n0 + wc * (BN / 2) + j * 8 + 2 * lq;
            const float bx = bias[col], by = bias[col + 1];
            float2 v0, v1;
            v0.x = acc[i][j][0] + bx; v0.y = acc[i][j][1] + by;
            v1.x = acc[i][j][2] + bx; v1.y = acc[i][j][3] + by;
            if (RELU) {
                v0.x = fmaxf(v0.x, 0.f); v0.y = fmaxf(v0.y, 0.f);
                v1.x = fmaxf(v1.x, 0.f); v1.y = fmaxf(v1.y, 0.f);
            }
            if (WF32) {
                *(float2*)(C + (size_t)row * ldc + coff + col) = v0;
                *(float2*)(C + (size_t)(row + 8) * ldc + coff + col) = v1;
            }
            if (WSPLIT) {
                uint32_t h0, l0, h1, l1;
                split2(v0.x, v0.y, h0, l0);
                split2(v1.x, v1.y, h1, l1);
                *(uint32_t*)(Sh + (size_t)row * lds_ + scoff + col) = h0;
                *(uint32_t*)(Sl + (size_t)row * lds_ + scoff + col) = l0;
                *(uint32_t*)(Sh + (size_t)(row + 8) * lds_ + scoff + col) = h1;
                *(uint32_t*)(Sl + (size_t)(row + 8) * lds_ + scoff + col) = l1;
            }
        }
    }
}

// ---------------- elementwise ----------------
__global__ void attn_kernel(const float* __restrict__ qkv, bf16* __restrict__ ch,
                            bf16* __restrict__ cl, int B)
{
    const int w = (blockIdx.x * blockDim.x + threadIdx.x) >> 5;
    const int lane = threadIdx.x & 31;
    if (w >= B) return;
    const float* r0 = qkv + (size_t)(2 * w) * 576;
    const float* r1 = r0 + 576;
    const size_t o0r = (size_t)(2 * w) * 192, o1r = o0r + 192;
#pragma unroll
    for (int h = 0; h < 3; h++) {
        const int o = h * 64 + 2 * lane;
        float2 q0 = *(const float2*)(r0 + o);
        float2 q1 = *(const float2*)(r1 + o);
        float2 k0 = *(const float2*)(r0 + 192 + o);
        float2 k1 = *(const float2*)(r1 + 192 + o);
        float2 v0 = *(const float2*)(r0 + 384 + o);
        float2 v1 = *(const float2*)(r1 + 384 + o);
        float s00 = q0.x * k0.x + q0.y * k0.y;
        float s01 = q0.x * k1.x + q0.y * k1.y;
        float s10 = q1.x * k0.x + q1.y * k0.y;
        float s11 = q1.x * k1.x + q1.y * k1.y;
#pragma unroll
        for (int d = 16; d; d >>= 1) {
            s00 += __shfl_xor_sync(0xffffffffu, s00, d);
            s01 += __shfl_xor_sync(0xffffffffu, s01, d);
            s10 += __shfl_xor_sync(0xffffffffu, s10, d);
            s11 += __shfl_xor_sync(0xffffffffu, s11, d);
        }
        s00 *= 0.125f; s01 *= 0.125f; s10 *= 0.125f; s11 *= 0.125f;
        float m0 = fmaxf(s00, s01);
        float e00 = expf(s00 - m0), e01 = expf(s01 - m0);
        float i0 = 1.f / (e00 + e01);
        float m1 = fmaxf(s10, s11);
        float e10 = expf(s10 - m1), e11 = expf(s11 - m1);
        float i1 = 1.f / (e10 + e11);
        float a00 = e00 * i0, a01 = e01 * i0, a10 = e10 * i1, a11 = e11 * i1;
        float ox0 = a00 * v0.x + a01 * v1.x, oy0 = a00 * v0.y + a01 * v1.y;
        float ox1 = a10 * v0.x + a11 * v1.x, oy1 = a10 * v0.y + a11 * v1.y;
        uint32_t h0, l0, h1, l1;
        split2(ox0, oy0, h0, l0);
        split2(ox1, oy1, h1, l1);
        *(uint32_t*)(ch + o0r + o) = h0; *(uint32_t*)(cl + o0r + o) = l0;
        *(uint32_t*)(ch + o1r + o) = h1; *(uint32_t*)(cl + o1r + o) = l1;
    }
}

__global__ void add_ln_kernel(const float* __restrict__ A, const float* __restrict__ Bq,
                              const float* __restrict__ g, const float* __restrict__ be,
                              float* __restrict__ O, bf16* __restrict__ Oh,
                              bf16* __restrict__ Ol, int nrows)
{
    const int w = (blockIdx.x * blockDim.x + threadIdx.x) >> 5;
    const int lane = threadIdx.x & 31;
    if (w >= nrows) return;
    const float* a = A + (size_t)w * 192;
    const float* b = Bq + (size_t)w * 192;
    float y[6], s = 0.f, ss = 0.f;
#pragma unroll
    for (int j = 0; j < 6; j++) {
        const int idx = lane + 32 * j;
        y[j] = a[idx] + b[idx];
        s += y[j]; ss += y[j] * y[j];
    }
#pragma unroll
    for (int d = 16; d; d >>= 1) {
        s += __shfl_xor_sync(0xffffffffu, s, d);
        ss += __shfl_xor_sync(0xffffffffu, ss, d);
    }
    const float mu = s * (1.f / 192.f);
    const float rs = rsqrtf(ss * (1.f / 192.f) - mu * mu + 1e-5f);
    float* o = O + (size_t)w * 192;
#pragma unroll
    for (int j = 0; j < 6; j++) {
        const int idx = lane + 32 * j;
        float v = (y[j] - mu) * rs * g[idx] + be[idx];
        o[idx] = v;
        bf16 h = __float2bfloat16_rn(v);
        Oh[(size_t)w * 192 + idx] = h;
        Ol[(size_t)w * 192 + idx] = __float2bfloat16_rn(v - __bfloat162float(h));
    }
}

__global__ void ln2_mean_kernel(const float* __restrict__ X, const float* __restrict__ F,
                                const float* __restrict__ g, const float* __restrict__ be,
                                bf16* __restrict__ Zh, bf16* __restrict__ Zl, int B)
{
    const int w = (blockIdx.x * blockDim.x + threadIdx.x) >> 5;
    const int lane = threadIdx.x & 31;
    if (w >= B) return;
    float zacc[6];
#pragma unroll
    for (int j = 0; j < 6; j++) zacc[j] = 0.f;
#pragma unroll
    for (int t = 0; t < 2; t++) {
        const size_t row = (size_t)(2 * w + t) * 192;
        float y[6], s = 0.f, ss = 0.f;
#pragma unroll
        for (int j = 0; j < 6; j++) {
            const int idx = lane + 32 * j;
            y[j] = X[row + idx] + F[row + idx];
            s += y[j]; ss += y[j] * y[j];
        }
#pragma unroll
        for (int d = 16; d; d >>= 1) {
            s += __shfl_xor_sync(0xffffffffu, s, d);
            ss += __shfl_xor_sync(0xffffffffu, ss, d);
        }
        const float mu = s * (1.f / 192.f);
        const float rs = rsqrtf(ss * (1.f / 192.f) - mu * mu + 1e-5f);
#pragma unroll
        for (int j = 0; j < 6; j++) {
            const int idx = lane + 32 * j;
            zacc[j] += 0.5f * ((y[j] - mu) * rs * g[idx] + be[idx]);
        }
    }
#pragma unroll
    for (int j = 0; j < 6; j++) {
        const int idx = lane + 32 * j;
        bf16 h = __float2bfloat16_rn(zacc[j]);
        Zh[(size_t)w * 192 + idx] = h;
        Zl[(size_t)w * 192 + idx] = __float2bfloat16_rn(zacc[j] - __bfloat162float(h));
    }
}

__global__ void head_kernel(const float* __restrict__ C, const float* __restrict__ FPr,
                            const float* __restrict__ w2, const float* __restrict__ b2,
                            float* __restrict__ out, int B)
{
    const int w = (blockIdx.x * blockDim.x + threadIdx.x) >> 5;
    const int lane = threadIdx.x & 31;
    if (w >= B) return;
    const float* c = C + (size_t)w * 192;
    float l0 = 0.f, l1 = 0.f, l2 = 0.f;
#pragma unroll
    for (int j = 0; j < 6; j++) {
        const int idx = lane + 32 * j;
        const float cv = c[idx];
        l0 += cv * w2[idx];
        l1 += cv * w2[192 + idx];
        l2 += cv * w2[384 + idx];
    }
#pragma unroll
    for (int d = 16; d; d >>= 1) {
        l0 += __shfl_xor_sync(0xffffffffu, l0, d);
        l1 += __shfl_xor_sync(0xffffffffu, l1, d);
        l2 += __shfl_xor_sync(0xffffffffu, l2, d);
    }
    if (lane == 0) {
        out[w]         = 1.f / (1.f + expf(-(l0 + b2[0])));
        out[B + w]     = 1.f / (1.f + expf(-(l1 + b2[1])));
        out[2 * B + w] = 1.f / (1.f + expf(-(l2 + b2[2])));
    }
    const float* f = FPr + (size_t)w * 128;
    float fv[4], ss = 0.f;
#pragma unroll
    for (int j = 0; j < 4; j++) {
        fv[j] = f[lane + 32 * j];
        ss += fv[j] * fv[j];
    }
#pragma unroll
    for (int d = 16; d; d >>= 1) ss += __shfl_xor_sync(0xffffffffu, ss, d);
    const float sc = 1.f / fmaxf(sqrtf(ss), 1e-12f);
    float* fo = out + 3L * B + (size_t)w * 128;
#pragma unroll
    for (int j = 0; j < 4; j++) fo[lane + 32 * j] = fv[j] * sc;
}

// ---------------- host ----------------
static inline void dsym(void** p, const void* sym) { cudaGetSymbolAddress(p, sym); }

extern "C" void kernel_launch(void* const* d_in, const int* in_sizes, int n_in,
                              void* d_out, int out_size)
{
    const float* perc   = (const float*)d_in[0];
    const float* tech   = (const float*)d_in[1];
    const float* Wp     = (const float*)d_in[2];
    const float* bp     = (const float*)d_in[3];
    const float* Wt     = (const float*)d_in[4];
    const float* bt     = (const float*)d_in[5];
    const float* in_w   = (const float*)d_in[6];
    const float* in_b   = (const float*)d_in[7];
    const float* out_w  = (const float*)d_in[8];
    const float* out_b  = (const float*)d_in[9];
    const float* ffn_w1 = (const float*)d_in[10];
    const float* ffn_b1 = (const float*)d_in[11];
    const float* ffn_w2 = (const float*)d_in[12];
    const float* ffn_b2 = (const float*)d_in[13];
    const float* ln1_g  = (const float*)d_in[14];
    const float* ln1_b  = (const float*)d_in[15];
    const float* ln2_g  = (const float*)d_in[16];
    const float* ln2_b  = (const float*)d_in[17];
    const float* cls_w1 = (const float*)d_in[18];
    const float* cls_b1 = (const float*)d_in[19];
    const float* cls_w2 = (const float*)d_in[20];
    const float* cls_b2 = (const float*)d_in[21];
    const float* fp_w   = (const float*)d_in[22];
    const float* fp_b   = (const float*)d_in[23];

    int B = in_sizes[0] / DM;
    if (B > MAXB) B = MAXB;
    const int T = 2 * B;

    float *seq, *qkv, *attnf, *x, *ffn, *c, *fp;
    dsym((void**)&seq, g_seq); dsym((void**)&qkv, g_qkv); dsym((void**)&attnf, g_attn);
    dsym((void**)&x, g_x); dsym((void**)&ffn, g_ffn); dsym((void**)&c, g_c);
    dsym((void**)&fp, g_fp);

    bf16 *pah, *pal, *tah, *tal, *seqh, *seql, *ctxh, *ctxl, *xh, *xl, *hh, *hl, *zh, *zl, *whi, *wlo;
    dsym((void**)&pah, g_pa_hi); dsym((void**)&pal, g_pa_lo);
    dsym((void**)&tah, g_ta_hi); dsym((void**)&tal, g_ta_lo);
    dsym((void**)&seqh, g_seq_hi); dsym((void**)&seql, g_seq_lo);
    dsym((void**)&ctxh, g_ctx_hi); dsym((void**)&ctxl, g_ctx_lo);
    dsym((void**)&xh, g_x_hi); dsym((void**)&xl, g_x_lo);
    dsym((void**)&hh, g_h_hi); dsym((void**)&hl, g_h_lo);
    dsym((void**)&zh, g_z_hi); dsym((void**)&zl, g_z_lo);
    dsym((void**)&whi, g_whi); dsym((void**)&wlo, g_wlo);

    cudaFuncSetAttribute(tc_gemm<96, false, true,  true >, cudaFuncAttributeMaxDynamicSharedMemorySize, GEMM_SMEM96);
    cudaFuncSetAttribute(tc_gemm<96, false, true,  false>, cudaFuncAttributeMaxDynamicSharedMemorySize, GEMM_SMEM96);
    cudaFuncSetAttribute(tc_gemm<96, true,  false, true >, cudaFuncAttributeMaxDynamicSharedMemorySize, GEMM_SMEM96);
    cudaFuncSetAttribute(tc_gemm<96, true,  true,  false>, cudaFuncAttributeMaxDynamicSharedMemorySize, GEMM_SMEM96);
    cudaFuncSetAttribute(tc_gemm<64, false, true,  false>, cudaFuncAttributeMaxDynamicSharedMemorySize, GEMM_SMEM64);

    float* out = (float*)d_out;

    auto spl = [&](const float* s, bf16* h, bf16* l, long n) {
        split_k<<<(int)((n / 4 + 255) / 256), 256>>>(s, h, l, n);
    };
    spl(Wp, whi + OW_P, wlo + OW_P, 36864);
    spl(Wt, whi + OW_T, wlo + OW_T, 36864);
    spl(in_w, whi + OW_IN, wlo + OW_IN, 110592);
    spl(out_w, whi + OW_OUT, wlo + OW_OUT, 36864);
    spl(ffn_w1, whi + OW_F1, wlo + OW_F1, 73728);
    spl(ffn_w2, whi + OW_F2, wlo + OW_F2, 73728);
    spl(cls_w1, whi + OW_CLS, wlo + OW_CLS, 36864);
    spl(fp_w, whi + OW_FP, wlo + OW_FP, 24576);
    spl(perc, pah, pal, (long)B * 192);
    spl(tech, tah, tal, (long)B * 192);

    // projections -> seq fp32 + split (seq stored [B,384]; token view [2B,192])
    tc_gemm<96, false, true, true><<<dim3(2, B / 128), 256, GEMM_SMEM96>>>(
        pah, pal, 192, whi + OW_P, wlo + OW_P, bp, seq, 384, 0, seqh, seql, 384, 0, 192);
    tc_gemm<96, false, true, true><<<dim3(2, B / 128), 256, GEMM_SMEM96>>>(
        tah, tal, 192, whi + OW_T, wlo + OW_T, bt, seq, 384, 192, seqh, seql, 384, 192, 192);
    // qkv: token view lda 192
    tc_gemm<96, false, true, false><<<dim3(6, T / 128), 256, GEMM_SMEM96>>>(
        seqh, seql, 192, whi + OW_IN, wlo + OW_IN, in_b, qkv, 576, 0, nullptr, nullptr, 0, 0, 192);
    attn_kernel<<<(B + 7) / 8, 256>>>(qkv, ctxh, ctxl, B);
    tc_gemm<96, false, true, false><<<dim3(2, T / 128), 256, GEMM_SMEM96>>>(
        ctxh, ctxl, 192, whi + OW_OUT, wlo + OW_OUT, out_b, attnf, 192, 0, nullptr, nullptr, 0, 0, 192);
    add_ln_kernel<<<(T + 7) / 8, 256>>>(seq, attnf, ln1_g, ln1_b, x, xh, xl, T);
    tc_gemm<96, true, false, true><<<dim3(4, T / 128), 256, GEMM_SMEM96>>>(
        xh, xl, 192, whi + OW_F1, wlo + OW_F1, ffn_b1, nullptr, 0, 0, hh, hl, 384, 0, 192);
    tc_gemm<96, false, true, false><<<dim3(2, T / 128), 256, GEMM_SMEM96>>>(
        hh, hl, 384, whi + OW_F2, wlo + OW_F2, ffn_b2, ffn, 192, 0, nullptr, nullptr, 0, 0, 384);
    ln2_mean_kernel<<<(B + 7) / 8, 256>>>(x, ffn, ln2_g, ln2_b, zh, zl, B);
    tc_gemm<96, true, true, false><<<dim3(2, B / 128), 256, GEMM_SMEM96>>>(
        zh, zl, 192, whi + OW_CLS, wlo + OW_CLS, cls_b1, c, 192, 0, nullptr, nullptr, 0, 0, 192);
    tc_gemm<64, false, true, false><<<dim3(2, B / 128), 256, GEMM_SMEM64>>>(
        zh, zl, 192, whi + OW_FP, wlo + OW_FP, fp_b, fp, 128, 0, nullptr, nullptr, 0, 0, 192);
    head_kernel<<<(B + 7) / 8, 256>>>(c, fp, cls_w2, cls_b2, out, B);
}

// round 10
// speedup vs baseline: 3.1541x; 1.3831x over previous
#include <cuda_runtime.h>
#include <cuda_fp16.h>
#include <stdint.h>
#include <string.h>
#include <math.h>

typedef __half fp16;

constexpr int DM = 192;
constexpr int MAXB = 65536;
constexpr long NT = 2L * MAXB;

// fp32 scratch
__device__ float g_seq[NT * DM];
__device__ float g_qkv[NT * 3 * DM];
__device__ float g_attn[NT * DM];
__device__ float g_x[NT * DM];
__device__ float g_ffn[NT * DM];
__device__ float g_c[(long)MAXB * DM];
__device__ float g_fp[(long)MAXB * 128];

// fp16 activation scratch (single precision-rounded copies)
__device__ fp16 g_pa[(long)MAXB * DM], g_ta[(long)MAXB * DM];
__device__ fp16 g_seqh[NT * DM];
__device__ fp16 g_ctxh[NT * DM];
__device__ fp16 g_xh[NT * DM];
__device__ fp16 g_hh[NT * 2 * DM];
__device__ fp16 g_zh[(long)MAXB * DM];

// weight split scratch (fp16 hi + lo)
constexpr int OW_P = 0, OW_T = 36864, OW_IN = 73728, OW_OUT = 184320;
constexpr int OW_F1 = 221184, OW_F2 = 294912, OW_CLS = 368640, OW_FP = 405504;
constexpr int OW_TOT = 430080;
__device__ fp16 g_whi[OW_TOT], g_wlo[OW_TOT];

// ---------------- helpers ----------------
__device__ __forceinline__ uint32_t smem_u32(const void* p) {
    uint32_t a;
    asm("{ .reg .u64 t; cvta.to.shared.u64 t, %1; cvt.u32.u64 %0, t; }" : "=r"(a) : "l"(p));
    return a;
}
__device__ __forceinline__ void cp16(uint32_t dst, const void* src) {
    asm volatile("cp.async.cg.shared.global [%0], [%1], 16;" :: "r"(dst), "l"(src));
}
__device__ __forceinline__ void cp_commit() { asm volatile("cp.async.commit_group;"); }
__device__ __forceinline__ void cp_wait1() { asm volatile("cp.async.wait_group 1;"); }
__device__ __forceinline__ void ldsm_x4(uint32_t* r, uint32_t addr) {
    asm volatile("ldmatrix.sync.aligned.m8n8.x4.shared.b16 {%0,%1,%2,%3}, [%4];"
        : "=r"(r[0]), "=r"(r[1]), "=r"(r[2]), "=r"(r[3]) : "r"(addr));
}
__device__ __forceinline__ void mma16816(float* c, const uint32_t* a, const uint32_t* b) {
    asm volatile(
        "mma.sync.aligned.m16n8k16.row.col.f32.f16.f16.f32 "
        "{%0,%1,%2,%3}, {%4,%5,%6,%7}, {%8,%9}, {%0,%1,%2,%3};"
        : "+f"(c[0]), "+f"(c[1]), "+f"(c[2]), "+f"(c[3])
        : "r"(a[0]), "r"(a[1]), "r"(a[2]), "r"(a[3]), "r"(b[0]), "r"(b[1]));
}
__device__ __forceinline__ uint32_t pack_h2(float x, float y) {
    __half2 h = __floats2half2_rn(x, y);
    uint32_t u; memcpy(&u, &h, 4); return u;
}
__device__ __forceinline__ void splitw2(float x, float y, uint32_t& h, uint32_t& l) {
    __half2 hb = __floats2half2_rn(x, y);
    float2 hf = __half22float2(hb);
    __half2 lb = __floats2half2_rn(x - hf.x, y - hf.y);
    memcpy(&h, &hb, 4); memcpy(&l, &lb, 4);
}

// weights: fp32 -> fp16 hi + lo
__global__ void splitw_k(const float* __restrict__ s, fp16* __restrict__ hi,
                         fp16* __restrict__ lo, long n)
{
    long i = 4L * (blockIdx.x * (long)blockDim.x + threadIdx.x);
    if (i >= n) return;
    float4 v = *(const float4*)(s + i);
    uint32_t h0, l0, h1, l1;
    splitw2(v.x, v.y, h0, l0);
    splitw2(v.z, v.w, h1, l1);
    *(uint32_t*)(hi + i) = h0; *(uint32_t*)(hi + i + 2) = h1;
    *(uint32_t*)(lo + i) = l0; *(uint32_t*)(lo + i + 2) = l1;
}
// activations: fp32 -> fp16
__global__ void cvt_k(const float* __restrict__ s, fp16* __restrict__ o, long n)
{
    long i = 4L * (blockIdx.x * (long)blockDim.x + threadIdx.x);
    if (i >= n) return;
    float4 v = *(const float4*)(s + i);
    *(uint32_t*)(o + i) = pack_h2(v.x, v.y);
    *(uint32_t*)(o + i + 2) = pack_h2(v.z, v.w);
}

// ---------------------------------------------------------------------------
// fp16 HMMA GEMM: C = act(A . (Wh+Wl)^T + bias), A fp16 [M,K], W split hi/lo.
// Tile 128 x BN x 32k; 8 warps 4(m) x 2(n); warp tile 32 x BN/2.
// Stage (u32): A[0,2560) Bh[2560,2560+BN*20) Bl[+BN*20). rows padded 20 u32.
// ---------------------------------------------------------------------------
template<int BN> struct StgSz { static constexpr int v = 2560 + BN * 40; };
constexpr int GEMM_SMEM96 = 2 * StgSz<96>::v * 4;   // 51200
constexpr int GEMM_SMEM64 = 2 * StgSz<64>::v * 4;   // 40960

template<int BN, bool RELU, bool WF32, bool WH16>
__global__ void __launch_bounds__(256)
tc_gemm(const fp16* __restrict__ Ag, int lda,
        const fp16* __restrict__ Whg, const fp16* __restrict__ Wlg,
        const float* __restrict__ bias,
        float* __restrict__ C, int ldc, int coff,
        fp16* __restrict__ S, int lds_, int scoff,
        int K)
{
    constexpr int NJ = BN / 16;
    constexpr int NJP = BN / 32;
    constexpr int STG = StgSz<BN>::v;
    constexpr int BLOFF = 2560 + BN * 20;

    extern __shared__ __align__(16) uint32_t sm32[];
    const uint32_t sbase = smem_u32(sm32);

    const int tid = threadIdx.x;
    const int wid = tid >> 5, lane = tid & 31;
    const int wr = wid >> 1, wc = wid & 1;
    const int m0 = blockIdx.y * 128, n0 = blockIdx.x * BN;

    float acc[2][NJ][4];
#pragma unroll
    for (int i = 0; i < 2; i++)
#pragma unroll
        for (int j = 0; j < NJ; j++)
#pragma unroll
            for (int q = 0; q < 4; q++) acc[i][j][q] = 0.f;

    const int lr = tid >> 2, seg = tid & 3;
    const int t7 = lane & 7, mi = lane >> 3;
    const int aRow0 = wr * 32 + t7 + (mi & 1) * 8;
    const int aCol  = (mi >> 1) * 4;
    const int bRow0 = wc * (BN / 2) + t7 + (mi >> 1) * 8;
    const int bCol  = (mi & 1) * 4;

    const int nc = K >> 5;

    auto issue = [&](int c, int buf) {
        const int k0 = c << 5;
        const uint32_t sb = sbase + buf * (STG * 4);
#pragma unroll
        for (int it = 0; it < 2; it++) {
            const int r = lr + it * 64;
            const size_t go = (size_t)(m0 + r) * lda + k0 + seg * 8;
            cp16(sb + (r * 20 + seg * 4) * 4, Ag + go);
        }
#pragma unroll
        for (int i = tid; i < BN * 4; i += 256) {
            const int r = i >> 2, sg = i & 3;
            const size_t gb = (size_t)(n0 + r) * K + k0 + sg * 8;
            cp16(sb + (2560 + r * 20 + sg * 4) * 4, Whg + gb);
            cp16(sb + (BLOFF + r * 20 + sg * 4) * 4, Wlg + gb);
        }
    };

    issue(0, 0);
    cp_commit();

    for (int c = 0; c < nc; c++) {
        if (c + 1 < nc) issue(c + 1, (c + 1) & 1);
        cp_commit();
        cp_wait1();
        __syncthreads();

        const uint32_t sb = sbase + (c & 1) * (STG * 4);
#pragma unroll
        for (int s = 0; s < 2; s++) {
            uint32_t ah[2][4], bh[NJ][2], bl[NJ][2];
#pragma unroll
            for (int i = 0; i < 2; i++) {
                const uint32_t ai = (uint32_t)((aRow0 + i * 16) * 20 + s * 8 + aCol) * 4;
                ldsm_x4(ah[i], sb + ai);
            }
#pragma unroll
            for (int jp = 0; jp < NJP; jp++) {
                const uint32_t bi = (uint32_t)((bRow0 + jp * 16) * 20 + s * 8 + bCol) * 4;
                uint32_t tb[4];
                ldsm_x4(tb, sb + 2560 * 4 + bi);
                bh[2 * jp][0] = tb[0]; bh[2 * jp][1] = tb[1];
                bh[2 * jp + 1][0] = tb[2]; bh[2 * jp + 1][1] = tb[3];
                ldsm_x4(tb, sb + BLOFF * 4 + bi);
                bl[2 * jp][0] = tb[0]; bl[2 * jp][1] = tb[1];
                bl[2 * jp + 1][0] = tb[2]; bl[2 * jp + 1][1] = tb[3];
            }
#pragma unroll
            for (int i = 0; i < 2; i++)
#pragma unroll
                for (int j = 0; j < NJ; j++) {
                    mma16816(acc[i][j], ah[i], bh[j]);
                    mma16816(acc[i][j], ah[i], bl[j]);
                }
        }
        __syncthreads();
    }

    const int lg = lane >> 2, lq = lane & 3;
#pragma unroll
    for (int i = 0; i < 2; i++) {
        const int row = m0 + wr * 32 + i * 16 + lg;
#pragma unroll
        for (int j = 0; j < NJ; j++) {
            const int col = n0 + wc * (BN / 2) + j * 8 + 2 * lq;
            const float bx = bias[col], by = bias[col + 1];
            float2 v0, v1;
            v0.x = acc[i][j][0] + bx; v0.y = acc[i][j][1] + by;
            v1.x = acc[i][j][2] + bx; v1.y = acc[i][j][3] + by;
            if (RELU) {
                v0.x = fmaxf(v0.x, 0.f); v0.y = fmaxf(v0.y, 0.f);
                v1.x = fmaxf(v1.x, 0.f); v1.y = fmaxf(v1.y, 0.f);
            }
            if (WF32) {
                *(float2*)(C + (size_t)row * ldc + coff + col) = v0;
                *(float2*)(C + (size_t)(row + 8) * ldc + coff + col) = v1;
            }
            if (WH16) {
                *(uint32_t*)(S + (size_t)row * lds_ + scoff + col) = pack_h2(v0.x, v0.y);
                *(uint32_t*)(S + (size_t)(row + 8) * lds_ + scoff + col) = pack_h2(v1.x, v1.y);
            }
        }
    }
}

// ---------------- elementwise ----------------
__global__ void attn_kernel(const float* __restrict__ qkv, fp16* __restrict__ ch, int B)
{
    const int w = (blockIdx.x * blockDim.x + threadIdx.x) >> 5;
    const int lane = threadIdx.x & 31;
    if (w >= B) return;
    const float* r0 = qkv + (size_t)(2 * w) * 576;
    const float* r1 = r0 + 576;
    const size_t o0r = (size_t)(2 * w) * 192, o1r = o0r + 192;
#pragma unroll
    for (int h = 0; h < 3; h++) {
        const int o = h * 64 + 2 * lane;
        float2 q0 = *(const float2*)(r0 + o);
        float2 q1 = *(const float2*)(r1 + o);
        float2 k0 = *(const float2*)(r0 + 192 + o);
        float2 k1 = *(const float2*)(r1 + 192 + o);
        float2 v0 = *(const float2*)(r0 + 384 + o);
        float2 v1 = *(const float2*)(r1 + 384 + o);
        float s00 = q0.x * k0.x + q0.y * k0.y;
        float s01 = q0.x * k1.x + q0.y * k1.y;
        float s10 = q1.x * k0.x + q1.y * k0.y;
        float s11 = q1.x * k1.x + q1.y * k1.y;
#pragma unroll
        for (int d = 16; d; d >>= 1) {
            s00 += __shfl_xor_sync(0xffffffffu, s00, d);
            s01 += __shfl_xor_sync(0xffffffffu, s01, d);
            s10 += __shfl_xor_sync(0xffffffffu, s10, d);
            s11 += __shfl_xor_sync(0xffffffffu, s11, d);
        }
        s00 *= 0.125f; s01 *= 0.125f; s10 *= 0.125f; s11 *= 0.125f;
        float m0 = fmaxf(s00, s01);
        float e00 = expf(s00 - m0), e01 = expf(s01 - m0);
        float i0 = 1.f / (e00 + e01);
        float m1 = fmaxf(s10, s11);
        float e10 = expf(s10 - m1), e11 = expf(s11 - m1);
        float i1 = 1.f / (e10 + e11);
        float a00 = e00 * i0, a01 = e01 * i0, a10 = e10 * i1, a11 = e11 * i1;
        *(uint32_t*)(ch + o0r + o) = pack_h2(a00 * v0.x + a01 * v1.x, a00 * v0.y + a01 * v1.y);
        *(uint32_t*)(ch + o1r + o) = pack_h2(a10 * v0.x + a11 * v1.x, a10 * v0.y + a11 * v1.y);
    }
}

__global__ void add_ln_kernel(const float* __restrict__ A, const float* __restrict__ Bq,
                              const float* __restrict__ g, const float* __restrict__ be,
                              float* __restrict__ O, fp16* __restrict__ Oh, int nrows)
{
    const int w = (blockIdx.x * blockDim.x + threadIdx.x) >> 5;
    const int lane = threadIdx.x & 31;
    if (w >= nrows) return;
    const float* a = A + (size_t)w * 192;
    const float* b = Bq + (size_t)w * 192;
    float y[6], s = 0.f, ss = 0.f;
#pragma unroll
    for (int j = 0; j < 6; j++) {
        const int idx = lane + 32 * j;
        y[j] = a[idx] + b[idx];
        s += y[j]; ss += y[j] * y[j];
    }
#pragma unroll
    for (int d = 16; d; d >>= 1) {
        s += __shfl_xor_sync(0xffffffffu, s, d);
        ss += __shfl_xor_sync(0xffffffffu, ss, d);
    }
    const float mu = s * (1.f / 192.f);
    const float rs = rsqrtf(ss * (1.f / 192.f) - mu * mu + 1e-5f);
    float* o = O + (size_t)w * 192;
#pragma unroll
    for (int j = 0; j < 6; j++) {
        const int idx = lane + 32 * j;
        float v = (y[j] - mu) * rs * g[idx] + be[idx];
        o[idx] = v;
        Oh[(size_t)w * 192 + idx] = __float2half_rn(v);
    }
}

__global__ void ln2_mean_kernel(const float* __restrict__ X, const float* __restrict__ F,
                                const float* __restrict__ g, const float* __restrict__ be,
                                fp16* __restrict__ Zh, int B)
{
    const int w = (blockIdx.x * blockDim.x + threadIdx.x) >> 5;
    const int lane = threadIdx.x & 31;
    if (w >= B) return;
    float zacc[6];
#pragma unroll
    for (int j = 0; j < 6; j++) zacc[j] = 0.f;
#pragma unroll
    for (int t = 0; t < 2; t++) {
        const size_t row = (size_t)(2 * w + t) * 192;
        float y[6], s = 0.f, ss = 0.f;
#pragma unroll
        for (int j = 0; j < 6; j++) {
            const int idx = lane + 32 * j;
            y[j] = X[row + idx] + F[row + idx];
            s += y[j]; ss += y[j] * y[j];
        }
#pragma unroll
        for (int d = 16; d; d >>= 1) {
            s += __shfl_xor_sync(0xffffffffu, s, d);
            ss += __shfl_xor_sync(0xffffffffu, ss, d);
        }
        const float mu = s * (1.f / 192.f);
        const float rs = rsqrtf(ss * (1.f / 192.f) - mu * mu + 1e-5f);
#pragma unroll
        for (int j = 0; j < 6; j++) {
            const int idx = lane + 32 * j;
            zacc[j] += 0.5f * ((y[j] - mu) * rs * g[idx] + be[idx]);
        }
    }
#pragma unroll
    for (int j = 0; j < 6; j++)
        Zh[(size_t)w * 192 + lane + 32 * j] = __float2half_rn(zacc[j]);
}

__global__ void head_kernel(const float* __restrict__ C, const float* __restrict__ FPr,
                            const float* __restrict__ w2, const float* __restrict__ b2,
                            float* __restrict__ out, int B)
{
    const int w = (blockIdx.x * blockDim.x + threadIdx.x) >> 5;
    const int lane = threadIdx.x & 31;
    if (w >= B) return;
    const float* c = C + (size_t)w * 192;
    float l0 = 0.f, l1 = 0.f, l2 = 0.f;
#pragma unroll
    for (int j = 0; j < 6; j++) {
        const int idx = lane + 32 * j;
        const float cv = c[idx];
        l0 += cv * w2[idx];
        l1 += cv * w2[192 + idx];
        l2 += cv * w2[384 + idx];
    }
#pragma unroll
    for (int d = 16; d; d >>= 1) {
        l0 += __shfl_xor_sync(0xffffffffu, l0, d);
        l1 += __shfl_xor_sync(0xffffffffu, l1, d);
        l2 += __shfl_xor_sync(0xffffffffu, l2, d);
    }
    if (lane == 0) {
        out[w]         = 1.f / (1.f + expf(-(l0 + b2[0])));
        out[B + w]     = 1.f / (1.f + expf(-(l1 + b2[1])));
        out[2 * B + w] = 1.f / (1.f + expf(-(l2 + b2[2])));
    }
    const float* f = FPr + (size_t)w * 128;
    float fv[4], ss = 0.f;
#pragma unroll
    for (int j = 0; j < 4; j++) {
        fv[j] = f[lane + 32 * j];
        ss += fv[j] * fv[j];
    }
#pragma unroll
    for (int d = 16; d; d >>= 1) ss += __shfl_xor_sync(0xffffffffu, ss, d);
    const float sc = 1.f / fmaxf(sqrtf(ss), 1e-12f);
    float* fo = out + 3L * B + (size_t)w * 128;
#pragma unroll
    for (int j = 0; j < 4; j++) fo[lane + 32 * j] = fv[j] * sc;
}

// ---------------- host ----------------
static inline void dsym(void** p, const void* sym) { cudaGetSymbolAddress(p, sym); }

extern "C" void kernel_launch(void* const* d_in, const int* in_sizes, int n_in,
                              void* d_out, int out_size)
{
    const float* perc   = (const float*)d_in[0];
    const float* tech   = (const float*)d_in[1];
    const float* Wp     = (const float*)d_in[2];
    const float* bp     = (const float*)d_in[3];
    const float* Wt     = (const float*)d_in[4];
    const float* bt     = (const float*)d_in[5];
    const float* in_w   = (const float*)d_in[6];
    const float* in_b   = (const float*)d_in[7];
    const float* out_w  = (const float*)d_in[8];
    const float* out_b  = (const float*)d_in[9];
    const float* ffn_w1 = (const float*)d_in[10];
    const float* ffn_b1 = (const float*)d_in[11];
    const float* ffn_w2 = (const float*)d_in[12];
    const float* ffn_b2 = (const float*)d_in[13];
    const float* ln1_g  = (const float*)d_in[14];
    const float* ln1_b  = (const float*)d_in[15];
    const float* ln2_g  = (const float*)d_in[16];
    const float* ln2_b  = (const float*)d_in[17];
    const float* cls_w1 = (const float*)d_in[18];
    const float* cls_b1 = (const float*)d_in[19];
    const float* cls_w2 = (const float*)d_in[20];
    const float* cls_b2 = (const float*)d_in[21];
    const float* fp_w   = (const float*)d_in[22];
    const float* fp_b   = (const float*)d_in[23];

    int B = in_sizes[0] / DM;
    if (B > MAXB) B = MAXB;
    const int T = 2 * B;

    float *seq, *qkv, *attnf, *x, *ffn, *c, *fp;
    dsym((void**)&seq, g_seq); dsym((void**)&qkv, g_qkv); dsym((void**)&attnf, g_attn);
    dsym((void**)&x, g_x); dsym((void**)&ffn, g_ffn); dsym((void**)&c, g_c);
    dsym((void**)&fp, g_fp);

    fp16 *pa, *ta, *seqh, *ctxh, *xh, *hh, *zh, *whi, *wlo;
    dsym((void**)&pa, g_pa); dsym((void**)&ta, g_ta);
    dsym((void**)&seqh, g_seqh); dsym((void**)&ctxh, g_ctxh);
    dsym((void**)&xh, g_xh); dsym((void**)&hh, g_hh); dsym((void**)&zh, g_zh);
    dsym((void**)&whi, g_whi); dsym((void**)&wlo, g_wlo);

    cudaFuncSetAttribute(tc_gemm<96, false, true,  true >, cudaFuncAttributeMaxDynamicSharedMemorySize, GEMM_SMEM96);
    cudaFuncSetAttribute(tc_gemm<96, false, true,  false>, cudaFuncAttributeMaxDynamicSharedMemorySize, GEMM_SMEM96);
    cudaFuncSetAttribute(tc_gemm<96, true,  false, true >, cudaFuncAttributeMaxDynamicSharedMemorySize, GEMM_SMEM96);
    cudaFuncSetAttribute(tc_gemm<96, true,  true,  false>, cudaFuncAttributeMaxDynamicSharedMemorySize, GEMM_SMEM96);
    cudaFuncSetAttribute(tc_gemm<64, false, true,  false>, cudaFuncAttributeMaxDynamicSharedMemorySize, GEMM_SMEM64);

    float* out = (float*)d_out;

    auto spw = [&](const float* s, fp16* h, fp16* l, long n) {
        splitw_k<<<(int)((n / 4 + 255) / 256), 256>>>(s, h, l, n);
    };
    spw(Wp, whi + OW_P, wlo + OW_P, 36864);
    spw(Wt, whi + OW_T, wlo + OW_T, 36864);
    spw(in_w, whi + OW_IN, wlo + OW_IN, 110592);
    spw(out_w, whi + OW_OUT, wlo + OW_OUT, 36864);
    spw(ffn_w1, whi + OW_F1, wlo + OW_F1, 73728);
    spw(ffn_w2, whi + OW_F2, wlo + OW_F2, 73728);
    spw(cls_w1, whi + OW_CLS, wlo + OW_CLS, 36864);
    spw(fp_w, whi + OW_FP, wlo + OW_FP, 24576);
    cvt_k<<<(int)(((long)B * 192 / 4 + 255) / 256), 256>>>(perc, pa, (long)B * 192);
    cvt_k<<<(int)(((long)B * 192 / 4 + 255) / 256), 256>>>(tech, ta, (long)B * 192);

    // projections -> seq fp32 + fp16 (seq stored [B,384]; token view [2B,192])
    tc_gemm<96, false, true, true><<<dim3(2, B / 128), 256, GEMM_SMEM96>>>(
        pa, 192, whi + OW_P, wlo + OW_P, bp, seq, 384, 0, seqh, 384, 0, 192);
    tc_gemm<96, false, true, true><<<dim3(2, B / 128), 256, GEMM_SMEM96>>>(
        ta, 192, whi + OW_T, wlo + OW_T, bt, seq, 384, 192, seqh, 384, 192, 192);
    // qkv: token view lda 192
    tc_gemm<96, false, true, false><<<dim3(6, T / 128), 256, GEMM_SMEM96>>>(
        seqh, 192, whi + OW_IN, wlo + OW_IN, in_b, qkv, 576, 0, nullptr, 0, 0, 192);
    attn_kernel<<<(B + 7) / 8, 256>>>(qkv, ctxh, B);
    tc_gemm<96, false, true, false><<<dim3(2, T / 128), 256, GEMM_SMEM96>>>(
        ctxh, 192, whi + OW_OUT, wlo + OW_OUT, out_b, attnf, 192, 0, nullptr, 0, 0, 192);
    add_ln_kernel<<<(T + 7) / 8, 256>>>(seq, attnf, ln1_g, ln1_b, x, xh, T);
    tc_gemm<96, true, false, true><<<dim3(4, T / 128), 256, GEMM_SMEM96>>>(
        xh, 192, whi + OW_F1, wlo + OW_F1, ffn_b1, nullptr, 0, 0, hh, 384, 0, 192);
    tc_gemm<96, false, true, false><<<dim3(2, T / 128), 256, GEMM_SMEM96>>>(
        hh, 384, whi + OW_F2, wlo + OW_F2, ffn_b2, ffn, 192, 0, nullptr, 0, 0, 384);
    ln2_mean_kernel<<<(B + 7) / 8, 256>>>(x, ffn, ln2_g, ln2_b, zh, B);
    tc_gemm<96, true, true, false><<<dim3(2, B / 128), 256, GEMM_SMEM96>>>(
        zh, 192, whi + OW_CLS, wlo + OW_CLS, cls_b1, c, 192, 0, nullptr, 0, 0, 192);
    tc_gemm<64, false, true, false><<<dim3(2, B / 128), 256, GEMM_SMEM64>>>(
        zh, 192, whi + OW_FP, wlo + OW_FP, fp_b, fp, 128, 0, nullptr, 0, 0, 192);
    head_kernel<<<(B + 7) / 8, 256>>>(c, fp, cls_w2, cls_b2, out, B);
}

// round 11
// speedup vs baseline: 3.2499x; 1.0304x over previous
#include <cuda_runtime.h>
#include <cuda_fp16.h>
#include <stdint.h>
#include <string.h>
#include <math.h>

typedef __half fp16;

constexpr int DM = 192;
constexpr int MAXB = 65536;
constexpr long NT = 2L * MAXB;

// fp32 scratch
__device__ float g_seq[NT * DM];
__device__ float g_attn[NT * DM];
__device__ float g_x[NT * DM];
__device__ float g_ffn[NT * DM];
__device__ float g_c[(long)MAXB * DM];
__device__ float g_fp[(long)MAXB * 128];

// fp16 activation scratch
__device__ fp16 g_pa[(long)MAXB * DM], g_ta[(long)MAXB * DM];
__device__ fp16 g_seqh[NT * DM];
__device__ fp16 g_qkvh[NT * 3 * DM];
__device__ fp16 g_ctxh[NT * DM];
__device__ fp16 g_xh[NT * DM];
__device__ fp16 g_hh[NT * 2 * DM];
__device__ fp16 g_zh[(long)MAXB * DM];

// weight split scratch (fp16 hi + lo)
constexpr int OW_P = 0, OW_T = 36864, OW_IN = 73728, OW_OUT = 184320;
constexpr int OW_F1 = 221184, OW_F2 = 294912, OW_CLS = 368640, OW_FP = 405504;
constexpr int OW_TOT = 430080;
__device__ fp16 g_whi[OW_TOT], g_wlo[OW_TOT];

// ---------------- helpers ----------------
__device__ __forceinline__ uint32_t smem_u32(const void* p) {
    uint32_t a;
    asm("{ .reg .u64 t; cvta.to.shared.u64 t, %1; cvt.u32.u64 %0, t; }" : "=r"(a) : "l"(p));
    return a;
}
__device__ __forceinline__ void cp16(uint32_t dst, const void* src) {
    asm volatile("cp.async.cg.shared.global [%0], [%1], 16;" :: "r"(dst), "l"(src));
}
__device__ __forceinline__ void cp_commit() { asm volatile("cp.async.commit_group;"); }
__device__ __forceinline__ void cp_wait1() { asm volatile("cp.async.wait_group 1;"); }
__device__ __forceinline__ void ldsm_x4(uint32_t* r, uint32_t addr) {
    asm volatile("ldmatrix.sync.aligned.m8n8.x4.shared.b16 {%0,%1,%2,%3}, [%4];"
        : "=r"(r[0]), "=r"(r[1]), "=r"(r[2]), "=r"(r[3]) : "r"(addr));
}
__device__ __forceinline__ void mma16816(float* c, const uint32_t* a, const uint32_t* b) {
    asm volatile(
        "mma.sync.aligned.m16n8k16.row.col.f32.f16.f16.f32 "
        "{%0,%1,%2,%3}, {%4,%5,%6,%7}, {%8,%9}, {%0,%1,%2,%3};"
        : "+f"(c[0]), "+f"(c[1]), "+f"(c[2]), "+f"(c[3])
        : "r"(a[0]), "r"(a[1]), "r"(a[2]), "r"(a[3]), "r"(b[0]), "r"(b[1]));
}
__device__ __forceinline__ uint32_t pack_h2(float x, float y) {
    __half2 h = __floats2half2_rn(x, y);
    uint32_t u; memcpy(&u, &h, 4); return u;
}
__device__ __forceinline__ void splitw2(float x, float y, uint32_t& h, uint32_t& l) {
    __half2 hb = __floats2half2_rn(x, y);
    float2 hf = __half22float2(hb);
    __half2 lb = __floats2half2_rn(x - hf.x, y - hf.y);
    memcpy(&h, &hb, 4); memcpy(&l, &lb, 4);
}

__global__ void splitw_k(const float* __restrict__ s, fp16* __restrict__ hi,
                         fp16* __restrict__ lo, long n)
{
    long i = 4L * (blockIdx.x * (long)blockDim.x + threadIdx.x);
    if (i >= n) return;
    float4 v = *(const float4*)(s + i);
    uint32_t h0, l0, h1, l1;
    splitw2(v.x, v.y, h0, l0);
    splitw2(v.z, v.w, h1, l1);
    *(uint32_t*)(hi + i) = h0; *(uint32_t*)(hi + i + 2) = h1;
    *(uint32_t*)(lo + i) = l0; *(uint32_t*)(lo + i + 2) = l1;
}
__global__ void cvt_k(const float* __restrict__ s, fp16* __restrict__ o, long n)
{
    long i = 4L * (blockIdx.x * (long)blockDim.x + threadIdx.x);
    if (i >= n) return;
    float4 v = *(const float4*)(s + i);
    *(uint32_t*)(o + i) = pack_h2(v.x, v.y);
    *(uint32_t*)(o + i + 2) = pack_h2(v.z, v.w);
}

// ---------------------------------------------------------------------------
// fp16 HMMA GEMM, 3-stage cp.async pipeline (1 barrier/iter), ldmatrix.
// C = act(A . (Wh+Wl)^T + bias). Tile 128 x BN x 32k; 8 warps 4x2.
// Stage (u32): A[0,2560) Bh[2560,+BN*20) Bl[+BN*20). rows padded 20 u32.
// ---------------------------------------------------------------------------
template<int BN> struct StgSz { static constexpr int v = 2560 + BN * 40; };
constexpr int GEMM_SMEM96 = 3 * StgSz<96>::v * 4;   // 76800
constexpr int GEMM_SMEM64 = 3 * StgSz<64>::v * 4;   // 61440

template<int BN, bool RELU, bool WF32, bool WH16>
__global__ void __launch_bounds__(256)
tc_gemm(const fp16* __restrict__ Ag, int lda,
        const fp16* __restrict__ Whg, const fp16* __restrict__ Wlg,
        const float* __restrict__ bias,
        float* __restrict__ C, int ldc, int coff,
        fp16* __restrict__ S, int lds_, int scoff,
        int K)
{
    constexpr int NJ = BN / 16;
    constexpr int NJP = BN / 32;
    constexpr int STG = StgSz<BN>::v;
    constexpr int BLOFF = 2560 + BN * 20;

    extern __shared__ __align__(16) uint32_t sm32[];
    const uint32_t sbase = smem_u32(sm32);

    const int tid = threadIdx.x;
    const int wid = tid >> 5, lane = tid & 31;
    const int wr = wid >> 1, wc = wid & 1;
    const int m0 = blockIdx.y * 128, n0 = blockIdx.x * BN;

    float acc[2][NJ][4];
#pragma unroll
    for (int i = 0; i < 2; i++)
#pragma unroll
        for (int j = 0; j < NJ; j++)
#pragma unroll
            for (int q = 0; q < 4; q++) acc[i][j][q] = 0.f;

    const int lr = tid >> 2, seg = tid & 3;
    const int t7 = lane & 7, mi = lane >> 3;
    const int aRow0 = wr * 32 + t7 + (mi & 1) * 8;
    const int aCol  = (mi >> 1) * 4;
    const int bRow0 = wc * (BN / 2) + t7 + (mi >> 1) * 8;
    const int bCol  = (mi & 1) * 4;

    const int nc = K >> 5;

    auto issue = [&](int c) {
        const int k0 = c << 5;
        const uint32_t sb = sbase + (c % 3) * (STG * 4);
#pragma unroll
        for (int it = 0; it < 2; it++) {
            const int r = lr + it * 64;
            const size_t go = (size_t)(m0 + r) * lda + k0 + seg * 8;
            cp16(sb + (r * 20 + seg * 4) * 4, Ag + go);
        }
#pragma unroll
        for (int i = tid; i < BN * 4; i += 256) {
            const int r = i >> 2, sg = i & 3;
            const size_t gb = (size_t)(n0 + r) * K + k0 + sg * 8;
            cp16(sb + (2560 + r * 20 + sg * 4) * 4, Whg + gb);
            cp16(sb + (BLOFF + r * 20 + sg * 4) * 4, Wlg + gb);
        }
    };

    issue(0); cp_commit();
    if (nc > 1) { issue(1); cp_commit(); }
    else cp_commit();   // keep group count uniform

    for (int c = 0; c < nc; c++) {
        cp_wait1();          // FIFO completion: all but newest group done => stage c ready
        __syncthreads();     // everyone done computing c-1; safe to overwrite stage (c+2)%3
        if (c + 2 < nc) issue(c + 2);
        cp_commit();         // possibly empty group, keeps wait_group accounting uniform

        const uint32_t sb = sbase + (c % 3) * (STG * 4);
#pragma unroll
        for (int s = 0; s < 2; s++) {
            uint32_t ah[2][4], bh[NJ][2], bl[NJ][2];
#pragma unroll
            for (int i = 0; i < 2; i++) {
                const uint32_t ai = (uint32_t)((aRow0 + i * 16) * 20 + s * 8 + aCol) * 4;
                ldsm_x4(ah[i], sb + ai);
            }
#pragma unroll
            for (int jp = 0; jp < NJP; jp++) {
                const uint32_t bi = (uint32_t)((bRow0 + jp * 16) * 20 + s * 8 + bCol) * 4;
                uint32_t tb[4];
                ldsm_x4(tb, sb + 2560 * 4 + bi);
                bh[2 * jp][0] = tb[0]; bh[2 * jp][1] = tb[1];
                bh[2 * jp + 1][0] = tb[2]; bh[2 * jp + 1][1] = tb[3];
                ldsm_x4(tb, sb + BLOFF * 4 + bi);
                bl[2 * jp][0] = tb[0]; bl[2 * jp][1] = tb[1];
                bl[2 * jp + 1][0] = tb[2]; bl[2 * jp + 1][1] = tb[3];
            }
#pragma unroll
            for (int i = 0; i < 2; i++)
#pragma unroll
                for (int j = 0; j < NJ; j++) {
                    mma16816(acc[i][j], ah[i], bh[j]);
                    mma16816(acc[i][j], ah[i], bl[j]);
                }
        }
    }

    const int lg = lane >> 2, lq = lane & 3;
#pragma unroll
    for (int i = 0; i < 2; i++) {
        const int row = m0 + wr * 32 + i * 16 + lg;
#pragma unroll
        for (int j = 0; j < NJ; j++) {
            const int col = n0 + wc * (BN / 2) + j * 8 + 2 * lq;
            const float bx = bias[col], by = bias[col + 1];
            float2 v0, v1;
            v0.x = acc[i][j][0] + bx; v0.y = acc[i][j][1] + by;
            v1.x = acc[i][j][2] + bx; v1.y = acc[i][j][3] + by;
            if (RELU) {
                v0.x = fmaxf(v0.x, 0.f); v0.y = fmaxf(v0.y, 0.f);
                v1.x = fmaxf(v1.x, 0.f); v1.y = fmaxf(v1.y, 0.f);
            }
            if (WF32) {
                *(float2*)(C + (size_t)row * ldc + coff + col) = v0;
                *(float2*)(C + (size_t)(row + 8) * ldc + coff + col) = v1;
            }
            if (WH16) {
                *(uint32_t*)(S + (size_t)row * lds_ + scoff + col) = pack_h2(v0.x, v0.y);
                *(uint32_t*)(S + (size_t)(row + 8) * lds_ + scoff + col) = pack_h2(v1.x, v1.y);
            }
        }
    }
}

// ---------------- elementwise ----------------
__global__ void attn_kernel(const fp16* __restrict__ qkv, fp16* __restrict__ ch, int B)
{
    const int w = (blockIdx.x * blockDim.x + threadIdx.x) >> 5;
    const int lane = threadIdx.x & 31;
    if (w >= B) return;
    const fp16* r0 = qkv + (size_t)(2 * w) * 576;
    const fp16* r1 = r0 + 576;
    const size_t o0r = (size_t)(2 * w) * 192, o1r = o0r + 192;
#pragma unroll
    for (int h = 0; h < 3; h++) {
        const int o = h * 64 + 2 * lane;
        float2 q0 = __half22float2(*(const __half2*)(r0 + o));
        float2 q1 = __half22float2(*(const __half2*)(r1 + o));
        float2 k0 = __half22float2(*(const __half2*)(r0 + 192 + o));
        float2 k1 = __half22float2(*(const __half2*)(r1 + 192 + o));
        float2 v0 = __half22float2(*(const __half2*)(r0 + 384 + o));
        float2 v1 = __half22float2(*(const __half2*)(r1 + 384 + o));
        float s00 = q0.x * k0.x + q0.y * k0.y;
        float s01 = q0.x * k1.x + q0.y * k1.y;
        float s10 = q1.x * k0.x + q1.y * k0.y;
        float s11 = q1.x * k1.x + q1.y * k1.y;
#pragma unroll
        for (int d = 16; d; d >>= 1) {
            s00 += __shfl_xor_sync(0xffffffffu, s00, d);
            s01 += __shfl_xor_sync(0xffffffffu, s01, d);
            s10 += __shfl_xor_sync(0xffffffffu, s10, d);
            s11 += __shfl_xor_sync(0xffffffffu, s11, d);
        }
        s00 *= 0.125f; s01 *= 0.125f; s10 *= 0.125f; s11 *= 0.125f;
        float m0 = fmaxf(s00, s01);
        float e00 = expf(s00 - m0), e01 = expf(s01 - m0);
        float i0 = 1.f / (e00 + e01);
        float m1 = fmaxf(s10, s11);
        float e10 = expf(s10 - m1), e11 = expf(s11 - m1);
        float i1 = 1.f / (e10 + e11);
        float a00 = e00 * i0, a01 = e01 * i0, a10 = e10 * i1, a11 = e11 * i1;
        *(uint32_t*)(ch + o0r + o) = pack_h2(a00 * v0.x + a01 * v1.x, a00 * v0.y + a01 * v1.y);
        *(uint32_t*)(ch + o1r + o) = pack_h2(a10 * v0.x + a11 * v1.x, a10 * v0.y + a11 * v1.y);
    }
}

__global__ void add_ln_kernel(const float* __restrict__ A, const float* __restrict__ Bq,
                              const float* __restrict__ g, const float* __restrict__ be,
                              float* __restrict__ O, fp16* __restrict__ Oh, int nrows)
{
    const int w = (blockIdx.x * blockDim.x + threadIdx.x) >> 5;
    const int lane = threadIdx.x & 31;
    if (w >= nrows) return;
    const float* a = A + (size_t)w * 192;
    const float* b = Bq + (size_t)w * 192;
    float y[6], s = 0.f, ss = 0.f;
#pragma unroll
    for (int j = 0; j < 6; j++) {
        const int idx = lane + 32 * j;
        y[j] = a[idx] + b[idx];
        s += y[j]; ss += y[j] * y[j];
    }
#pragma unroll
    for (int d = 16; d; d >>= 1) {
        s += __shfl_xor_sync(0xffffffffu, s, d);
        ss += __shfl_xor_sync(0xffffffffu, ss, d);
    }
    const float mu = s * (1.f / 192.f);
    const float rs = rsqrtf(ss * (1.f / 192.f) - mu * mu + 1e-5f);
    float* o = O + (size_t)w * 192;
#pragma unroll
    for (int j = 0; j < 6; j++) {
        const int idx = lane + 32 * j;
        float v = (y[j] - mu) * rs * g[idx] + be[idx];
        o[idx] = v;
        Oh[(size_t)w * 192 + idx] = __float2half_rn(v);
    }
}

__global__ void ln2_mean_kernel(const float* __restrict__ X, const float* __restrict__ F,
                                const float* __restrict__ g, const float* __restrict__ be,
                                fp16* __restrict__ Zh, int B)
{
    const int w = (blockIdx.x * blockDim.x + threadIdx.x) >> 5;
    const int lane = threadIdx.x & 31;
    if (w >= B) return;
    float zacc[6];
#pragma unroll
    for (int j = 0; j < 6; j++) zacc[j] = 0.f;
#pragma unroll
    for (int t = 0; t < 2; t++) {
        const size_t row = (size_t)(2 * w + t) * 192;
        float y[6], s = 0.f, ss = 0.f;
#pragma unroll
        for (int j = 0; j < 6; j++) {
            const int idx = lane + 32 * j;
            y[j] = X[row + idx] + F[row + idx];
            s += y[j]; ss += y[j] * y[j];
        }
#pragma unroll
        for (int d = 16; d; d >>= 1) {
            s += __shfl_xor_sync(0xffffffffu, s, d);
            ss += __shfl_xor_sync(0xffffffffu, ss, d);
        }
        const float mu = s * (1.f / 192.f);
        const float rs = rsqrtf(ss * (1.f / 192.f) - mu * mu + 1e-5f);
#pragma unroll
        for (int j = 0; j < 6; j++) {
            const int idx = lane + 32 * j;
            zacc[j] += 0.5f * ((y[j] - mu) * rs * g[idx] + be[idx]);
        }
    }
#pragma unroll
    for (int j = 0; j < 6; j++)
        Zh[(size_t)w * 192 + lane + 32 * j] = __float2half_rn(zacc[j]);
}

__global__ void head_kernel(const float* __restrict__ C, const float* __restrict__ FPr,
                            const float* __restrict__ w2, const float* __restrict__ b2,
                            float* __restrict__ out, int B)
{
    const int w = (blockIdx.x * blockDim.x + threadIdx.x) >> 5;
    const int lane = threadIdx.x & 31;
    if (w >= B) return;
    const float* c = C + (size_t)w * 192;
    float l0 = 0.f, l1 = 0.f, l2 = 0.f;
#pragma unroll
    for (int j = 0; j < 6; j++) {
        const int idx = lane + 32 * j;
        const float cv = c[idx];
        l0 += cv * w2[idx];
        l1 += cv * w2[192 + idx];
        l2 += cv * w2[384 + idx];
    }
#pragma unroll
    for (int d = 16; d; d >>= 1) {
        l0 += __shfl_xor_sync(0xffffffffu, l0, d);
        l1 += __shfl_xor_sync(0xffffffffu, l1, d);
        l2 += __shfl_xor_sync(0xffffffffu, l2, d);
    }
    if (lane == 0) {
        out[w]         = 1.f / (1.f + expf(-(l0 + b2[0])));
        out[B + w]     = 1.f / (1.f + expf(-(l1 + b2[1])));
        out[2 * B + w] = 1.f / (1.f + expf(-(l2 + b2[2])));
    }
    const float* f = FPr + (size_t)w * 128;
    float fv[4], ss = 0.f;
#pragma unroll
    for (int j = 0; j < 4; j++) {
        fv[j] = f[lane + 32 * j];
        ss += fv[j] * fv[j];
    }
#pragma unroll
    for (int d = 16; d; d >>= 1) ss += __shfl_xor_sync(0xffffffffu, ss, d);
    const float sc = 1.f / fmaxf(sqrtf(ss), 1e-12f);
    float* fo = out + 3L * B + (size_t)w * 128;
#pragma unroll
    for (int j = 0; j < 4; j++) fo[lane + 32 * j] = fv[j] * sc;
}

// ---------------- host ----------------
static inline void dsym(void** p, const void* sym) { cudaGetSymbolAddress(p, sym); }

extern "C" void kernel_launch(void* const* d_in, const int* in_sizes, int n_in,
                              void* d_out, int out_size)
{
    const float* perc   = (const float*)d_in[0];
    const float* tech   = (const float*)d_in[1];
    const float* Wp     = (const float*)d_in[2];
    const float* bp     = (const float*)d_in[3];
    const float* Wt     = (const float*)d_in[4];
    const float* bt     = (const float*)d_in[5];
    const float* in_w   = (const float*)d_in[6];
    const float* in_b   = (const float*)d_in[7];
    const float* out_w  = (const float*)d_in[8];
    const float* out_b  = (const float*)d_in[9];
    const float* ffn_w1 = (const float*)d_in[10];
    const float* ffn_b1 = (const float*)d_in[11];
    const float* ffn_w2 = (const float*)d_in[12];
    const float* ffn_b2 = (const float*)d_in[13];
    const float* ln1_g  = (const float*)d_in[14];
    const float* ln1_b  = (const float*)d_in[15];
    const float* ln2_g  = (const float*)d_in[16];
    const float* ln2_b  = (const float*)d_in[17];
    const float* cls_w1 = (const float*)d_in[18];
    const float* cls_b1 = (const float*)d_in[19];
    const float* cls_w2 = (const float*)d_in[20];
    const float* cls_b2 = (const float*)d_in[21];
    const float* fp_w   = (const float*)d_in[22];
    const float* fp_b   = (const float*)d_in[23];

    int B = in_sizes[0] / DM;
    if (B > MAXB) B = MAXB;
    const int T = 2 * B;

    float *seq, *attnf, *x, *ffn, *c, *fp;
    dsym((void**)&seq, g_seq); dsym((void**)&attnf, g_attn);
    dsym((void**)&x, g_x); dsym((void**)&ffn, g_ffn); dsym((void**)&c, g_c);
    dsym((void**)&fp, g_fp);

    fp16 *pa, *ta, *seqh, *qkvh, *ctxh, *xh, *hh, *zh, *whi, *wlo;
    dsym((void**)&pa, g_pa); dsym((void**)&ta, g_ta);
    dsym((void**)&seqh, g_seqh); dsym((void**)&qkvh, g_qkvh);
    dsym((void**)&ctxh, g_ctxh);
    dsym((void**)&xh, g_xh); dsym((void**)&hh, g_hh); dsym((void**)&zh, g_zh);
    dsym((void**)&whi, g_whi); dsym((void**)&wlo, g_wlo);

    cudaFuncSetAttribute(tc_gemm<96, false, true,  true >, cudaFuncAttributeMaxDynamicSharedMemorySize, GEMM_SMEM96);
    cudaFuncSetAttribute(tc_gemm<96, false, false, true >, cudaFuncAttributeMaxDynamicSharedMemorySize, GEMM_SMEM96);
    cudaFuncSetAttribute(tc_gemm<96, false, true,  false>, cudaFuncAttributeMaxDynamicSharedMemorySize, GEMM_SMEM96);
    cudaFuncSetAttribute(tc_gemm<96, true,  false, true >, cudaFuncAttributeMaxDynamicSharedMemorySize, GEMM_SMEM96);
    cudaFuncSetAttribute(tc_gemm<96, true,  true,  false>, cudaFuncAttributeMaxDynamicSharedMemorySize, GEMM_SMEM96);
    cudaFuncSetAttribute(tc_gemm<64, false, true,  false>, cudaFuncAttributeMaxDynamicSharedMemorySize, GEMM_SMEM64);

    float* out = (float*)d_out;

    auto spw = [&](const float* s, fp16* h, fp16* l, long n) {
        splitw_k<<<(int)((n / 4 + 255) / 256), 256>>>(s, h, l, n);
    };
    spw(Wp, whi + OW_P, wlo + OW_P, 36864);
    spw(Wt, whi + OW_T, wlo + OW_T, 36864);
    spw(in_w, whi + OW_IN, wlo + OW_IN, 110592);
    spw(out_w, whi + OW_OUT, wlo + OW_OUT, 36864);
    spw(ffn_w1, whi + OW_F1, wlo + OW_F1, 73728);
    spw(ffn_w2, whi + OW_F2, wlo + OW_F2, 73728);
    spw(cls_w1, whi + OW_CLS, wlo + OW_CLS, 36864);
    spw(fp_w, whi + OW_FP, wlo + OW_FP, 24576);
    cvt_k<<<(int)(((long)B * 192 / 4 + 255) / 256), 256>>>(perc, pa, (long)B * 192);
    cvt_k<<<(int)(((long)B * 192 / 4 + 255) / 256), 256>>>(tech, ta, (long)B * 192);

    // projections -> seq fp32 + fp16 (seq stored [B,384]; token view [2B,192])
    tc_gemm<96, false, true, true><<<dim3(2, B / 128), 256, GEMM_SMEM96>>>(
        pa, 192, whi + OW_P, wlo + OW_P, bp, seq, 384, 0, seqh, 384, 0, 192);
    tc_gemm<96, false, true, true><<<dim3(2, B / 128), 256, GEMM_SMEM96>>>(
        ta, 192, whi + OW_T, wlo + OW_T, bt, seq, 384, 192, seqh, 384, 192, 192);
    // qkv fp16 only: token view lda 192
    tc_gemm<96, false, false, true><<<dim3(6, T / 128), 256, GEMM_SMEM96>>>(
        seqh, 192, whi + OW_IN, wlo + OW_IN, in_b, nullptr, 0, 0, qkvh, 576, 0, 192);
    attn_kernel<<<(B + 7) / 8, 256>>>(qkvh, ctxh, B);
    tc_gemm<96, false, true, false><<<dim3(2, T / 128), 256, GEMM_SMEM96>>>(
        ctxh, 192, whi + OW_OUT, wlo + OW_OUT, out_b, attnf, 192, 0, nullptr, 0, 0, 192);
    add_ln_kernel<<<(T + 7) / 8, 256>>>(seq, attnf, ln1_g, ln1_b, x, xh, T);
    tc_gemm<96, true, false, true><<<dim3(4, T / 128), 256, GEMM_SMEM96>>>(
        xh, 192, whi + OW_F1, wlo + OW_F1, ffn_b1, nullptr, 0, 0, hh, 384, 0, 192);
    tc_gemm<96, false, true, false><<<dim3(2, T / 128), 256, GEMM_SMEM96>>>(
        hh, 384, whi + OW_F2, wlo + OW_F2, ffn_b2, ffn, 192, 0, nullptr, 0, 0, 384);
    ln2_mean_kernel<<<(B + 7) / 8, 256>>>(x, ffn, ln2_g, ln2_b, zh, B);
    tc_gemm<96, true, true, false><<<dim3(2, B / 128), 256, GEMM_SMEM96>>>(
        zh, 192, whi + OW_CLS, wlo + OW_CLS, cls_b1, c, 192, 0, nullptr, 0, 0, 192);
    tc_gemm<64, false, true, false><<<dim3(2, B / 128), 256, GEMM_SMEM64>>>(
        zh, 192, whi + OW_FP, wlo + OW_FP, fp_b, fp, 128, 0, nullptr, 0, 0, 192);
    head_kernel<<<(B + 7) / 8, 256>>>(c, fp, cls_w2, cls_b2, out, B);
}

// round 12
// speedup vs baseline: 3.2670x; 1.0053x over previous
#include <cuda_runtime.h>
#include <cuda_fp16.h>
#include <stdint.h>
#include <string.h>
#include <math.h>

typedef __half fp16;

constexpr int DM = 192;
constexpr int MAXB = 65536;
constexpr long NT = 2L * MAXB;

// fp32 scratch
__device__ float g_seq[NT * DM];
__device__ float g_x[NT * DM];
__device__ float g_c[(long)MAXB * DM];
__device__ float g_fp[(long)MAXB * 128];

// fp16 activation scratch
__device__ fp16 g_pa[(long)MAXB * DM], g_ta[(long)MAXB * DM];
__device__ fp16 g_seqh[NT * DM];
__device__ fp16 g_qkvh[NT * 3 * DM];
__device__ fp16 g_ctxh[NT * DM];
__device__ fp16 g_xh[NT * DM];
__device__ fp16 g_hh[NT * 2 * DM];
__device__ fp16 g_zh[(long)MAXB * DM];

// weight split scratch (fp16 hi + lo)
constexpr int OW_P = 0, OW_T = 36864, OW_IN = 73728, OW_OUT = 184320;
constexpr int OW_F1 = 221184, OW_F2 = 294912, OW_CLS = 368640, OW_FP = 405504;
constexpr int OW_TOT = 430080;
__device__ fp16 g_whi[OW_TOT], g_wlo[OW_TOT];

// ---------------- helpers ----------------
__device__ __forceinline__ uint32_t smem_u32(const void* p) {
    uint32_t a;
    asm("{ .reg .u64 t; cvta.to.shared.u64 t, %1; cvt.u32.u64 %0, t; }" : "=r"(a) : "l"(p));
    return a;
}
__device__ __forceinline__ void cp16(uint32_t dst, const void* src) {
    asm volatile("cp.async.cg.shared.global [%0], [%1], 16;" :: "r"(dst), "l"(src));
}
__device__ __forceinline__ void cp_commit() { asm volatile("cp.async.commit_group;"); }
__device__ __forceinline__ void cp_wait1() { asm volatile("cp.async.wait_group 1;"); }
__device__ __forceinline__ void ldsm_x4(uint32_t* r, uint32_t addr) {
    asm volatile("ldmatrix.sync.aligned.m8n8.x4.shared.b16 {%0,%1,%2,%3}, [%4];"
        : "=r"(r[0]), "=r"(r[1]), "=r"(r[2]), "=r"(r[3]) : "r"(addr));
}
__device__ __forceinline__ void mma16816(float* c, const uint32_t* a, const uint32_t* b) {
    asm volatile(
        "mma.sync.aligned.m16n8k16.row.col.f32.f16.f16.f32 "
        "{%0,%1,%2,%3}, {%4,%5,%6,%7}, {%8,%9}, {%0,%1,%2,%3};"
        : "+f"(c[0]), "+f"(c[1]), "+f"(c[2]), "+f"(c[3])
        : "r"(a[0]), "r"(a[1]), "r"(a[2]), "r"(a[3]), "r"(b[0]), "r"(b[1]));
}
__device__ __forceinline__ uint32_t pack_h2(float x, float y) {
    __half2 h = __floats2half2_rn(x, y);
    uint32_t u; memcpy(&u, &h, 4); return u;
}
__device__ __forceinline__ void splitw2(float x, float y, uint32_t& h, uint32_t& l) {
    __half2 hb = __floats2half2_rn(x, y);
    float2 hf = __half22float2(hb);
    __half2 lb = __floats2half2_rn(x - hf.x, y - hf.y);
    memcpy(&h, &hb, 4); memcpy(&l, &lb, 4);
}

__global__ void splitw_k(const float* __restrict__ s, fp16* __restrict__ hi,
                         fp16* __restrict__ lo, long n)
{
    long i = 4L * (blockIdx.x * (long)blockDim.x + threadIdx.x);
    if (i >= n) return;
    float4 v = *(const float4*)(s + i);
    uint32_t h0, l0, h1, l1;
    splitw2(v.x, v.y, h0, l0);
    splitw2(v.z, v.w, h1, l1);
    *(uint32_t*)(hi + i) = h0; *(uint32_t*)(hi + i + 2) = h1;
    *(uint32_t*)(lo + i) = l0; *(uint32_t*)(lo + i + 2) = l1;
}
__global__ void cvt_k(const float* __restrict__ s, fp16* __restrict__ o, long n)
{
    long i = 4L * (blockIdx.x * (long)blockDim.x + threadIdx.x);
    if (i >= n) return;
    float4 v = *(const float4*)(s + i);
    *(uint32_t*)(o + i) = pack_h2(v.x, v.y);
    *(uint32_t*)(o + i + 2) = pack_h2(v.z, v.w);
}

// ---------------------------------------------------------------------------
// Generic fp16 HMMA GEMM (3-stage, ldmatrix) — same as R11.
// ---------------------------------------------------------------------------
template<int BN> struct StgSz { static constexpr int v = 2560 + BN * 40; };
constexpr int GEMM_SMEM96 = 3 * StgSz<96>::v * 4;
constexpr int GEMM_SMEM64 = 3 * StgSz<64>::v * 4;
constexpr int LN_SMEM = 2 * StgSz<192>::v * 4;   // 81920

template<int BN, bool RELU, bool WF32, bool WH16>
__global__ void __launch_bounds__(256)
tc_gemm(const fp16* __restrict__ Ag, int lda,
        const fp16* __restrict__ Whg, const fp16* __restrict__ Wlg,
        const float* __restrict__ bias,
        float* __restrict__ C, int ldc, int coff,
        fp16* __restrict__ S, int lds_, int scoff,
        int K)
{
    constexpr int NJ = BN / 16;
    constexpr int NJP = BN / 32;
    constexpr int STG = StgSz<BN>::v;
    constexpr int BLOFF = 2560 + BN * 20;

    extern __shared__ __align__(16) uint32_t sm32[];
    const uint32_t sbase = smem_u32(sm32);
    const int tid = threadIdx.x;
    const int wid = tid >> 5, lane = tid & 31;
    const int wr = wid >> 1, wc = wid & 1;
    const int m0 = blockIdx.y * 128, n0 = blockIdx.x * BN;

    float acc[2][NJ][4];
#pragma unroll
    for (int i = 0; i < 2; i++)
#pragma unroll
        for (int j = 0; j < NJ; j++)
#pragma unroll
            for (int q = 0; q < 4; q++) acc[i][j][q] = 0.f;

    const int lr = tid >> 2, seg = tid & 3;
    const int t7 = lane & 7, mi = lane >> 3;
    const int aRow0 = wr * 32 + t7 + (mi & 1) * 8;
    const int aCol  = (mi >> 1) * 4;
    const int bRow0 = wc * (BN / 2) + t7 + (mi >> 1) * 8;
    const int bCol  = (mi & 1) * 4;
    const int nc = K >> 5;

    auto issue = [&](int c) {
        const int k0 = c << 5;
        const uint32_t sb = sbase + (c % 3) * (STG * 4);
#pragma unroll
        for (int it = 0; it < 2; it++) {
            const int r = lr + it * 64;
            cp16(sb + (r * 20 + seg * 4) * 4, Ag + (size_t)(m0 + r) * lda + k0 + seg * 8);
        }
#pragma unroll
        for (int i = tid; i < BN * 4; i += 256) {
            const int r = i >> 2, sg = i & 3;
            const size_t gb = (size_t)(n0 + r) * K + k0 + sg * 8;
            cp16(sb + (2560 + r * 20 + sg * 4) * 4, Whg + gb);
            cp16(sb + (BLOFF + r * 20 + sg * 4) * 4, Wlg + gb);
        }
    };

    issue(0); cp_commit();
    if (nc > 1) { issue(1); cp_commit(); } else cp_commit();

    for (int c = 0; c < nc; c++) {
        cp_wait1();
        __syncthreads();
        if (c + 2 < nc) issue(c + 2);
        cp_commit();

        const uint32_t sb = sbase + (c % 3) * (STG * 4);
#pragma unroll
        for (int s = 0; s < 2; s++) {
            uint32_t ah[2][4], bh[NJ][2], bl[NJ][2];
#pragma unroll
            for (int i = 0; i < 2; i++) {
                const uint32_t ai = (uint32_t)((aRow0 + i * 16) * 20 + s * 8 + aCol) * 4;
                ldsm_x4(ah[i], sb + ai);
            }
#pragma unroll
            for (int jp = 0; jp < NJP; jp++) {
                const uint32_t bi = (uint32_t)((bRow0 + jp * 16) * 20 + s * 8 + bCol) * 4;
                uint32_t tb[4];
                ldsm_x4(tb, sb + 2560 * 4 + bi);
                bh[2 * jp][0] = tb[0]; bh[2 * jp][1] = tb[1];
                bh[2 * jp + 1][0] = tb[2]; bh[2 * jp + 1][1] = tb[3];
                ldsm_x4(tb, sb + BLOFF * 4 + bi);
                bl[2 * jp][0] = tb[0]; bl[2 * jp][1] = tb[1];
                bl[2 * jp + 1][0] = tb[2]; bl[2 * jp + 1][1] = tb[3];
            }
#pragma unroll
            for (int i = 0; i < 2; i++)
#pragma unroll
                for (int j = 0; j < NJ; j++) {
                    mma16816(acc[i][j], ah[i], bh[j]);
                    mma16816(acc[i][j], ah[i], bl[j]);
                }
        }
    }

    const int lg = lane >> 2, lq = lane & 3;
#pragma unroll
    for (int i = 0; i < 2; i++) {
        const int row = m0 + wr * 32 + i * 16 + lg;
#pragma unroll
        for (int j = 0; j < NJ; j++) {
            const int col = n0 + wc * (BN / 2) + j * 8 + 2 * lq;
            const float bx = bias[col], by = bias[col + 1];
            float2 v0, v1;
            v0.x = acc[i][j][0] + bx; v0.y = acc[i][j][1] + by;
            v1.x = acc[i][j][2] + bx; v1.y = acc[i][j][3] + by;
            if (RELU) {
                v0.x = fmaxf(v0.x, 0.f); v0.y = fmaxf(v0.y, 0.f);
                v1.x = fmaxf(v1.x, 0.f); v1.y = fmaxf(v1.y, 0.f);
            }
            if (WF32) {
                *(float2*)(C + (size_t)row * ldc + coff + col) = v0;
                *(float2*)(C + (size_t)(row + 8) * ldc + coff + col) = v1;
            }
            if (WH16) {
                *(uint32_t*)(S + (size_t)row * lds_ + scoff + col) = pack_h2(v0.x, v0.y);
                *(uint32_t*)(S + (size_t)(row + 8) * lds_ + scoff + col) = pack_h2(v1.x, v1.y);
            }
        }
    }
}

// ---------------------------------------------------------------------------
// Fused GEMM + residual + LayerNorm. BN=192 (full row in one CTA), 2-stage.
// MODE 1: y = RES + A.W^T + bias; x = LN1(y) -> Xout fp32 + Xh fp16
// MODE 2: y = RES + A.W^T + bias; v = LN2(y); z = token-pair mean -> Zh fp16
// ---------------------------------------------------------------------------
template<int MODE>
__global__ void __launch_bounds__(256)
gemm_ln(const fp16* __restrict__ Ag, int lda,
        const fp16* __restrict__ Whg, const fp16* __restrict__ Wlg,
        const float* __restrict__ bias,
        const float* __restrict__ RES,
        const float* __restrict__ gam, const float* __restrict__ bet,
        float* __restrict__ Xout, fp16* __restrict__ Xh,
        int K)
{
    constexpr int BN = 192, NJ = 12, NJP = 6;
    constexpr int STG = StgSz<192>::v;     // 10240 u32
    constexpr int BLOFF = 2560 + 192 * 20; // 6400

    extern __shared__ __align__(16) uint32_t sm32[];
    __shared__ float rsum[128][2], rssq[128][2];
    const uint32_t sbase = smem_u32(sm32);
    const int tid = threadIdx.x;
    const int wid = tid >> 5, lane = tid & 31;
    const int wr = wid >> 1, wc = wid & 1;
    const int m0 = blockIdx.y * 128;

    float acc[2][NJ][4];
#pragma unroll
    for (int i = 0; i < 2; i++)
#pragma unroll
        for (int j = 0; j < NJ; j++)
#pragma unroll
            for (int q = 0; q < 4; q++) acc[i][j][q] = 0.f;

    const int lr = tid >> 2, seg = tid & 3;
    const int t7 = lane & 7, mi = lane >> 3;
    const int aRow0 = wr * 32 + t7 + (mi & 1) * 8;
    const int aCol  = (mi >> 1) * 4;
    const int bRow0 = wc * 96 + t7 + (mi >> 1) * 8;
    const int bCol  = (mi & 1) * 4;
    const int nc = K >> 5;

    auto issue = [&](int c, int buf) {
        const int k0 = c << 5;
        const uint32_t sb = sbase + buf * (STG * 4);
#pragma unroll
        for (int it = 0; it < 2; it++) {
            const int r = lr + it * 64;
            cp16(sb + (r * 20 + seg * 4) * 4, Ag + (size_t)(m0 + r) * lda + k0 + seg * 8);
        }
#pragma unroll
        for (int i = tid; i < 768; i += 256) {
            const int r = i >> 2, sg = i & 3;
            const size_t gb = (size_t)r * K + k0 + sg * 8;
            cp16(sb + (2560 + r * 20 + sg * 4) * 4, Whg + gb);
            cp16(sb + (BLOFF + r * 20 + sg * 4) * 4, Wlg + gb);
        }
    };

    issue(0, 0); cp_commit();
    for (int c = 0; c < nc; c++) {
        if (c + 1 < nc) issue(c + 1, (c + 1) & 1);
        cp_commit();
        cp_wait1();
        __syncthreads();

        const uint32_t sb = sbase + (c & 1) * (STG * 4);
#pragma unroll
        for (int s = 0; s < 2; s++) {
            uint32_t ah[2][4], bh[NJ][2], bl[NJ][2];
#pragma unroll
            for (int i = 0; i < 2; i++) {
                const uint32_t ai = (uint32_t)((aRow0 + i * 16) * 20 + s * 8 + aCol) * 4;
                ldsm_x4(ah[i], sb + ai);
            }
#pragma unroll
            for (int jp = 0; jp < NJP; jp++) {
                const uint32_t bi = (uint32_t)((bRow0 + jp * 16) * 20 + s * 8 + bCol) * 4;
                uint32_t tb[4];
                ldsm_x4(tb, sb + 2560 * 4 + bi);
                bh[2 * jp][0] = tb[0]; bh[2 * jp][1] = tb[1];
                bh[2 * jp + 1][0] = tb[2]; bh[2 * jp + 1][1] = tb[3];
                ldsm_x4(tb, sb + BLOFF * 4 + bi);
                bl[2 * jp][0] = tb[0]; bl[2 * jp][1] = tb[1];
                bl[2 * jp + 1][0] = tb[2]; bl[2 * jp + 1][1] = tb[3];
            }
#pragma unroll
            for (int i = 0; i < 2; i++)
#pragma unroll
                for (int j = 0; j < NJ; j++) {
                    mma16816(acc[i][j], ah[i], bh[j]);
                    mma16816(acc[i][j], ah[i], bl[j]);
                }
        }
        __syncthreads();
    }

    // ---- fused epilogue: y = RES + acc + bias; row LN ----
    const int lg = lane >> 2, lq = lane & 3;
    float sP[4] = {0.f, 0.f, 0.f, 0.f}, ssP[4] = {0.f, 0.f, 0.f, 0.f};
#pragma unroll
    for (int i = 0; i < 2; i++) {
#pragma unroll
        for (int h = 0; h < 2; h++) {
            const int row = m0 + wr * 32 + i * 16 + h * 8 + lg;
            const float* rp = RES + (size_t)row * 192;
            const int slot = i * 2 + h;
#pragma unroll
            for (int j = 0; j < NJ; j++) {
                const int col = wc * 96 + j * 8 + 2 * lq;
                float2 r2 = *(const float2*)(rp + col);
                float y0 = acc[i][j][2 * h]     + bias[col]     + r2.x;
                float y1 = acc[i][j][2 * h + 1] + bias[col + 1] + r2.y;
                acc[i][j][2 * h] = y0; acc[i][j][2 * h + 1] = y1;
                sP[slot] += y0 + y1;
                ssP[slot] += y0 * y0 + y1 * y1;
            }
        }
    }
#pragma unroll
    for (int slot = 0; slot < 4; slot++) {
#pragma unroll
        for (int d = 1; d < 4; d <<= 1) {
            sP[slot]  += __shfl_xor_sync(0xffffffffu, sP[slot], d);
            ssP[slot] += __shfl_xor_sync(0xffffffffu, ssP[slot], d);
        }
    }
    if (lq == 0) {
#pragma unroll
        for (int i = 0; i < 2; i++)
#pragma unroll
            for (int h = 0; h < 2; h++) {
                const int lrow = wr * 32 + i * 16 + h * 8 + lg;
                rsum[lrow][wc] = sP[i * 2 + h];
                rssq[lrow][wc] = ssP[i * 2 + h];
            }
    }
    __syncthreads();

#pragma unroll
    for (int i = 0; i < 2; i++) {
#pragma unroll
        for (int h = 0; h < 2; h++) {
            const int lrow = wr * 32 + i * 16 + h * 8 + lg;
            const int row = m0 + lrow;
            const float tot = rsum[lrow][0] + rsum[lrow][1];
            const float tss = rssq[lrow][0] + rssq[lrow][1];
            const float mu = tot * (1.f / 192.f);
            const float rs = rsqrtf(tss * (1.f / 192.f) - mu * mu + 1e-5f);
#pragma unroll
            for (int j = 0; j < NJ; j++) {
                const int col = wc * 96 + j * 8 + 2 * lq;
                float v0 = (acc[i][j][2 * h]     - mu) * rs * gam[col]     + bet[col];
                float v1 = (acc[i][j][2 * h + 1] - mu) * rs * gam[col + 1] + bet[col + 1];
                if (MODE == 1) {
                    *(float2*)(Xout + (size_t)row * 192 + col) = make_float2(v0, v1);
                    *(uint32_t*)(Xh + (size_t)row * 192 + col) = pack_h2(v0, v1);
                } else {
                    float p0 = __shfl_xor_sync(0xffffffffu, v0, 4);
                    float p1 = __shfl_xor_sync(0xffffffffu, v1, 4);
                    if ((lg & 1) == 0) {
                        *(uint32_t*)(Xh + (size_t)(row >> 1) * 192 + col) =
                            pack_h2(0.5f * (v0 + p0), 0.5f * (v1 + p1));
                    }
                }
            }
        }
    }
}

// ---------------- elementwise ----------------
__global__ void attn_kernel(const fp16* __restrict__ qkv, fp16* __restrict__ ch, int B)
{
    const int w = (blockIdx.x * blockDim.x + threadIdx.x) >> 5;
    const int lane = threadIdx.x & 31;
    if (w >= B) return;
    const fp16* r0 = qkv + (size_t)(2 * w) * 576;
    const fp16* r1 = r0 + 576;
    const size_t o0r = (size_t)(2 * w) * 192, o1r = o0r + 192;
#pragma unroll
    for (int h = 0; h < 3; h++) {
        const int o = h * 64 + 2 * lane;
        float2 q0 = __half22float2(*(const __half2*)(r0 + o));
        float2 q1 = __half22float2(*(const __half2*)(r1 + o));
        float2 k0 = __half22float2(*(const __half2*)(r0 + 192 + o));
        float2 k1 = __half22float2(*(const __half2*)(r1 + 192 + o));
        float2 v0 = __half22float2(*(const __half2*)(r0 + 384 + o));
        float2 v1 = __half22float2(*(const __half2*)(r1 + 384 + o));
        float s00 = q0.x * k0.x + q0.y * k0.y;
        float s01 = q0.x * k1.x + q0.y * k1.y;
        float s10 = q1.x * k0.x + q1.y * k0.y;
        float s11 = q1.x * k1.x + q1.y * k1.y;
#pragma unroll
        for (int d = 16; d; d >>= 1) {
            s00 += __shfl_xor_sync(0xffffffffu, s00, d);
            s01 += __shfl_xor_sync(0xffffffffu, s01, d);
            s10 += __shfl_xor_sync(0xffffffffu, s10, d);
            s11 += __shfl_xor_sync(0xffffffffu, s11, d);
        }
        s00 *= 0.125f; s01 *= 0.125f; s10 *= 0.125f; s11 *= 0.125f;
        float m0 = fmaxf(s00, s01);
        float e00 = expf(s00 - m0), e01 = expf(s01 - m0);
        float i0 = 1.f / (e00 + e01);
        float m1 = fmaxf(s10, s11);
        float e10 = expf(s10 - m1), e11 = expf(s11 - m1);
        float i1 = 1.f / (e10 + e11);
        float a00 = e00 * i0, a01 = e01 * i0, a10 = e10 * i1, a11 = e11 * i1;
        *(uint32_t*)(ch + o0r + o) = pack_h2(a00 * v0.x + a01 * v1.x, a00 * v0.y + a01 * v1.y);
        *(uint32_t*)(ch + o1r + o) = pack_h2(a10 * v0.x + a11 * v1.x, a10 * v0.y + a11 * v1.y);
    }
}

__global__ void head_kernel(const float* __restrict__ C, const float* __restrict__ FPr,
                            const float* __restrict__ w2, const float* __restrict__ b2,
                            float* __restrict__ out, int B)
{
    const int w = (blockIdx.x * blockDim.x + threadIdx.x) >> 5;
    const int lane = threadIdx.x & 31;
    if (w >= B) return;
    const float* c = C + (size_t)w * 192;
    float l0 = 0.f, l1 = 0.f, l2 = 0.f;
#pragma unroll
    for (int j = 0; j < 6; j++) {
        const int idx = lane + 32 * j;
        const float cv = c[idx];
        l0 += cv * w2[idx];
        l1 += cv * w2[192 + idx];
        l2 += cv * w2[384 + idx];
    }
#pragma unroll
    for (int d = 16; d; d >>= 1) {
        l0 += __shfl_xor_sync(0xffffffffu, l0, d);
        l1 += __shfl_xor_sync(0xffffffffu, l1, d);
        l2 += __shfl_xor_sync(0xffffffffu, l2, d);
    }
    if (lane == 0) {
        out[w]         = 1.f / (1.f + expf(-(l0 + b2[0])));
        out[B + w]     = 1.f / (1.f + expf(-(l1 + b2[1])));
        out[2 * B + w] = 1.f / (1.f + expf(-(l2 + b2[2])));
    }
    const float* f = FPr + (size_t)w * 128;
    float fv[4], ss = 0.f;
#pragma unroll
    for (int j = 0; j < 4; j++) {
        fv[j] = f[lane + 32 * j];
        ss += fv[j] * fv[j];
    }
#pragma unroll
    for (int d = 16; d; d >>= 1) ss += __shfl_xor_sync(0xffffffffu, ss, d);
    const float sc = 1.f / fmaxf(sqrtf(ss), 1e-12f);
    float* fo = out + 3L * B + (size_t)w * 128;
#pragma unroll
    for (int j = 0; j < 4; j++) fo[lane + 32 * j] = fv[j] * sc;
}

// ---------------- host ----------------
static inline void dsym(void** p, const void* sym) { cudaGetSymbolAddress(p, sym); }

extern "C" void kernel_launch(void* const* d_in, const int* in_sizes, int n_in,
                              void* d_out, int out_size)
{
    const float* perc   = (const float*)d_in[0];
    const float* tech   = (const float*)d_in[1];
    const float* Wp     = (const float*)d_in[2];
    const float* bp     = (const float*)d_in[3];
    const float* Wt     = (const float*)d_in[4];
    const float* bt     = (const float*)d_in[5];
    const float* in_w   = (const float*)d_in[6];
    const float* in_b   = (const float*)d_in[7];
    const float* out_w  = (const float*)d_in[8];
    const float* out_b  = (const float*)d_in[9];
    const float* ffn_w1 = (const float*)d_in[10];
    const float* ffn_b1 = (const float*)d_in[11];
    const float* ffn_w2 = (const float*)d_in[12];
    const float* ffn_b2 = (const float*)d_in[13];
    const float* ln1_g  = (const float*)d_in[14];
    const float* ln1_b  = (const float*)d_in[15];
    const float* ln2_g  = (const float*)d_in[16];
    const float* ln2_b  = (const float*)d_in[17];
    const float* cls_w1 = (const float*)d_in[18];
    const float* cls_b1 = (const float*)d_in[19];
    const float* cls_w2 = (const float*)d_in[20];
    const float* cls_b2 = (const float*)d_in[21];
    const float* fp_w   = (const float*)d_in[22];
    const float* fp_b   = (const float*)d_in[23];

    int B = in_sizes[0] / DM;
    if (B > MAXB) B = MAXB;
    const int T = 2 * B;

    float *seq, *x, *c, *fp;
    dsym((void**)&seq, g_seq); dsym((void**)&x, g_x);
    dsym((void**)&c, g_c); dsym((void**)&fp, g_fp);

    fp16 *pa, *ta, *seqh, *qkvh, *ctxh, *xh, *hh, *zh, *whi, *wlo;
    dsym((void**)&pa, g_pa); dsym((void**)&ta, g_ta);
    dsym((void**)&seqh, g_seqh); dsym((void**)&qkvh, g_qkvh);
    dsym((void**)&ctxh, g_ctxh);
    dsym((void**)&xh, g_xh); dsym((void**)&hh, g_hh); dsym((void**)&zh, g_zh);
    dsym((void**)&whi, g_whi); dsym((void**)&wlo, g_wlo);

    cudaFuncSetAttribute(tc_gemm<96, false, true,  true >, cudaFuncAttributeMaxDynamicSharedMemorySize, GEMM_SMEM96);
    cudaFuncSetAttribute(tc_gemm<96, false, false, true >, cudaFuncAttributeMaxDynamicSharedMemorySize, GEMM_SMEM96);
    cudaFuncSetAttribute(tc_gemm<96, true,  false, true >, cudaFuncAttributeMaxDynamicSharedMemorySize, GEMM_SMEM96);
    cudaFuncSetAttribute(tc_gemm<96, true,  true,  false>, cudaFuncAttributeMaxDynamicSharedMemorySize, GEMM_SMEM96);
    cudaFuncSetAttribute(tc_gemm<64, false, true,  false>, cudaFuncAttributeMaxDynamicSharedMemorySize, GEMM_SMEM64);
    cudaFuncSetAttribute(gemm_ln<1>, cudaFuncAttributeMaxDynamicSharedMemorySize, LN_SMEM);
    cudaFuncSetAttribute(gemm_ln<2>, cudaFuncAttributeMaxDynamicSharedMemorySize, LN_SMEM);

    float* out = (float*)d_out;

    auto spw = [&](const float* s, fp16* h, fp16* l, long n) {
        splitw_k<<<(int)((n / 4 + 255) / 256), 256>>>(s, h, l, n);
    };
    spw(Wp, whi + OW_P, wlo + OW_P, 36864);
    spw(Wt, whi + OW_T, wlo + OW_T, 36864);
    spw(in_w, whi + OW_IN, wlo + OW_IN, 110592);
    spw(out_w, whi + OW_OUT, wlo + OW_OUT, 36864);
    spw(ffn_w1, whi + OW_F1, wlo + OW_F1, 73728);
    spw(ffn_w2, whi + OW_F2, wlo + OW_F2, 73728);
    spw(cls_w1, whi + OW_CLS, wlo + OW_CLS, 36864);
    spw(fp_w, whi + OW_FP, wlo + OW_FP, 24576);
    cvt_k<<<(int)(((long)B * 192 / 4 + 255) / 256), 256>>>(perc, pa, (long)B * 192);
    cvt_k<<<(int)(((long)B * 192 / 4 + 255) / 256), 256>>>(tech, ta, (long)B * 192);

    // projections -> seq fp32 + fp16 (seq stored [B,384]; token view [2B,192])
    tc_gemm<96, false, true, true><<<dim3(2, B / 128), 256, GEMM_SMEM96>>>(
        pa, 192, whi + OW_P, wlo + OW_P, bp, seq, 384, 0, seqh, 384, 0, 192);
    tc_gemm<96, false, true, true><<<dim3(2, B / 128), 256, GEMM_SMEM96>>>(
        ta, 192, whi + OW_T, wlo + OW_T, bt, seq, 384, 192, seqh, 384, 192, 192);
    // qkv fp16: token view lda 192
    tc_gemm<96, false, false, true><<<dim3(6, T / 128), 256, GEMM_SMEM96>>>(
        seqh, 192, whi + OW_IN, wlo + OW_IN, in_b, nullptr, 0, 0, qkvh, 576, 0, 192);
    attn_kernel<<<(B + 7) / 8, 256>>>(qkvh, ctxh, B);
    // out-proj fused with +seq residual and LN1 -> x fp32 + xh fp16
    gemm_ln<1><<<dim3(1, T / 128), 256, LN_SMEM>>>(
        ctxh, 192, whi + OW_OUT, wlo + OW_OUT, out_b, seq, ln1_g, ln1_b, x, xh, 192);
    // ffn1
    tc_gemm<96, true, false, true><<<dim3(4, T / 128), 256, GEMM_SMEM96>>>(
        xh, 192, whi + OW_F1, wlo + OW_F1, ffn_b1, nullptr, 0, 0, hh, 384, 0, 192);
    // ffn2 fused with +x residual, LN2, token mean -> zh fp16
    gemm_ln<2><<<dim3(1, T / 128), 256, LN_SMEM>>>(
        hh, 384, whi + OW_F2, wlo + OW_F2, ffn_b2, x, ln2_g, ln2_b, nullptr, zh, 384);
    // heads
    tc_gemm<96, true, true, false><<<dim3(2, B / 128), 256, GEMM_SMEM96>>>(
        zh, 192, whi + OW_CLS, wlo + OW_CLS, cls_b1, c, 192, 0, nullptr, 0, 0, 192);
    tc_gemm<64, false, true, false><<<dim3(2, B / 128), 256, GEMM_SMEM64>>>(
        zh, 192, whi + OW_FP, wlo + OW_FP, fp_b, fp, 128, 0, nullptr, 0, 0, 192);
    head_kernel<<<(B + 7) / 8, 256>>>(c, fp, cls_w2, cls_b2, out, B);
}

// round 13
// speedup vs baseline: 4.2512x; 1.3013x over previous
#include <cuda_runtime.h>
#include <cuda_fp16.h>
#include <stdint.h>
#include <string.h>
#include <math.h>

typedef __half fp16;

constexpr int DM = 192;
constexpr int MAXB = 65536;
constexpr long NT = 2L * MAXB;

// fp32 scratch
__device__ float g_seq[NT * DM];
__device__ float g_x[NT * DM];
__device__ float g_c[(long)MAXB * DM];
__device__ float g_fp[(long)MAXB * 128];

// fp16 activation scratch
__device__ fp16 g_pa[(long)MAXB * DM], g_ta[(long)MAXB * DM];
__device__ fp16 g_seqh[NT * DM];
__device__ fp16 g_qkvh[NT * 3 * DM];
__device__ fp16 g_ctxh[NT * DM];
__device__ fp16 g_xh[NT * DM];
__device__ fp16 g_hh[NT * 2 * DM];
__device__ fp16 g_zh[(long)MAXB * DM];

// fp16 weight scratch
constexpr int OW_P = 0, OW_T = 36864, OW_IN = 73728, OW_OUT = 184320;
constexpr int OW_F1 = 221184, OW_F2 = 294912, OW_CLS = 368640, OW_FP = 405504;
constexpr int OW_TOT = 430080;
__device__ fp16 g_whi[OW_TOT];

// ---------------- helpers ----------------
__device__ __forceinline__ uint32_t smem_u32(const void* p) {
    uint32_t a;
    asm("{ .reg .u64 t; cvta.to.shared.u64 t, %1; cvt.u32.u64 %0, t; }" : "=r"(a) : "l"(p));
    return a;
}
__device__ __forceinline__ void cp16(uint32_t dst, const void* src) {
    asm volatile("cp.async.cg.shared.global [%0], [%1], 16;" :: "r"(dst), "l"(src));
}
__device__ __forceinline__ void cp_commit() { asm volatile("cp.async.commit_group;"); }
__device__ __forceinline__ void cp_wait1() { asm volatile("cp.async.wait_group 1;"); }
__device__ __forceinline__ void ldsm_x4(uint32_t* r, uint32_t addr) {
    asm volatile("ldmatrix.sync.aligned.m8n8.x4.shared.b16 {%0,%1,%2,%3}, [%4];"
        : "=r"(r[0]), "=r"(r[1]), "=r"(r[2]), "=r"(r[3]) : "r"(addr));
}
__device__ __forceinline__ void mma16816(float* c, const uint32_t* a, const uint32_t* b) {
    asm volatile(
        "mma.sync.aligned.m16n8k16.row.col.f32.f16.f16.f32 "
        "{%0,%1,%2,%3}, {%4,%5,%6,%7}, {%8,%9}, {%0,%1,%2,%3};"
        : "+f"(c[0]), "+f"(c[1]), "+f"(c[2]), "+f"(c[3])
        : "r"(a[0]), "r"(a[1]), "r"(a[2]), "r"(a[3]), "r"(b[0]), "r"(b[1]));
}
__device__ __forceinline__ uint32_t pack_h2(float x, float y) {
    __half2 h = __floats2half2_rn(x, y);
    uint32_t u; memcpy(&u, &h, 4); return u;
}

__global__ void cvt_k(const float* __restrict__ s, fp16* __restrict__ o, long n)
{
    long i = 4L * (blockIdx.x * (long)blockDim.x + threadIdx.x);
    if (i >= n) return;
    float4 v = *(const float4*)(s + i);
    *(uint32_t*)(o + i) = pack_h2(v.x, v.y);
    *(uint32_t*)(o + i + 2) = pack_h2(v.z, v.w);
}

// ---------------------------------------------------------------------------
// fp16 HMMA GEMM (single-precision weights), 3-stage cp.async, ldmatrix.
// C = act(A . W^T + bias). Tile 128 x BN x 32k; 8 warps 4x2.
// Stage (u32): A[0,2560) B[2560,2560+BN*20). rows padded 20 u32.
// ---------------------------------------------------------------------------
template<int BN> struct StgSz { static constexpr int v = 2560 + BN * 20; };
constexpr int GEMM_SMEM96 = 3 * StgSz<96>::v * 4;   // 53760
constexpr int GEMM_SMEM64 = 3 * StgSz<64>::v * 4;   // 46080
constexpr int LN_SMEM = 2 * StgSz<192>::v * 4;      // 51200

template<int BN, bool RELU, bool WF32, bool WH16>
__global__ void __launch_bounds__(256)
tc_gemm(const fp16* __restrict__ Ag, int lda,
        const fp16* __restrict__ Whg,
        const float* __restrict__ bias,
        float* __restrict__ C, int ldc, int coff,
        fp16* __restrict__ S, int lds_, int scoff,
        int K)
{
    constexpr int NJ = BN / 16;
    constexpr int NJP = BN / 32;
    constexpr int STG = StgSz<BN>::v;

    extern __shared__ __align__(16) uint32_t sm32[];
    const uint32_t sbase = smem_u32(sm32);
    const int tid = threadIdx.x;
    const int wid = tid >> 5, lane = tid & 31;
    const int wr = wid >> 1, wc = wid & 1;
    const int m0 = blockIdx.y * 128, n0 = blockIdx.x * BN;

    float acc[2][NJ][4];
#pragma unroll
    for (int i = 0; i < 2; i++)
#pragma unroll
        for (int j = 0; j < NJ; j++)
#pragma unroll
            for (int q = 0; q < 4; q++) acc[i][j][q] = 0.f;

    const int lr = tid >> 2, seg = tid & 3;
    const int t7 = lane & 7, mi = lane >> 3;
    const int aRow0 = wr * 32 + t7 + (mi & 1) * 8;
    const int aCol  = (mi >> 1) * 4;
    const int bRow0 = wc * (BN / 2) + t7 + (mi >> 1) * 8;
    const int bCol  = (mi & 1) * 4;
    const int nc = K >> 5;

    auto issue = [&](int c) {
        const int k0 = c << 5;
        const uint32_t sb = sbase + (c % 3) * (STG * 4);
#pragma unroll
        for (int it = 0; it < 2; it++) {
            const int r = lr + it * 64;
            cp16(sb + (r * 20 + seg * 4) * 4, Ag + (size_t)(m0 + r) * lda + k0 + seg * 8);
        }
#pragma unroll
        for (int i = tid; i < BN * 4; i += 256) {
            const int r = i >> 2, sg = i & 3;
            cp16(sb + (2560 + r * 20 + sg * 4) * 4, Whg + (size_t)(n0 + r) * K + k0 + sg * 8);
        }
    };

    issue(0); cp_commit();
    if (nc > 1) { issue(1); cp_commit(); } else cp_commit();

    for (int c = 0; c < nc; c++) {
        cp_wait1();
        __syncthreads();
        if (c + 2 < nc) issue(c + 2);
        cp_commit();

        const uint32_t sb = sbase + (c % 3) * (STG * 4);
#pragma unroll
        for (int s = 0; s < 2; s++) {
            uint32_t ah[2][4], bh[NJ][2];
#pragma unroll
            for (int i = 0; i < 2; i++) {
                const uint32_t ai = (uint32_t)((aRow0 + i * 16) * 20 + s * 8 + aCol) * 4;
                ldsm_x4(ah[i], sb + ai);
            }
#pragma unroll
            for (int jp = 0; jp < NJP; jp++) {
                const uint32_t bi = (uint32_t)((bRow0 + jp * 16) * 20 + s * 8 + bCol) * 4;
                uint32_t tb[4];
                ldsm_x4(tb, sb + 2560 * 4 + bi);
                bh[2 * jp][0] = tb[0]; bh[2 * jp][1] = tb[1];
                bh[2 * jp + 1][0] = tb[2]; bh[2 * jp + 1][1] = tb[3];
            }
#pragma unroll
            for (int i = 0; i < 2; i++)
#pragma unroll
                for (int j = 0; j < NJ; j++)
                    mma16816(acc[i][j], ah[i], bh[j]);
        }
    }

    const int lg = lane >> 2, lq = lane & 3;
#pragma unroll
    for (int i = 0; i < 2; i++) {
        const int row = m0 + wr * 32 + i * 16 + lg;
#pragma unroll
        for (int j = 0; j < NJ; j++) {
            const int col = n0 + wc * (BN / 2) + j * 8 + 2 * lq;
            const float bx = bias[col], by = bias[col + 1];
            float2 v0, v1;
            v0.x = acc[i][j][0] + bx; v0.y = acc[i][j][1] + by;
            v1.x = acc[i][j][2] + bx; v1.y = acc[i][j][3] + by;
            if (RELU) {
                v0.x = fmaxf(v0.x, 0.f); v0.y = fmaxf(v0.y, 0.f);
                v1.x = fmaxf(v1.x, 0.f); v1.y = fmaxf(v1.y, 0.f);
            }
            if (WF32) {
                *(float2*)(C + (size_t)row * ldc + coff + col) = v0;
                *(float2*)(C + (size_t)(row + 8) * ldc + coff + col) = v1;
            }
            if (WH16) {
                *(uint32_t*)(S + (size_t)row * lds_ + scoff + col) = pack_h2(v0.x, v0.y);
                *(uint32_t*)(S + (size_t)(row + 8) * lds_ + scoff + col) = pack_h2(v1.x, v1.y);
            }
        }
    }
}

// ---------------------------------------------------------------------------
// Fused GEMM + residual + LayerNorm (single-precision weights). BN=192.
// MODE 1: x = LN1(RES + A.W^T + b) -> Xout fp32 + Xh fp16
// MODE 2: z = token-mean(LN2(RES + A.W^T + b)) -> Xh fp16
// ---------------------------------------------------------------------------
template<int MODE>
__global__ void __launch_bounds__(256)
gemm_ln(const fp16* __restrict__ Ag, int lda,
        const fp16* __restrict__ Whg,
        const float* __restrict__ bias,
        const float* __restrict__ RES,
        const float* __restrict__ gam, const float* __restrict__ bet,
        float* __restrict__ Xout, fp16* __restrict__ Xh,
        int K)
{
    constexpr int NJ = 12, NJP = 6;
    constexpr int STG = StgSz<192>::v;   // 6400 u32

    extern __shared__ __align__(16) uint32_t sm32[];
    __shared__ float rsum[128][2], rssq[128][2];
    const uint32_t sbase = smem_u32(sm32);
    const int tid = threadIdx.x;
    const int wid = tid >> 5, lane = tid & 31;
    const int wr = wid >> 1, wc = wid & 1;
    const int m0 = blockIdx.y * 128;

    float acc[2][NJ][4];
#pragma unroll
    for (int i = 0; i < 2; i++)
#pragma unroll
        for (int j = 0; j < NJ; j++)
#pragma unroll
            for (int q = 0; q < 4; q++) acc[i][j][q] = 0.f;

    const int lr = tid >> 2, seg = tid & 3;
    const int t7 = lane & 7, mi = lane >> 3;
    const int aRow0 = wr * 32 + t7 + (mi & 1) * 8;
    const int aCol  = (mi >> 1) * 4;
    const int bRow0 = wc * 96 + t7 + (mi >> 1) * 8;
    const int bCol  = (mi & 1) * 4;
    const int nc = K >> 5;

    auto issue = [&](int c, int buf) {
        const int k0 = c << 5;
        const uint32_t sb = sbase + buf * (STG * 4);
#pragma unroll
        for (int it = 0; it < 2; it++) {
            const int r = lr + it * 64;
            cp16(sb + (r * 20 + seg * 4) * 4, Ag + (size_t)(m0 + r) * lda + k0 + seg * 8);
        }
#pragma unroll
        for (int i = tid; i < 768; i += 256) {
            const int r = i >> 2, sg = i & 3;
            cp16(sb + (2560 + r * 20 + sg * 4) * 4, Whg + (size_t)r * K + k0 + sg * 8);
        }
    };

    issue(0, 0); cp_commit();
    for (int c = 0; c < nc; c++) {
        if (c + 1 < nc) issue(c + 1, (c + 1) & 1);
        cp_commit();
        cp_wait1();
        __syncthreads();

        const uint32_t sb = sbase + (c & 1) * (STG * 4);
#pragma unroll
        for (int s = 0; s < 2; s++) {
            uint32_t ah[2][4], bh[NJ][2];
#pragma unroll
            for (int i = 0; i < 2; i++) {
                const uint32_t ai = (uint32_t)((aRow0 + i * 16) * 20 + s * 8 + aCol) * 4;
                ldsm_x4(ah[i], sb + ai);
            }
#pragma unroll
            for (int jp = 0; jp < NJP; jp++) {
                const uint32_t bi = (uint32_t)((bRow0 + jp * 16) * 20 + s * 8 + bCol) * 4;
                uint32_t tb[4];
                ldsm_x4(tb, sb + 2560 * 4 + bi);
                bh[2 * jp][0] = tb[0]; bh[2 * jp][1] = tb[1];
                bh[2 * jp + 1][0] = tb[2]; bh[2 * jp + 1][1] = tb[3];
            }
#pragma unroll
            for (int i = 0; i < 2; i++)
#pragma unroll
                for (int j = 0; j < NJ; j++)
                    mma16816(acc[i][j], ah[i], bh[j]);
        }
        __syncthreads();
    }

    // fused epilogue: y = RES + acc + bias; per-row LN over 192 cols (2 warps)
    const int lg = lane >> 2, lq = lane & 3;
    float sP[4] = {0.f, 0.f, 0.f, 0.f}, ssP[4] = {0.f, 0.f, 0.f, 0.f};
#pragma unroll
    for (int i = 0; i < 2; i++) {
#pragma unroll
        for (int h = 0; h < 2; h++) {
            const int row = m0 + wr * 32 + i * 16 + h * 8 + lg;
            const float* rp = RES + (size_t)row * 192;
            const int slot = i * 2 + h;
#pragma unroll
            for (int j = 0; j < NJ; j++) {
                const int col = wc * 96 + j * 8 + 2 * lq;
                float2 r2 = *(const float2*)(rp + col);
                float y0 = acc[i][j][2 * h]     + bias[col]     + r2.x;
                float y1 = acc[i][j][2 * h + 1] + bias[col + 1] + r2.y;
                acc[i][j][2 * h] = y0; acc[i][j][2 * h + 1] = y1;
                sP[slot] += y0 + y1;
                ssP[slot] += y0 * y0 + y1 * y1;
            }
        }
    }
#pragma unroll
    for (int slot = 0; slot < 4; slot++) {
#pragma unroll
        for (int d = 1; d < 4; d <<= 1) {
            sP[slot]  += __shfl_xor_sync(0xffffffffu, sP[slot], d);
            ssP[slot] += __shfl_xor_sync(0xffffffffu, ssP[slot], d);
        }
    }
    if (lq == 0) {
#pragma unroll
        for (int i = 0; i < 2; i++)
#pragma unroll
            for (int h = 0; h < 2; h++) {
                const int lrow = wr * 32 + i * 16 + h * 8 + lg;
                rsum[lrow][wc] = sP[i * 2 + h];
                rssq[lrow][wc] = ssP[i * 2 + h];
            }
    }
    __syncthreads();

#pragma unroll
    for (int i = 0; i < 2; i++) {
#pragma unroll
        for (int h = 0; h < 2; h++) {
            const int lrow = wr * 32 + i * 16 + h * 8 + lg;
            const int row = m0 + lrow;
            const float tot = rsum[lrow][0] + rsum[lrow][1];
            const float tss = rssq[lrow][0] + rssq[lrow][1];
            const float mu = tot * (1.f / 192.f);
            const float rs = rsqrtf(tss * (1.f / 192.f) - mu * mu + 1e-5f);
#pragma unroll
            for (int j = 0; j < NJ; j++) {
                const int col = wc * 96 + j * 8 + 2 * lq;
                float v0 = (acc[i][j][2 * h]     - mu) * rs * gam[col]     + bet[col];
                float v1 = (acc[i][j][2 * h + 1] - mu) * rs * gam[col + 1] + bet[col + 1];
                if (MODE == 1) {
                    *(float2*)(Xout + (size_t)row * 192 + col) = make_float2(v0, v1);
                    *(uint32_t*)(Xh + (size_t)row * 192 + col) = pack_h2(v0, v1);
                } else {
                    float p0 = __shfl_xor_sync(0xffffffffu, v0, 4);
                    float p1 = __shfl_xor_sync(0xffffffffu, v1, 4);
                    if ((lg & 1) == 0) {
                        *(uint32_t*)(Xh + (size_t)(row >> 1) * 192 + col) =
                            pack_h2(0.5f * (v0 + p0), 0.5f * (v1 + p1));
                    }
                }
            }
        }
    }
}

// ---------------- elementwise ----------------
__global__ void attn_kernel(const fp16* __restrict__ qkv, fp16* __restrict__ ch, int B)
{
    const int w = (blockIdx.x * blockDim.x + threadIdx.x) >> 5;
    const int lane = threadIdx.x & 31;
    if (w >= B) return;
    const fp16* r0 = qkv + (size_t)(2 * w) * 576;
    const fp16* r1 = r0 + 576;
    const size_t o0r = (size_t)(2 * w) * 192, o1r = o0r + 192;
#pragma unroll
    for (int h = 0; h < 3; h++) {
        const int o = h * 64 + 2 * lane;
        float2 q0 = __half22float2(*(const __half2*)(r0 + o));
        float2 q1 = __half22float2(*(const __half2*)(r1 + o));
        float2 k0 = __half22float2(*(const __half2*)(r0 + 192 + o));
        float2 k1 = __half22float2(*(const __half2*)(r1 + 192 + o));
        float2 v0 = __half22float2(*(const __half2*)(r0 + 384 + o));
        float2 v1 = __half22float2(*(const __half2*)(r1 + 384 + o));
        float s00 = q0.x * k0.x + q0.y * k0.y;
        float s01 = q0.x * k1.x + q0.y * k1.y;
        float s10 = q1.x * k0.x + q1.y * k0.y;
        float s11 = q1.x * k1.x + q1.y * k1.y;
#pragma unroll
        for (int d = 16; d; d >>= 1) {
            s00 += __shfl_xor_sync(0xffffffffu, s00, d);
            s01 += __shfl_xor_sync(0xffffffffu, s01, d);
            s10 += __shfl_xor_sync(0xffffffffu, s10, d);
            s11 += __shfl_xor_sync(0xffffffffu, s11, d);
        }
        s00 *= 0.125f; s01 *= 0.125f; s10 *= 0.125f; s11 *= 0.125f;
        float m0 = fmaxf(s00, s01);
        float e00 = expf(s00 - m0), e01 = expf(s01 - m0);
        float i0 = 1.f / (e00 + e01);
        float m1 = fmaxf(s10, s11);
        float e10 = expf(s10 - m1), e11 = expf(s11 - m1);
        float i1 = 1.f / (e10 + e11);
        float a00 = e00 * i0, a01 = e01 * i0, a10 = e10 * i1, a11 = e11 * i1;
        *(uint32_t*)(ch + o0r + o) = pack_h2(a00 * v0.x + a01 * v1.x, a00 * v0.y + a01 * v1.y);
        *(uint32_t*)(ch + o1r + o) = pack_h2(a10 * v0.x + a11 * v1.x, a10 * v0.y + a11 * v1.y);
    }
}

__global__ void head_kernel(const float* __restrict__ C, const float* __restrict__ FPr,
                            const float* __restrict__ w2, const float* __restrict__ b2,
                            float* __restrict__ out, int B)
{
    const int w = (blockIdx.x * blockDim.x + threadIdx.x) >> 5;
    const int lane = threadIdx.x & 31;
    if (w >= B) return;
    const float* c = C + (size_t)w * 192;
    float l0 = 0.f, l1 = 0.f, l2 = 0.f;
#pragma unroll
    for (int j = 0; j < 6; j++) {
        const int idx = lane + 32 * j;
        const float cv = c[idx];
        l0 += cv * w2[idx];
        l1 += cv * w2[192 + idx];
        l2 += cv * w2[384 + idx];
    }
#pragma unroll
    for (int d = 16; d; d >>= 1) {
        l0 += __shfl_xor_sync(0xffffffffu, l0, d);
        l1 += __shfl_xor_sync(0xffffffffu, l1, d);
        l2 += __shfl_xor_sync(0xffffffffu, l2, d);
    }
    if (lane == 0) {
        out[w]         = 1.f / (1.f + expf(-(l0 + b2[0])));
        out[B + w]     = 1.f / (1.f + expf(-(l1 + b2[1])));
        out[2 * B + w] = 1.f / (1.f + expf(-(l2 + b2[2])));
    }
    const float* f = FPr + (size_t)w * 128;
    float fv[4], ss = 0.f;
#pragma unroll
    for (int j = 0; j < 4; j++) {
        fv[j] = f[lane + 32 * j];
        ss += fv[j] * fv[j];
    }
#pragma unroll
    for (int d = 16; d; d >>= 1) ss += __shfl_xor_sync(0xffffffffu, ss, d);
    const float sc = 1.f / fmaxf(sqrtf(ss), 1e-12f);
    float* fo = out + 3L * B + (size_t)w * 128;
#pragma unroll
    for (int j = 0; j < 4; j++) fo[lane + 32 * j] = fv[j] * sc;
}

// ---------------- host ----------------
static inline void dsym(void** p, const void* sym) { cudaGetSymbolAddress(p, sym); }

extern "C" void kernel_launch(void* const* d_in, const int* in_sizes, int n_in,
                              void* d_out, int out_size)
{
    const float* perc   = (const float*)d_in[0];
    const float* tech   = (const float*)d_in[1];
    const float* Wp     = (const float*)d_in[2];
    const float* bp     = (const float*)d_in[3];
    const float* Wt     = (const float*)d_in[4];
    const float* bt     = (const float*)d_in[5];
    const float* in_w   = (const float*)d_in[6];
    const float* in_b   = (const float*)d_in[7];
    const float* out_w  = (const float*)d_in[8];
    const float* out_b  = (const float*)d_in[9];
    const float* ffn_w1 = (const float*)d_in[10];
    const float* ffn_b1 = (const float*)d_in[11];
    const float* ffn_w2 = (const float*)d_in[12];
    const float* ffn_b2 = (const float*)d_in[13];
    const float* ln1_g  = (const float*)d_in[14];
    const float* ln1_b  = (const float*)d_in[15];
    const float* ln2_g  = (const float*)d_in[16];
    const float* ln2_b  = (const float*)d_in[17];
    const float* cls_w1 = (const float*)d_in[18];
    const float* cls_b1 = (const float*)d_in[19];
    const float* cls_w2 = (const float*)d_in[20];
    const float* cls_b2 = (const float*)d_in[21];
    const float* fp_w   = (const float*)d_in[22];
    const float* fp_b   = (const float*)d_in[23];

    int B = in_sizes[0] / DM;
    if (B > MAXB) B = MAXB;
    const int T = 2 * B;

    float *seq, *x, *c, *fp;
    dsym((void**)&seq, g_seq); dsym((void**)&x, g_x);
    dsym((void**)&c, g_c); dsym((void**)&fp, g_fp);

    fp16 *pa, *ta, *seqh, *qkvh, *ctxh, *xh, *hh, *zh, *whi;
    dsym((void**)&pa, g_pa); dsym((void**)&ta, g_ta);
    dsym((void**)&seqh, g_seqh); dsym((void**)&qkvh, g_qkvh);
    dsym((void**)&ctxh, g_ctxh);
    dsym((void**)&xh, g_xh); dsym((void**)&hh, g_hh); dsym((void**)&zh, g_zh);
    dsym((void**)&whi, g_whi);

    cudaFuncSetAttribute(tc_gemm<96, false, true,  true >, cudaFuncAttributeMaxDynamicSharedMemorySize, GEMM_SMEM96);
    cudaFuncSetAttribute(tc_gemm<96, false, false, true >, cudaFuncAttributeMaxDynamicSharedMemorySize, GEMM_SMEM96);
    cudaFuncSetAttribute(tc_gemm<96, true,  false, true >, cudaFuncAttributeMaxDynamicSharedMemorySize, GEMM_SMEM96);
    cudaFuncSetAttribute(tc_gemm<96, true,  true,  false>, cudaFuncAttributeMaxDynamicSharedMemorySize, GEMM_SMEM96);
    cudaFuncSetAttribute(tc_gemm<64, false, true,  false>, cudaFuncAttributeMaxDynamicSharedMemorySize, GEMM_SMEM64);
    cudaFuncSetAttribute(gemm_ln<1>, cudaFuncAttributeMaxDynamicSharedMemorySize, LN_SMEM);
    cudaFuncSetAttribute(gemm_ln<2>, cudaFuncAttributeMaxDynamicSharedMemorySize, LN_SMEM);

    float* out = (float*)d_out;

    auto cv = [&](const float* s, fp16* o, long n) {
        cvt_k<<<(int)((n / 4 + 255) / 256), 256>>>(s, o, n);
    };
    cv(Wp, whi + OW_P, 36864);
    cv(Wt, whi + OW_T, 36864);
    cv(in_w, whi + OW_IN, 110592);
    cv(out_w, whi + OW_OUT, 36864);
    cv(ffn_w1, whi + OW_F1, 73728);
    cv(ffn_w2, whi + OW_F2, 73728);
    cv(cls_w1, whi + OW_CLS, 36864);
    cv(fp_w, whi + OW_FP, 24576);
    cv(perc, pa, (long)B * 192);
    cv(tech, ta, (long)B * 192);

    // projections -> seq fp32 + fp16 (seq stored [B,384]; token view [2B,192])
    tc_gemm<96, false, true, true><<<dim3(2, B / 128), 256, GEMM_SMEM96>>>(
        pa, 192, whi + OW_P, bp, seq, 384, 0, seqh, 384, 0, 192);
    tc_gemm<96, false, true, true><<<dim3(2, B / 128), 256, GEMM_SMEM96>>>(
        ta, 192, whi + OW_T, bt, seq, 384, 192, seqh, 384, 192, 192);
    // qkv fp16: token view lda 192
    tc_gemm<96, false, false, true><<<dim3(6, T / 128), 256, GEMM_SMEM96>>>(
        seqh, 192, whi + OW_IN, in_b, nullptr, 0, 0, qkvh, 576, 0, 192);
    attn_kernel<<<(B + 7) / 8, 256>>>(qkvh, ctxh, B);
    // out-proj fused +seq residual + LN1 -> x fp32 + xh fp16
    gemm_ln<1><<<dim3(1, T / 128), 256, LN_SMEM>>>(
        ctxh, 192, whi + OW_OUT, out_b, seq, ln1_g, ln1_b, x, xh, 192);
    // ffn1
    tc_gemm<96, true, false, true><<<dim3(4, T / 128), 256, GEMM_SMEM96>>>(
        xh, 192, whi + OW_F1, ffn_b1, nullptr, 0, 0, hh, 384, 0, 192);
    // ffn2 fused +x residual + LN2 + token mean -> zh fp16
    gemm_ln<2><<<dim3(1, T / 128), 256, LN_SMEM>>>(
        hh, 384, whi + OW_F2, ffn_b2, x, ln2_g, ln2_b, nullptr, zh, 384);
    // heads
    tc_gemm<96, true, true, false><<<dim3(2, B / 128), 256, GEMM_SMEM96>>>(
        zh, 192, whi + OW_CLS, cls_b1, c, 192, 0, nullptr, 0, 0, 192);
    tc_gemm<64, false, true, false><<<dim3(2, B / 128), 256, GEMM_SMEM64>>>(
        zh, 192, whi + OW_FP, fp_b, fp, 128, 0, nullptr, 0, 0, 192);
    head_kernel<<<(B + 7) / 8, 256>>>(c, fp, cls_w2, cls_b2, out, B);
}

// round 14
// speedup vs baseline: 4.3734x; 1.0288x over previous
#include <cuda_runtime.h>
#include <cuda_fp16.h>
#include <stdint.h>
#include <string.h>
#include <math.h>

typedef __half fp16;

constexpr int DM = 192;
constexpr int MAXB = 65536;
constexpr long NT = 2L * MAXB;

// fp32 scratch
__device__ float g_seq[NT * DM];
__device__ float g_x[NT * DM];

// fp16 activation scratch
__device__ fp16 g_pa[(long)MAXB * DM], g_ta[(long)MAXB * DM];
__device__ fp16 g_seqh[NT * DM];
__device__ fp16 g_qkvh[NT * 3 * DM];
__device__ fp16 g_ctxh[NT * DM];
__device__ fp16 g_xh[NT * DM];
__device__ fp16 g_hh[NT * 2 * DM];
__device__ fp16 g_zh[(long)MAXB * DM];

// fp16 weight scratch
constexpr int OW_P = 0, OW_T = 36864, OW_IN = 73728, OW_OUT = 184320;
constexpr int OW_F1 = 221184, OW_F2 = 294912, OW_CLS = 368640, OW_FP = 405504;
constexpr int OW_TOT = 430080;
__device__ fp16 g_whi[OW_TOT];

// ---------------- helpers ----------------
__device__ __forceinline__ uint32_t smem_u32(const void* p) {
    uint32_t a;
    asm("{ .reg .u64 t; cvta.to.shared.u64 t, %1; cvt.u32.u64 %0, t; }" : "=r"(a) : "l"(p));
    return a;
}
__device__ __forceinline__ void cp16(uint32_t dst, const void* src) {
    asm volatile("cp.async.cg.shared.global [%0], [%1], 16;" :: "r"(dst), "l"(src));
}
__device__ __forceinline__ void cp_commit() { asm volatile("cp.async.commit_group;"); }
__device__ __forceinline__ void cp_wait1() { asm volatile("cp.async.wait_group 1;"); }
__device__ __forceinline__ void ldsm_x4(uint32_t* r, uint32_t addr) {
    asm volatile("ldmatrix.sync.aligned.m8n8.x4.shared.b16 {%0,%1,%2,%3}, [%4];"
        : "=r"(r[0]), "=r"(r[1]), "=r"(r[2]), "=r"(r[3]) : "r"(addr));
}
__device__ __forceinline__ void mma16816(float* c, const uint32_t* a, const uint32_t* b) {
    asm volatile(
        "mma.sync.aligned.m16n8k16.row.col.f32.f16.f16.f32 "
        "{%0,%1,%2,%3}, {%4,%5,%6,%7}, {%8,%9}, {%0,%1,%2,%3};"
        : "+f"(c[0]), "+f"(c[1]), "+f"(c[2]), "+f"(c[3])
        : "r"(a[0]), "r"(a[1]), "r"(a[2]), "r"(a[3]), "r"(b[0]), "r"(b[1]));
}
__device__ __forceinline__ uint32_t pack_h2(float x, float y) {
    __half2 h = __floats2half2_rn(x, y);
    uint32_t u; memcpy(&u, &h, 4); return u;
}

__global__ void cvt_k(const float* __restrict__ s, fp16* __restrict__ o, long n)
{
    long i = 4L * (blockIdx.x * (long)blockDim.x + threadIdx.x);
    if (i >= n) return;
    float4 v = *(const float4*)(s + i);
    *(uint32_t*)(o + i) = pack_h2(v.x, v.y);
    *(uint32_t*)(o + i + 2) = pack_h2(v.z, v.w);
}

// all 8 weight tensors in one launch
__global__ void cvt_weights(const float* __restrict__ wp, const float* __restrict__ wt,
                            const float* __restrict__ inw, const float* __restrict__ ow,
                            const float* __restrict__ f1, const float* __restrict__ f2,
                            const float* __restrict__ cls, const float* __restrict__ fpw,
                            fp16* __restrict__ dst)
{
    long i = 4L * (blockIdx.x * (long)blockDim.x + threadIdx.x);
    if (i >= OW_TOT) return;
    const float* src;
    long off;
    if      (i < OW_T)   { src = wp;  off = i - OW_P; }
    else if (i < OW_IN)  { src = wt;  off = i - OW_T; }
    else if (i < OW_OUT) { src = inw; off = i - OW_IN; }
    else if (i < OW_F1)  { src = ow;  off = i - OW_OUT; }
    else if (i < OW_F2)  { src = f1;  off = i - OW_F1; }
    else if (i < OW_CLS) { src = f2;  off = i - OW_F2; }
    else if (i < OW_FP)  { src = cls; off = i - OW_CLS; }
    else                 { src = fpw; off = i - OW_FP; }
    float4 v = *(const float4*)(src + off);
    *(uint32_t*)(dst + i) = pack_h2(v.x, v.y);
    *(uint32_t*)(dst + i + 2) = pack_h2(v.z, v.w);
}

// ---------------------------------------------------------------------------
// fp16 HMMA GEMM, 3-stage cp.async, ldmatrix. (unchanged verified core)
// ---------------------------------------------------------------------------
template<int BN> struct StgSz { static constexpr int v = 2560 + BN * 20; };
constexpr int GEMM_SMEM96 = 3 * StgSz<96>::v * 4;
constexpr int LN_SMEM  = 2 * StgSz<192>::v * 4;
constexpr int FP_SMEM  = 2 * StgSz<128>::v * 4;

template<int BN, bool RELU, bool WF32, bool WH16>
__global__ void __launch_bounds__(256)
tc_gemm(const fp16* __restrict__ Ag, int lda,
        const fp16* __restrict__ Whg,
        const float* __restrict__ bias,
        float* __restrict__ C, int ldc, int coff,
        fp16* __restrict__ S, int lds_, int scoff,
        int K)
{
    constexpr int NJ = BN / 16;
    constexpr int NJP = BN / 32;
    constexpr int STG = StgSz<BN>::v;

    extern __shared__ __align__(16) uint32_t sm32[];
    const uint32_t sbase = smem_u32(sm32);
    const int tid = threadIdx.x;
    const int wid = tid >> 5, lane = tid & 31;
    const int wr = wid >> 1, wc = wid & 1;
    const int m0 = blockIdx.y * 128, n0 = blockIdx.x * BN;

    float acc[2][NJ][4];
#pragma unroll
    for (int i = 0; i < 2; i++)
#pragma unroll
        for (int j = 0; j < NJ; j++)
#pragma unroll
            for (int q = 0; q < 4; q++) acc[i][j][q] = 0.f;

    const int lr = tid >> 2, seg = tid & 3;
    const int t7 = lane & 7, mi = lane >> 3;
    const int aRow0 = wr * 32 + t7 + (mi & 1) * 8;
    const int aCol  = (mi >> 1) * 4;
    const int bRow0 = wc * (BN / 2) + t7 + (mi >> 1) * 8;
    const int bCol  = (mi & 1) * 4;
    const int nc = K >> 5;

    auto issue = [&](int c) {
        const int k0 = c << 5;
        const uint32_t sb = sbase + (c % 3) * (STG * 4);
#pragma unroll
        for (int it = 0; it < 2; it++) {
            const int r = lr + it * 64;
            cp16(sb + (r * 20 + seg * 4) * 4, Ag + (size_t)(m0 + r) * lda + k0 + seg * 8);
        }
#pragma unroll
        for (int i = tid; i < BN * 4; i += 256) {
            const int r = i >> 2, sg = i & 3;
            cp16(sb + (2560 + r * 20 + sg * 4) * 4, Whg + (size_t)(n0 + r) * K + k0 + sg * 8);
        }
    };

    issue(0); cp_commit();
    if (nc > 1) { issue(1); cp_commit(); } else cp_commit();

    for (int c = 0; c < nc; c++) {
        cp_wait1();
        __syncthreads();
        if (c + 2 < nc) issue(c + 2);
        cp_commit();

        const uint32_t sb = sbase + (c % 3) * (STG * 4);
#pragma unroll
        for (int s = 0; s < 2; s++) {
            uint32_t ah[2][4], bh[NJ][2];
#pragma unroll
            for (int i = 0; i < 2; i++) {
                const uint32_t ai = (uint32_t)((aRow0 + i * 16) * 20 + s * 8 + aCol) * 4;
                ldsm_x4(ah[i], sb + ai);
            }
#pragma unroll
            for (int jp = 0; jp < NJP; jp++) {
                const uint32_t bi = (uint32_t)((bRow0 + jp * 16) * 20 + s * 8 + bCol) * 4;
                uint32_t tb[4];
                ldsm_x4(tb, sb + 2560 * 4 + bi);
                bh[2 * jp][0] = tb[0]; bh[2 * jp][1] = tb[1];
                bh[2 * jp + 1][0] = tb[2]; bh[2 * jp + 1][1] = tb[3];
            }
#pragma unroll
            for (int i = 0; i < 2; i++)
#pragma unroll
                for (int j = 0; j < NJ; j++)
                    mma16816(acc[i][j], ah[i], bh[j]);
        }
    }

    const int lg = lane >> 2, lq = lane & 3;
#pragma unroll
    for (int i = 0; i < 2; i++) {
        const int row = m0 + wr * 32 + i * 16 + lg;
#pragma unroll
        for (int j = 0; j < NJ; j++) {
            const int col = n0 + wc * (BN / 2) + j * 8 + 2 * lq;
            const float bx = bias[col], by = bias[col + 1];
            float2 v0, v1;
            v0.x = acc[i][j][0] + bx; v0.y = acc[i][j][1] + by;
            v1.x = acc[i][j][2] + bx; v1.y = acc[i][j][3] + by;
            if (RELU) {
                v0.x = fmaxf(v0.x, 0.f); v0.y = fmaxf(v0.y, 0.f);
                v1.x = fmaxf(v1.x, 0.f); v1.y = fmaxf(v1.y, 0.f);
            }
            if (WF32) {
                *(float2*)(C + (size_t)row * ldc + coff + col) = v0;
                *(float2*)(C + (size_t)(row + 8) * ldc + coff + col) = v1;
            }
            if (WH16) {
                *(uint32_t*)(S + (size_t)row * lds_ + scoff + col) = pack_h2(v0.x, v0.y);
                *(uint32_t*)(S + (size_t)(row + 8) * lds_ + scoff + col) = pack_h2(v1.x, v1.y);
            }
        }
    }
}

// 2-stage BN=192 mainloop shared by the fused kernels (macro to keep one copy)
#define MAINLOOP_192(AG, LDA, WHG, KK)                                           \
    const int lr = tid >> 2, seg = tid & 3;                                      \
    const int t7 = lane & 7, mi = lane >> 3;                                     \
    const int aRow0 = wr * 32 + t7 + (mi & 1) * 8;                               \
    const int aCol  = (mi >> 1) * 4;                                             \
    const int bRow0 = wc * (BNV / 2) + t7 + (mi >> 1) * 8;                       \
    const int bCol  = (mi & 1) * 4;                                              \
    const int nc = (KK) >> 5;                                                    \
    auto issue = [&](int c, int buf) {                                           \
        const int k0 = c << 5;                                                   \
        const uint32_t sb = sbase + buf * (STGV * 4);                            \
        for (int it = 0; it < 2; it++) {                                         \
            const int r = lr + it * 64;                                          \
            cp16(sb + (r * 20 + seg * 4) * 4,                                    \
                 (AG) + (size_t)(m0 + r) * (LDA) + k0 + seg * 8);                \
        }                                                                        \
        for (int i = tid; i < BNV * 4; i += 256) {                               \
            const int r = i >> 2, sg = i & 3;                                    \
            cp16(sb + (2560 + r * 20 + sg * 4) * 4,                              \
                 (WHG) + (size_t)r * (KK) + k0 + sg * 8);                        \
        }                                                                        \
    };                                                                           \
    issue(0, 0); cp_commit();                                                    \
    for (int c = 0; c < nc; c++) {                                               \
        if (c + 1 < nc) issue(c + 1, (c + 1) & 1);                               \
        cp_commit(); cp_wait1(); __syncthreads();                                \
        const uint32_t sb = sbase + (c & 1) * (STGV * 4);                        \
        for (int s = 0; s < 2; s++) {                                            \
            uint32_t ah[2][4], bh[NJV][2];                                       \
            for (int i = 0; i < 2; i++) {                                        \
                const uint32_t ai =                                              \
                    (uint32_t)((aRow0 + i * 16) * 20 + s * 8 + aCol) * 4;        \
                ldsm_x4(ah[i], sb + ai);                                         \
            }                                                                    \
            for (int jp = 0; jp < NJV / 2; jp++) {                               \
                const uint32_t bi =                                              \
                    (uint32_t)((bRow0 + jp * 16) * 20 + s * 8 + bCol) * 4;       \
                uint32_t tb[4];                                                  \
                ldsm_x4(tb, sb + 2560 * 4 + bi);                                 \
                bh[2 * jp][0] = tb[0]; bh[2 * jp][1] = tb[1];                    \
                bh[2 * jp + 1][0] = tb[2]; bh[2 * jp + 1][1] = tb[3];            \
            }                                                                    \
            for (int i = 0; i < 2; i++)                                          \
                for (int j = 0; j < NJV; j++)                                    \
                    mma16816(acc[i][j], ah[i], bh[j]);                           \
        }                                                                        \
        __syncthreads();                                                         \
    }

// ---------------------------------------------------------------------------
// Fused GEMM + residual + LayerNorm (as R13, verified).
// ---------------------------------------------------------------------------
template<int MODE>
__global__ void __launch_bounds__(256)
gemm_ln(const fp16* __restrict__ Ag, int lda,
        const fp16* __restrict__ Whg,
        const float* __restrict__ bias,
        const float* __restrict__ RES,
        const float* __restrict__ gam, const float* __restrict__ bet,
        float* __restrict__ Xout, fp16* __restrict__ Xh,
        int K)
{
    constexpr int BNV = 192, NJV = 12;
    constexpr int STGV = StgSz<192>::v;
    extern __shared__ __align__(16) uint32_t sm32[];
    __shared__ float rsum[128][2], rssq[128][2];
    const uint32_t sbase = smem_u32(sm32);
    const int tid = threadIdx.x;
    const int wid = tid >> 5, lane = tid & 31;
    const int wr = wid >> 1, wc = wid & 1;
    const int m0 = blockIdx.y * 128;

    float acc[2][NJV][4];
#pragma unroll
    for (int i = 0; i < 2; i++)
#pragma unroll
        for (int j = 0; j < NJV; j++)
#pragma unroll
            for (int q = 0; q < 4; q++) acc[i][j][q] = 0.f;

    MAINLOOP_192(Ag, lda, Whg, K)

    const int lg = lane >> 2, lq = lane & 3;
    float sP[4] = {0.f, 0.f, 0.f, 0.f}, ssP[4] = {0.f, 0.f, 0.f, 0.f};
#pragma unroll
    for (int i = 0; i < 2; i++)
#pragma unroll
        for (int h = 0; h < 2; h++) {
            const int row = m0 + wr * 32 + i * 16 + h * 8 + lg;
            const float* rp = RES + (size_t)row * 192;
            const int slot = i * 2 + h;
#pragma unroll
            for (int j = 0; j < NJV; j++) {
                const int col = wc * 96 + j * 8 + 2 * lq;
                float2 r2 = *(const float2*)(rp + col);
                float y0 = acc[i][j][2 * h]     + bias[col]     + r2.x;
                float y1 = acc[i][j][2 * h + 1] + bias[col + 1] + r2.y;
                acc[i][j][2 * h] = y0; acc[i][j][2 * h + 1] = y1;
                sP[slot] += y0 + y1;
                ssP[slot] += y0 * y0 + y1 * y1;
            }
        }
#pragma unroll
    for (int slot = 0; slot < 4; slot++)
#pragma unroll
        for (int d = 1; d < 4; d <<= 1) {
            sP[slot]  += __shfl_xor_sync(0xffffffffu, sP[slot], d);
            ssP[slot] += __shfl_xor_sync(0xffffffffu, ssP[slot], d);
        }
    if (lq == 0) {
#pragma unroll
        for (int i = 0; i < 2; i++)
#pragma unroll
            for (int h = 0; h < 2; h++) {
                const int lrow = wr * 32 + i * 16 + h * 8 + lg;
                rsum[lrow][wc] = sP[i * 2 + h];
                rssq[lrow][wc] = ssP[i * 2 + h];
            }
    }
    __syncthreads();

#pragma unroll
    for (int i = 0; i < 2; i++)
#pragma unroll
        for (int h = 0; h < 2; h++) {
            const int lrow = wr * 32 + i * 16 + h * 8 + lg;
            const int row = m0 + lrow;
            const float mu = (rsum[lrow][0] + rsum[lrow][1]) * (1.f / 192.f);
            const float rs = rsqrtf((rssq[lrow][0] + rssq[lrow][1]) * (1.f / 192.f)
                                    - mu * mu + 1e-5f);
#pragma unroll
            for (int j = 0; j < NJV; j++) {
                const int col = wc * 96 + j * 8 + 2 * lq;
                float v0 = (acc[i][j][2 * h]     - mu) * rs * gam[col]     + bet[col];
                float v1 = (acc[i][j][2 * h + 1] - mu) * rs * gam[col + 1] + bet[col + 1];
                if (MODE == 1) {
                    *(float2*)(Xout + (size_t)row * 192 + col) = make_float2(v0, v1);
                    *(uint32_t*)(Xh + (size_t)row * 192 + col) = pack_h2(v0, v1);
                } else {
                    float p0 = __shfl_xor_sync(0xffffffffu, v0, 4);
                    float p1 = __shfl_xor_sync(0xffffffffu, v1, 4);
                    if ((lg & 1) == 0) {
                        *(uint32_t*)(Xh + (size_t)(row >> 1) * 192 + col) =
                            pack_h2(0.5f * (v0 + p0), 0.5f * (v1 + p1));
                    }
                }
            }
        }
}

// ---------------------------------------------------------------------------
// Fused classifier: c = relu(z.W1^T + b1); logits = c.w2^T + b2; sigmoid -> out
// BN=192, one CTA per 128 rows. out[k*B + row], k=0..2.
// ---------------------------------------------------------------------------
__global__ void __launch_bounds__(256)
gemm_cls(const fp16* __restrict__ Ag,
         const fp16* __restrict__ Whg,
         const float* __restrict__ bias,
         const float* __restrict__ w2, const float* __restrict__ b2,
         float* __restrict__ out, int Bn)
{
    constexpr int BNV = 192, NJV = 12;
    constexpr int STGV = StgSz<192>::v;
    extern __shared__ __align__(16) uint32_t sm32[];
    __shared__ float lsum[128][2][3];
    const uint32_t sbase = smem_u32(sm32);
    const int tid = threadIdx.x;
    const int wid = tid >> 5, lane = tid & 31;
    const int wr = wid >> 1, wc = wid & 1;
    const int m0 = blockIdx.y * 128;
    const int lda = 192, K = 192;

    float acc[2][NJV][4];
#pragma unroll
    for (int i = 0; i < 2; i++)
#pragma unroll
        for (int j = 0; j < NJV; j++)
#pragma unroll
            for (int q = 0; q < 4; q++) acc[i][j][q] = 0.f;

    MAINLOOP_192(Ag, lda, Whg, K)

    const int lg = lane >> 2, lq = lane & 3;
    float lp[4][3];
#pragma unroll
    for (int s2 = 0; s2 < 4; s2++) { lp[s2][0] = 0.f; lp[s2][1] = 0.f; lp[s2][2] = 0.f; }
#pragma unroll
    for (int i = 0; i < 2; i++)
#pragma unroll
        for (int h = 0; h < 2; h++) {
            const int slot = i * 2 + h;
#pragma unroll
            for (int j = 0; j < NJV; j++) {
                const int col = wc * 96 + j * 8 + 2 * lq;
                float c0 = fmaxf(acc[i][j][2 * h]     + bias[col], 0.f);
                float c1 = fmaxf(acc[i][j][2 * h + 1] + bias[col + 1], 0.f);
#pragma unroll
                for (int k = 0; k < 3; k++)
                    lp[slot][k] += c0 * w2[k * 192 + col] + c1 * w2[k * 192 + col + 1];
            }
        }
#pragma unroll
    for (int slot = 0; slot < 4; slot++)
#pragma unroll
        for (int k = 0; k < 3; k++)
#pragma unroll
            for (int d = 1; d < 4; d <<= 1)
                lp[slot][k] += __shfl_xor_sync(0xffffffffu, lp[slot][k], d);
    if (lq == 0) {
#pragma unroll
        for (int i = 0; i < 2; i++)
#pragma unroll
            for (int h = 0; h < 2; h++) {
                const int lrow = wr * 32 + i * 16 + h * 8 + lg;
#pragma unroll
                for (int k = 0; k < 3; k++) lsum[lrow][wc][k] = lp[i * 2 + h][k];
            }
    }
    __syncthreads();
    if (lq == 0 && wc == 0) {
#pragma unroll
        for (int i = 0; i < 2; i++)
#pragma unroll
            for (int h = 0; h < 2; h++) {
                const int lrow = wr * 32 + i * 16 + h * 8 + lg;
                const int row = m0 + lrow;
#pragma unroll
                for (int k = 0; k < 3; k++) {
                    float l = lsum[lrow][0][k] + lsum[lrow][1][k] + b2[k];
                    out[(size_t)k * Bn + row] = 1.f / (1.f + expf(-l));
                }
            }
    }
}

// ---------------------------------------------------------------------------
// Fused fingerprint: fpr = z.Wf^T + bf [B,128]; row-normalize -> out + 3B
// BN=128, one CTA per 128 rows.
// ---------------------------------------------------------------------------
__global__ void __launch_bounds__(256)
gemm_fp(const fp16* __restrict__ Ag,
        const fp16* __restrict__ Whg,
        const float* __restrict__ bias,
        float* __restrict__ out, int Bn)
{
    constexpr int BNV = 128, NJV = 8;
    constexpr int STGV = StgSz<128>::v;
    extern __shared__ __align__(16) uint32_t sm32[];
    __shared__ float rssq[128][2];
    const uint32_t sbase = smem_u32(sm32);
    const int tid = threadIdx.x;
    const int wid = tid >> 5, lane = tid & 31;
    const int wr = wid >> 1, wc = wid & 1;
    const int m0 = blockIdx.y * 128;
    const int lda = 192, K = 192;

    float acc[2][NJV][4];
#pragma unroll
    for (int i = 0; i < 2; i++)
#pragma unroll
        for (int j = 0; j < NJV; j++)
#pragma unroll
            for (int q = 0; q < 4; q++) acc[i][j][q] = 0.f;

    MAINLOOP_192(Ag, lda, Whg, K)

    const int lg = lane >> 2, lq = lane & 3;
    float ssP[4] = {0.f, 0.f, 0.f, 0.f};
#pragma unroll
    for (int i = 0; i < 2; i++)
#pragma unroll
        for (int h = 0; h < 2; h++) {
            const int slot = i * 2 + h;
#pragma unroll
            for (int j = 0; j < NJV; j++) {
                const int col = wc * 64 + j * 8 + 2 * lq;
                float v0 = acc[i][j][2 * h]     + bias[col];
                float v1 = acc[i][j][2 * h + 1] + bias[col + 1];
                acc[i][j][2 * h] = v0; acc[i][j][2 * h + 1] = v1;
                ssP[slot] += v0 * v0 + v1 * v1;
            }
        }
#pragma unroll
    for (int slot = 0; slot < 4; slot++)
#pragma unroll
        for (int d = 1; d < 4; d <<= 1)
            ssP[slot] += __shfl_xor_sync(0xffffffffu, ssP[slot], d);
    if (lq == 0) {
#pragma unroll
        for (int i = 0; i < 2; i++)
#pragma unroll
            for (int h = 0; h < 2; h++)
                rssq[wr * 32 + i * 16 + h * 8 + lg][wc] = ssP[i * 2 + h];
    }
    __syncthreads();

#pragma unroll
    for (int i = 0; i < 2; i++)
#pragma unroll
        for (int h = 0; h < 2; h++) {
            const int lrow = wr * 32 + i * 16 + h * 8 + lg;
            const int row = m0 + lrow;
            const float nrm = sqrtf(rssq[lrow][0] + rssq[lrow][1]);
            const float sc = 1.f / fmaxf(nrm, 1e-12f);
            float* op = out + 3L * Bn + (size_t)row * 128;
#pragma unroll
            for (int j = 0; j < NJV; j++) {
                const int col = wc * 64 + j * 8 + 2 * lq;
                *(float2*)(op + col) =
                    make_float2(acc[i][j][2 * h] * sc, acc[i][j][2 * h + 1] * sc);
            }
        }
}

// ---------------- attention ----------------
__global__ void attn_kernel(const fp16* __restrict__ qkv, fp16* __restrict__ ch, int B)
{
    const int w = (blockIdx.x * blockDim.x + threadIdx.x) >> 5;
    const int lane = threadIdx.x & 31;
    if (w >= B) return;
    const fp16* r0 = qkv + (size_t)(2 * w) * 576;
    const fp16* r1 = r0 + 576;
    const size_t o0r = (size_t)(2 * w) * 192, o1r = o0r + 192;
#pragma unroll
    for (int h = 0; h < 3; h++) {
        const int o = h * 64 + 2 * lane;
        float2 q0 = __half22float2(*(const __half2*)(r0 + o));
        float2 q1 = __half22float2(*(const __half2*)(r1 + o));
        float2 k0 = __half22float2(*(const __half2*)(r0 + 192 + o));
        float2 k1 = __half22float2(*(const __half2*)(r1 + 192 + o));
        float2 v0 = __half22float2(*(const __half2*)(r0 + 384 + o));
        float2 v1 = __half22float2(*(const __half2*)(r1 + 384 + o));
        float s00 = q0.x * k0.x + q0.y * k0.y;
        float s01 = q0.x * k1.x + q0.y * k1.y;
        float s10 = q1.x * k0.x + q1.y * k0.y;
        float s11 = q1.x * k1.x + q1.y * k1.y;
#pragma unroll
        for (int d = 16; d; d >>= 1) {
            s00 += __shfl_xor_sync(0xffffffffu, s00, d);
            s01 += __shfl_xor_sync(0xffffffffu, s01, d);
            s10 += __shfl_xor_sync(0xffffffffu, s10, d);
            s11 += __shfl_xor_sync(0xffffffffu, s11, d);
        }
        s00 *= 0.125f; s01 *= 0.125f; s10 *= 0.125f; s11 *= 0.125f;
        float m0 = fmaxf(s00, s01);
        float e00 = expf(s00 - m0), e01 = expf(s01 - m0);
        float i0 = 1.f / (e00 + e01);
        float m1 = fmaxf(s10, s11);
        float e10 = expf(s10 - m1), e11 = expf(s11 - m1);
        float i1 = 1.f / (e10 + e11);
        float a00 = e00 * i0, a01 = e01 * i0, a10 = e10 * i1, a11 = e11 * i1;
        *(uint32_t*)(ch + o0r + o) = pack_h2(a00 * v0.x + a01 * v1.x, a00 * v0.y + a01 * v1.y);
        *(uint32_t*)(ch + o1r + o) = pack_h2(a10 * v0.x + a11 * v1.x, a10 * v0.y + a11 * v1.y);
    }
}

// ---------------- host ----------------
static inline void dsym(void** p, const void* sym) { cudaGetSymbolAddress(p, sym); }

extern "C" void kernel_launch(void* const* d_in, const int* in_sizes, int n_in,
                              void* d_out, int out_size)
{
    const float* perc   = (const float*)d_in[0];
    const float* tech   = (const float*)d_in[1];
    const float* Wp     = (const float*)d_in[2];
    const float* bp     = (const float*)d_in[3];
    const float* Wt     = (const float*)d_in[4];
    const float* bt     = (const float*)d_in[5];
    const float* in_w   = (const float*)d_in[6];
    const float* in_b   = (const float*)d_in[7];
    const float* out_w  = (const float*)d_in[8];
    const float* out_b  = (const float*)d_in[9];
    const float* ffn_w1 = (const float*)d_in[10];
    const float* ffn_b1 = (const float*)d_in[11];
    const float* ffn_w2 = (const float*)d_in[12];
    const float* ffn_b2 = (const float*)d_in[13];
    const float* ln1_g  = (const float*)d_in[14];
    const float* ln1_b  = (const float*)d_in[15];
    const float* ln2_g  = (const float*)d_in[16];
    const float* ln2_b  = (const float*)d_in[17];
    const float* cls_w1 = (const float*)d_in[18];
    const float* cls_b1 = (const float*)d_in[19];
    const float* cls_w2 = (const float*)d_in[20];
    const float* cls_b2 = (const float*)d_in[21];
    const float* fp_w   = (const float*)d_in[22];
    const float* fp_b   = (const float*)d_in[23];

    int B = in_sizes[0] / DM;
    if (B > MAXB) B = MAXB;
    const int T = 2 * B;

    float *seq, *x;
    dsym((void**)&seq, g_seq); dsym((void**)&x, g_x);

    fp16 *pa, *ta, *seqh, *qkvh, *ctxh, *xh, *hh, *zh, *whi;
    dsym((void**)&pa, g_pa); dsym((void**)&ta, g_ta);
    dsym((void**)&seqh, g_seqh); dsym((void**)&qkvh, g_qkvh);
    dsym((void**)&ctxh, g_ctxh);
    dsym((void**)&xh, g_xh); dsym((void**)&hh, g_hh); dsym((void**)&zh, g_zh);
    dsym((void**)&whi, g_whi);

    cudaFuncSetAttribute(tc_gemm<96, false, true,  true >, cudaFuncAttributeMaxDynamicSharedMemorySize, GEMM_SMEM96);
    cudaFuncSetAttribute(tc_gemm<96, false, false, true >, cudaFuncAttributeMaxDynamicSharedMemorySize, GEMM_SMEM96);
    cudaFuncSetAttribute(tc_gemm<96, true,  false, true >, cudaFuncAttributeMaxDynamicSharedMemorySize, GEMM_SMEM96);
    cudaFuncSetAttribute(gemm_ln<1>, cudaFuncAttributeMaxDynamicSharedMemorySize, LN_SMEM);
    cudaFuncSetAttribute(gemm_ln<2>, cudaFuncAttributeMaxDynamicSharedMemorySize, LN_SMEM);
    cudaFuncSetAttribute(gemm_cls, cudaFuncAttributeMaxDynamicSharedMemorySize, LN_SMEM);
    cudaFuncSetAttribute(gemm_fp,  cudaFuncAttributeMaxDynamicSharedMemorySize, FP_SMEM);

    float* out = (float*)d_out;

    cvt_weights<<<(OW_TOT / 4 + 255) / 256, 256>>>(
        Wp, Wt, in_w, out_w, ffn_w1, ffn_w2, cls_w1, fp_w, whi);
    cvt_k<<<(int)(((long)B * 192 / 4 + 255) / 256), 256>>>(perc, pa, (long)B * 192);
    cvt_k<<<(int)(((long)B * 192 / 4 + 255) / 256), 256>>>(tech, ta, (long)B * 192);

    // projections -> seq fp32 + fp16 (seq stored [B,384]; token view [2B,192])
    tc_gemm<96, false, true, true><<<dim3(2, B / 128), 256, GEMM_SMEM96>>>(
        pa, 192, whi + OW_P, bp, seq, 384, 0, seqh, 384, 0, 192);
    tc_gemm<96, false, true, true><<<dim3(2, B / 128), 256, GEMM_SMEM96>>>(
        ta, 192, whi + OW_T, bt, seq, 384, 192, seqh, 384, 192, 192);
    // qkv fp16: token view lda 192
    tc_gemm<96, false, false, true><<<dim3(6, T / 128), 256, GEMM_SMEM96>>>(
        seqh, 192, whi + OW_IN, in_b, nullptr, 0, 0, qkvh, 576, 0, 192);
    attn_kernel<<<(B + 7) / 8, 256>>>(qkvh, ctxh, B);
    // out-proj fused +seq residual + LN1
    gemm_ln<1><<<dim3(1, T / 128), 256, LN_SMEM>>>(
        ctxh, 192, whi + OW_OUT, out_b, seq, ln1_g, ln1_b, x, xh, 192);
    // ffn1
    tc_gemm<96, true, false, true><<<dim3(4, T / 128), 256, GEMM_SMEM96>>>(
        xh, 192, whi + OW_F1, ffn_b1, nullptr, 0, 0, hh, 384, 0, 192);
    // ffn2 fused +x residual + LN2 + token mean
    gemm_ln<2><<<dim3(1, T / 128), 256, LN_SMEM>>>(
        hh, 384, whi + OW_F2, ffn_b2, x, ln2_g, ln2_b, nullptr, zh, 384);
    // fused heads -> out
    gemm_cls<<<dim3(1, B / 128), 256, LN_SMEM>>>(
        zh, whi + OW_CLS, cls_b1, cls_w2, cls_b2, out, B);
    gemm_fp<<<dim3(1, B / 128), 256, FP_SMEM>>>(
        zh, whi + OW_FP, fp_b, out, B);
}